// round 9
// baseline (speedup 1.0000x reference)
#include <cuda_runtime.h>
#include <math.h>

#define N_PIX    90000
#define HALF_PIX 45000
#define C_IN     256
#define E_CH     64
#define CROP     300
#define HEADS    2
#define DH       32

typedef unsigned long long ull;

__device__ __forceinline__ void fma2(ull& d, ull a, ull b) {
    asm("fma.rn.f32x2 %0, %1, %2, %0;" : "+l"(d) : "l"(a), "l"(b));
}
__device__ __forceinline__ ull add2(ull a, ull b) {
    ull r; asm("add.rn.f32x2 %0, %1, %2;" : "=l"(r) : "l"(a), "l"(b)); return r;
}
__device__ __forceinline__ ull mul2(ull a, ull b) {
    ull r; asm("mul.rn.f32x2 %0, %1, %2;" : "=l"(r) : "l"(a), "l"(b)); return r;
}
__device__ __forceinline__ ull fdup(float v) {
    ull r; asm("mov.b64 %0, {%1, %1};" : "=l"(r) : "f"(v)); return r;
}
__device__ __forceinline__ float2 u2f(ull v) {
    float2 f; asm("mov.b64 {%0, %1}, %2;" : "=f"(f.x), "=f"(f.y) : "l"(v)); return f;
}
__device__ __forceinline__ float hsum2(ull v) { float2 f = u2f(v); return f.x + f.y; }

// ---------------- scratch ----------------
__device__ float g_h[N_PIX * E_CH];        // [p][c] pre-BN1 (attn gather)
__device__ float g_h_cp[E_CH * N_PIX];     // [c][p] pre-BN1 (epilogue streaming)
__device__ float g_new[E_CH * N_PIX];      // [c][p] attention scatter target
__device__ float g_xa[E_CH * N_PIX];       // [d][p] relu(w_out . new + b)
__device__ float g_outpre[E_CH * N_PIX];   // [c][p] pre-BN2
__device__ int   g_obj[HALF_PIX];
__device__ int   g_bg[HALF_PIX];
__device__ int   g_blkcnt[360];
__device__ float g_sum1[E_CH], g_sumsq1[E_CH];
__device__ float g_sum2[E_CH], g_sumsq2[E_CH];

// ---------------- init: zero BN accumulators (also shifts ncu capture slot) ----------------
__global__ void k_init() {
    int t = threadIdx.x;
    if (t < 64) g_sum1[t] = 0.f;
    else if (t < 128) g_sumsq1[t - 64] = 0.f;
    else if (t < 192) g_sum2[t - 128] = 0.f;
    else if (t < 256) g_sumsq2[t - 192] = 0.f;
}

// ---------------- scanA ----------------
#define SCAN_B 352
__global__ void k_scanA(const int* __restrict__ prop) {
    int idx = blockIdx.x * 256 + threadIdx.x;
    int v = (idx < N_PIX) ? (prop[idx] != 0) : 0;
    unsigned m = __ballot_sync(0xffffffffu, v);
    __shared__ int wc[8];
    if ((threadIdx.x & 31) == 0) wc[threadIdx.x >> 5] = __popc(m);
    __syncthreads();
    if (threadIdx.x == 0) {
        int t = 0;
        for (int w = 0; w < 8; w++) t += wc[w];
        g_blkcnt[blockIdx.x] = t;
    }
}

// ---------------- scanBC: per-block prefix + scatter ----------------
__global__ void k_scanBC(const int* __restrict__ prop) {
    int tid = threadIdx.x;
    int b = blockIdx.x;
    int acc = 0;
    for (int i = tid; i < b; i += 256) acc += g_blkcnt[i];
    __shared__ int red[256];
    red[tid] = acc;
    __syncthreads();
    for (int off = 128; off > 0; off >>= 1) {
        if (tid < off) red[tid] += red[tid + off];
        __syncthreads();
    }
    int blkobj = red[0];

    int idx = b * 256 + tid;
    int valid = idx < N_PIX;
    int v = valid ? (prop[idx] != 0) : 0;
    unsigned objm = __ballot_sync(0xffffffffu, v);
    unsigned valm = __ballot_sync(0xffffffffu, valid);
    int lane = tid & 31, w = tid >> 5;
    __shared__ int wobj[8], wval[8];
    if (lane == 0) { wobj[w] = __popc(objm); wval[w] = __popc(valm); }
    __syncthreads();
    int objbase = 0, valbase = 0;
    for (int i = 0; i < w; i++) { objbase += wobj[i]; valbase += wval[i]; }
    unsigned ltm = (1u << lane) - 1u;
    if (valid) {
        if (v) {
            g_obj[blkobj + objbase + __popc(objm & ltm)] = idx;
        } else {
            int bg_before_blk = b * 256 - blkobj;
            int intra = (valbase - objbase) + (__popc(valm & ltm) - __popc(objm & ltm));
            g_bg[bg_before_blk + intra] = idx;
        }
    }
}

// block-level stats reduction: shuffle-reduced warp partials -> SMEM -> 1 atomic/channel
__device__ __forceinline__ void stats_block_reduce(ull* acc2, float* ssum, float* ssq,
                                                   float* gsum, float* gsq,
                                                   int tid, int lane, int warp) {
#pragma unroll 4
    for (int k = 0; k < 32; k++) {
        ull s = acc2[k];
        ull q = mul2(acc2[k], acc2[k]);
#pragma unroll
        for (int o = 16; o > 0; o >>= 1) {
            s = add2(s, __shfl_xor_sync(0xffffffffu, s, o));
            q = add2(q, __shfl_xor_sync(0xffffffffu, q, o));
        }
        if (lane == 0) {
            float2 sf = u2f(s), qf = u2f(q);
            ssum[warp * 64 + 2 * k]     = sf.x;
            ssum[warp * 64 + 2 * k + 1] = sf.y;
            ssq[warp * 64 + 2 * k]      = qf.x;
            ssq[warp * 64 + 2 * k + 1]  = qf.y;
        }
    }
    __syncthreads();
    if (tid < 64) {
        float t = 0.f;
#pragma unroll
        for (int w = 0; w < 8; w++) t += ssum[w * 64 + tid];
        atomicAdd(&gsum[tid], t);
    } else if (tid < 128) {
        int c = tid - 64;
        float t = 0.f;
#pragma unroll
        for (int w = 0; w < 8; w++) t += ssq[w * 64 + c];
        atomicAdd(&gsq[c], t);
    }
}

// ---------------- conv1: dual-layout store + fused BN1 stats ----------------
__global__ __launch_bounds__(256) void k_conv1(const float* __restrict__ x,
                                               const float* __restrict__ w) {
    extern __shared__ float ws[]; // transposed [c][e]
    __shared__ float ssum[512], ssq[512];
    int tid = threadIdx.x;
    for (int i = tid; i < E_CH * C_IN; i += 256) {
        int e = i >> 8, c = i & 255;
        ws[c * 64 + e] = w[i];
    }
    __syncthreads();
    int p = blockIdx.x * 256 + tid;
    bool valid = p < N_PIX;

    ull acc2[32];
#pragma unroll
    for (int i = 0; i < 32; i++) acc2[i] = 0ull;

    if (valid) {
#pragma unroll 4
        for (int c = 0; c < C_IN; c++) {
            ull xd = fdup(__ldg(&x[(size_t)c * N_PIX + p]));
            const float* wr = &ws[c * 64];
#pragma unroll
            for (int i = 0; i < 16; i++) {
                ulonglong2 wv = *(const ulonglong2*)&wr[i * 4];
                fma2(acc2[2 * i],     wv.x, xd);
                fma2(acc2[2 * i + 1], wv.y, xd);
            }
        }
        ull* op = (ull*)&g_h[(size_t)p * 64];
#pragma unroll
        for (int i = 0; i < 32; i++) op[i] = acc2[i];
#pragma unroll
        for (int i = 0; i < 32; i++) {
            float2 f = u2f(acc2[i]);
            g_h_cp[(size_t)(2 * i) * N_PIX + p]     = f.x;
            g_h_cp[(size_t)(2 * i + 1) * N_PIX + p] = f.y;
        }
    }

    stats_block_reduce(acc2, ssum, ssq, g_sum1, g_sumsq1, tid, tid & 31, tid >> 5);
}

// ---------------- attention: 10 warps, 6 rows/warp ----------------
#define ATT_THREADS 320
#define ATT_WARPS 10
#define ATT_R 6
// floats: sc1 64 | bi1 64 | wq_t 1152 | wk_t 1152 | wv_t 1152 | p 18000 | q 9600 | k 9600 | v 9600 | pix 300
#define SM_ATT_FLOATS (64 + 64 + 1152 * 3 + 18000 + 9600 * 3 + 300)
#define SM_ATT_BYTES (SM_ATT_FLOATS * 4)

__global__ __launch_bounds__(ATT_THREADS, 1) void k_attn(const float* __restrict__ wq,
                                                         const float* __restrict__ wkv,
                                                         const int* __restrict__ rand_inds,
                                                         const float* __restrict__ bn1_g,
                                                         const float* __restrict__ bn1_b) {
    extern __shared__ float sm[];
    float* sc1    = sm;                    // 64
    float* bi1    = sm + 64;               // 64
    float* wq_t   = sm + 128;              // 32*36
    float* wk_t   = wq_t + 1152;
    float* wv_t   = wk_t + 1152;
    float* p_rows = wv_t + 1152;           // 18000 (seq alias)
    float* q_s    = p_rows + 18000;        // 9600
    float* k_s    = q_s + 9600;            // 9600
    float* v_t    = k_s + 9600;            // 9600 : [d][300]
    int*   pix_s  = (int*)(v_t + 9600);    // 300
    float* seq_s  = p_rows;

    int tid = threadIdx.x, warp = tid >> 5, lane = tid & 31;
    int b = blockIdx.x;
    int head = b / CROP;
    int iblk = b - head * CROP;
    int hoff = head * DH;

    if (tid < 64) {
        float m = g_sum1[tid] * (1.f / (float)N_PIX);
        float var = g_sumsq1[tid] * (1.f / (float)N_PIX) - m * m;
        float sc = bn1_g[tid] * rsqrtf(var + 1e-5f);
        sc1[tid] = sc;
        bi1[tid] = bn1_b[tid] - m * sc;
    }
    const int* src = (iblk < CROP / 2) ? g_obj : g_bg;
    const int* ri = rand_inds + (size_t)head * N_PIX + (size_t)iblk * CROP;
    for (int j = tid; j < CROP; j += ATT_THREADS) pix_s[j] = src[ri[j]];
    for (int i = tid; i < 1024; i += ATT_THREADS) {
        int e = i >> 5, d = i & 31;
        wq_t[d * 36 + e] = wq[i];
    }
    for (int i = tid; i < 2048; i += ATT_THREADS) {
        int e = i >> 6, c = i & 63;
        if (c < 32) wk_t[c * 36 + e] = wkv[i];
        else        wv_t[(c - 32) * 36 + e] = wkv[i];
    }
    __syncthreads();

    // gather + BN1 + relu, XOR-swizzled [j][32]
    for (int u = tid; u < CROP * 8; u += ATT_THREADS) {
        int j = u >> 3, seg = u & 7;
        int ch = hoff + seg * 4;
        float4 v = *(const float4*)&g_h[(size_t)pix_s[j] * 64 + ch];
        float4 s4 = *(const float4*)&sc1[ch];
        float4 b4 = *(const float4*)&bi1[ch];
        v.x = fmaxf(fmaf(v.x, s4.x, b4.x), 0.f);
        v.y = fmaxf(fmaf(v.y, s4.y, b4.y), 0.f);
        v.z = fmaxf(fmaf(v.z, s4.z, b4.z), 0.f);
        v.w = fmaxf(fmaf(v.w, s4.w, b4.w), 0.f);
        int pc = seg ^ (j & 7);
        *(float4*)&seq_s[j * 32 + pc * 4] = v;
    }
    __syncthreads();

    // QKV with register-resident weights (d = lane)
    {
        ull rq[16], rk[16], rv[16];
#pragma unroll
        for (int e2 = 0; e2 < 8; e2++) {
            ulonglong2 t;
            t = *(const ulonglong2*)&wq_t[lane * 36 + e2 * 4]; rq[2*e2] = t.x; rq[2*e2+1] = t.y;
            t = *(const ulonglong2*)&wk_t[lane * 36 + e2 * 4]; rk[2*e2] = t.x; rk[2*e2+1] = t.y;
            t = *(const ulonglong2*)&wv_t[lane * 36 + e2 * 4]; rv[2*e2] = t.x; rv[2*e2+1] = t.y;
        }
        for (int j = warp; j < CROP; j += ATT_WARPS) {
            int sw2 = (j & 7) << 2;
            ull aq = 0, ak = 0, av = 0;
#pragma unroll
            for (int e4 = 0; e4 < 8; e4++) {
                ulonglong2 sp = *(const ulonglong2*)&seq_s[j * 32 + ((e4 << 2) ^ sw2)];
                fma2(aq, sp.x, rq[2*e4]);
                fma2(ak, sp.x, rk[2*e4]);
                fma2(av, sp.x, rv[2*e4]);
                fma2(aq, sp.y, rq[2*e4+1]);
                fma2(ak, sp.y, rk[2*e4+1]);
                fma2(av, sp.y, rv[2*e4+1]);
            }
            int wi = j * 32 + (lane ^ sw2);
            q_s[wi] = hsum2(aq);
            k_s[wi] = hsum2(ak);
            v_t[lane * 300 + j] = hsum2(av);
        }
    }
    __syncthreads();

    const float scale = 0.17677669529663687f; // 1/sqrt(32)
    float* pw = &p_rows[warp * ATT_R * 300];
    for (int rp = warp; rp < CROP / ATT_R; rp += ATT_WARPS) {
        int r0 = rp * ATT_R;
        ull a[ATT_R][10];
#pragma unroll
        for (int r = 0; r < ATT_R; r++)
#pragma unroll
            for (int jj = 0; jj < 10; jj++) a[r][jj] = 0ull;

#pragma unroll
        for (int c = 0; c < 8; c++) {
            ull qx[ATT_R], qy[ATT_R];
#pragma unroll
            for (int r = 0; r < ATT_R; r++) {
                int row = r0 + r;
                ulonglong2 t = *(const ulonglong2*)&q_s[row * 32 + ((c << 2) ^ ((row & 7) << 2))];
                qx[r] = t.x; qy[r] = t.y;
            }
#pragma unroll
            for (int jj = 0; jj < 10; jj++) {
                int j = lane + (jj << 5);
                int jc = (j < CROP) ? j : 0;
                ulonglong2 kv = *(const ulonglong2*)&k_s[jc * 32 + ((c << 2) ^ ((jc & 7) << 2))];
#pragma unroll
                for (int r = 0; r < ATT_R; r++) fma2(a[r][jj], qx[r], kv.x);
#pragma unroll
                for (int r = 0; r < ATT_R; r++) fma2(a[r][jj], qy[r], kv.y);
            }
        }
#pragma unroll
        for (int r = 0; r < ATT_R; r++) {
            float sv[10];
            float mx = -1e30f;
#pragma unroll
            for (int jj = 0; jj < 10; jj++) {
                float s = hsum2(a[r][jj]) * scale;
                sv[jj] = s;
                if (lane + (jj << 5) < CROP) mx = fmaxf(mx, s);
            }
#pragma unroll
            for (int o = 16; o > 0; o >>= 1)
                mx = fmaxf(mx, __shfl_xor_sync(0xffffffffu, mx, o));
            float sum = 0.f;
#pragma unroll
            for (int jj = 0; jj < 10; jj++) {
                int j = lane + (jj << 5);
                float e = (j < CROP) ? __expf(sv[jj] - mx) : 0.f;
                sv[jj] = e;
                sum += e;
            }
#pragma unroll
            for (int o = 16; o > 0; o >>= 1)
                sum += __shfl_xor_sync(0xffffffffu, sum, o);
            float inv = 1.f / sum;
#pragma unroll
            for (int jj = 0; jj < 10; jj++) {
                int j = lane + (jj << 5);
                if (j < CROP) pw[r * 300 + j] = sv[jj] * inv;
            }
        }
        __syncwarp();
        ull oa[ATT_R], ob[ATT_R];
#pragma unroll
        for (int r = 0; r < ATT_R; r++) { oa[r] = 0ull; ob[r] = 0ull; }
        const float* vrow = &v_t[lane * 300];
#pragma unroll 5
        for (int j4 = 0; j4 < 75; j4++) {
            ulonglong2 vv = *(const ulonglong2*)&vrow[j4 * 4];
#pragma unroll
            for (int r = 0; r < ATT_R; r++) {
                ulonglong2 pv = *(const ulonglong2*)&pw[r * 300 + j4 * 4];
                fma2(oa[r], pv.x, vv.x);
                fma2(ob[r], pv.y, vv.y);
            }
        }
        // scatter into channel-major g_new: [hoff+d][pix]
#pragma unroll
        for (int r = 0; r < ATT_R; r++) {
            float ov = hsum2(add2(oa[r], ob[r]));
            int t = (r0 + r) * 32 + lane;
            int d = t / 300, mm = t - d * 300;
            g_new[(size_t)(hoff + d) * N_PIX + pix_s[mm]] = ov;
        }
        __syncwarp();
    }
}

// ---------------- w_out: xa[d][p] = relu(sum_c new[c][p]*w_out[c][d] + b[d]) ----------------
__global__ __launch_bounds__(256) void k_wout(const float* __restrict__ w_out,
                                              const float* __restrict__ b_out) {
    __shared__ float ws[4096]; // [c][d]
    __shared__ float bs[64];
    int tid = threadIdx.x;
    for (int i = tid; i < 4096; i += 256) ws[i] = w_out[i];
    if (tid < 64) bs[tid] = b_out[tid];
    __syncthreads();
    int p = blockIdx.x * 256 + tid;
    if (p >= N_PIX) return;

    ull acc2[32];
#pragma unroll
    for (int i = 0; i < 32; i++) acc2[i] = 0ull;

#pragma unroll 4
    for (int c = 0; c < 64; c++) {
        ull xd = fdup(__ldg(&g_new[(size_t)c * N_PIX + p]));
        const float* wr = &ws[c * 64];
#pragma unroll
        for (int i = 0; i < 16; i++) {
            ulonglong2 wv = *(const ulonglong2*)&wr[i * 4];
            fma2(acc2[2 * i],     wv.x, xd);
            fma2(acc2[2 * i + 1], wv.y, xd);
        }
    }
#pragma unroll
    for (int i = 0; i < 32; i++) {
        float2 f = u2f(acc2[i]);
        g_xa[(size_t)(2 * i) * N_PIX + p]     = fmaxf(f.x + bs[2 * i], 0.f);
        g_xa[(size_t)(2 * i + 1) * N_PIX + p] = fmaxf(f.y + bs[2 * i + 1], 0.f);
    }
}

// ---------------- conv2 (channel-major streaming) + fused BN2 stats ----------------
__global__ __launch_bounds__(256) void k_conv2(const float* __restrict__ w2,
                                               const float* __restrict__ bn1_g,
                                               const float* __restrict__ bn1_b) {
    __shared__ float w2t[8192]; // [c][o]
    __shared__ float sc1[64], bi1[64];
    __shared__ float ssum[512], ssq[512];
    int tid = threadIdx.x;
    for (int i = tid; i < 8192; i += 256) {
        int c = i >> 6, o = i & 63;
        w2t[i] = w2[o * 128 + c];
    }
    if (tid < 64) {
        float m = g_sum1[tid] * (1.f / (float)N_PIX);
        float var = g_sumsq1[tid] * (1.f / (float)N_PIX) - m * m;
        float sc = bn1_g[tid] * rsqrtf(var + 1e-5f);
        sc1[tid] = sc;
        bi1[tid] = bn1_b[tid] - m * sc;
    }
    __syncthreads();
    int p = blockIdx.x * 256 + tid;
    bool valid = p < N_PIX;

    ull acc2[32];
#pragma unroll
    for (int i = 0; i < 32; i++) acc2[i] = 0ull;

    if (valid) {
#pragma unroll 4
        for (int c = 0; c < 64; c++) {
            ull xd = fdup(__ldg(&g_xa[(size_t)c * N_PIX + p]));
            const float* wr = &w2t[c * 64];
#pragma unroll
            for (int i = 0; i < 16; i++) {
                ulonglong2 wv = *(const ulonglong2*)&wr[i * 4];
                fma2(acc2[2 * i],     wv.x, xd);
                fma2(acc2[2 * i + 1], wv.y, xd);
            }
        }
#pragma unroll 4
        for (int c = 0; c < 64; c++) {
            float hv = __ldg(&g_h_cp[(size_t)c * N_PIX + p]);
            float hs = fmaxf(fmaf(hv, sc1[c], bi1[c]), 0.f);
            ull hd = fdup(hs);
            const float* wr = &w2t[(64 + c) * 64];
#pragma unroll
            for (int i = 0; i < 16; i++) {
                ulonglong2 wv = *(const ulonglong2*)&wr[i * 4];
                fma2(acc2[2 * i],     wv.x, hd);
                fma2(acc2[2 * i + 1], wv.y, hd);
            }
        }
#pragma unroll
        for (int i = 0; i < 32; i++) {
            float2 f = u2f(acc2[i]);
            g_outpre[(size_t)(2 * i) * N_PIX + p]     = f.x;
            g_outpre[(size_t)(2 * i + 1) * N_PIX + p] = f.y;
        }
    }

    stats_block_reduce(acc2, ssum, ssq, g_sum2, g_sumsq2, tid, tid & 31, tid >> 5);
}

// ---------------- BN2 apply ----------------
__global__ void k_apply2(const float* __restrict__ g, const float* __restrict__ b,
                         float* __restrict__ out) {
    __shared__ float ssc, sbi;
    int c = blockIdx.y;
    if (threadIdx.x == 0) {
        float m = g_sum2[c] * (1.f / (float)N_PIX);
        float var = g_sumsq2[c] * (1.f / (float)N_PIX) - m * m;
        float sc = g[c] * rsqrtf(var + 1e-5f);
        ssc = sc;
        sbi = b[c] - m * sc;
    }
    __syncthreads();
    int p = blockIdx.x * 256 + threadIdx.x;
    if (p >= N_PIX) return;
    float v = g_outpre[(size_t)c * N_PIX + p] * ssc + sbi;
    out[(size_t)c * N_PIX + p] = v > 0.f ? v : 0.f;
}

// ---------------- launch ----------------
extern "C" void kernel_launch(void* const* d_in, const int* in_sizes, int n_in,
                              void* d_out, int out_size) {
    const float* x         = (const float*)d_in[0];
    const int*   prop      = (const int*)d_in[1];
    const int*   rand_inds = (const int*)d_in[2];
    const float* w_conv1   = (const float*)d_in[3];
    const float* bn1_g     = (const float*)d_in[4];
    const float* bn1_b     = (const float*)d_in[5];
    const float* wq        = (const float*)d_in[6];
    const float* wkv       = (const float*)d_in[7];
    const float* w_out     = (const float*)d_in[8];
    const float* b_out     = (const float*)d_in[9];
    const float* w_conv2   = (const float*)d_in[10];
    const float* bn2_g     = (const float*)d_in[11];
    const float* bn2_b     = (const float*)d_in[12];
    float* out = (float*)d_out;

    size_t smem_c1 = (size_t)E_CH * C_IN * sizeof(float);
    cudaFuncSetAttribute(k_conv1, cudaFuncAttributeMaxDynamicSharedMemorySize, (int)smem_c1);
    cudaFuncSetAttribute(k_attn,  cudaFuncAttributeMaxDynamicSharedMemorySize, SM_ATT_BYTES);

    k_init<<<1, 256>>>();
    k_scanA<<<SCAN_B, 256>>>(prop);
    k_scanBC<<<SCAN_B, 256>>>(prop);
    k_conv1<<<(N_PIX + 255) / 256, 256, smem_c1>>>(x, w_conv1);
    k_attn<<<HEADS * CROP, ATT_THREADS, SM_ATT_BYTES>>>(wq, wkv, rand_inds, bn1_g, bn1_b);
    k_wout<<<(N_PIX + 255) / 256, 256>>>(w_out, b_out);
    k_conv2<<<(N_PIX + 255) / 256, 256>>>(w_conv2, bn1_g, bn1_b);
    dim3 g2((N_PIX + 255) / 256, E_CH);
    k_apply2<<<g2, 256>>>(bn2_g, bn2_b, out);
}

// round 10
// speedup vs baseline: 1.2243x; 1.2243x over previous
#include <cuda_runtime.h>
#include <math.h>

#define N_PIX    90000
#define HALF_PIX 45000
#define C_IN     256
#define E_CH     64
#define CROP     300
#define HEADS    2
#define DH       32

typedef unsigned long long ull;

__device__ __forceinline__ void fma2(ull& d, ull a, ull b) {
    asm("fma.rn.f32x2 %0, %1, %2, %0;" : "+l"(d) : "l"(a), "l"(b));
}
__device__ __forceinline__ ull add2(ull a, ull b) {
    ull r; asm("add.rn.f32x2 %0, %1, %2;" : "=l"(r) : "l"(a), "l"(b)); return r;
}
__device__ __forceinline__ ull mul2(ull a, ull b) {
    ull r; asm("mul.rn.f32x2 %0, %1, %2;" : "=l"(r) : "l"(a), "l"(b)); return r;
}
__device__ __forceinline__ ull fdup(float v) {
    ull r; asm("mov.b64 %0, {%1, %1};" : "=l"(r) : "f"(v)); return r;
}
__device__ __forceinline__ float2 u2f(ull v) {
    float2 f; asm("mov.b64 {%0, %1}, %2;" : "=f"(f.x), "=f"(f.y) : "l"(v)); return f;
}
__device__ __forceinline__ float hsum2(ull v) { float2 f = u2f(v); return f.x + f.y; }

// ---------------- scratch ----------------
__device__ float g_h[N_PIX * E_CH];        // [p][c] pre-BN1 (attn gather)
__device__ float g_h_cp[E_CH * N_PIX];     // [c][p] pre-BN1 (epilogue streaming)
__device__ float g_new[E_CH * N_PIX];      // [c][p] attention scatter target
__device__ float g_xa[E_CH * N_PIX];       // [d][p] relu(w_out . new + b)
__device__ float g_outpre[E_CH * N_PIX];   // [c][p] pre-BN2
__device__ int   g_obj[HALF_PIX];
__device__ int   g_bg[HALF_PIX];
__device__ int   g_blkcnt[360];
__device__ float g_sum1[E_CH], g_sumsq1[E_CH];
__device__ float g_sum2[E_CH], g_sumsq2[E_CH];

// ---------------- init ----------------
__global__ void k_init() {
    int t = threadIdx.x;
    if (t < 64) g_sum1[t] = 0.f;
    else if (t < 128) g_sumsq1[t - 64] = 0.f;
    else if (t < 192) g_sum2[t - 128] = 0.f;
    else if (t < 256) g_sumsq2[t - 192] = 0.f;
}

// ---------------- scanA ----------------
#define SCAN_B 352
__global__ void k_scanA(const int* __restrict__ prop) {
    int idx = blockIdx.x * 256 + threadIdx.x;
    int v = (idx < N_PIX) ? (prop[idx] != 0) : 0;
    unsigned m = __ballot_sync(0xffffffffu, v);
    __shared__ int wc[8];
    if ((threadIdx.x & 31) == 0) wc[threadIdx.x >> 5] = __popc(m);
    __syncthreads();
    if (threadIdx.x == 0) {
        int t = 0;
        for (int w = 0; w < 8; w++) t += wc[w];
        g_blkcnt[blockIdx.x] = t;
    }
}

// ---------------- scanBC ----------------
__global__ void k_scanBC(const int* __restrict__ prop) {
    int tid = threadIdx.x;
    int b = blockIdx.x;
    int acc = 0;
    for (int i = tid; i < b; i += 256) acc += g_blkcnt[i];
    __shared__ int red[256];
    red[tid] = acc;
    __syncthreads();
    for (int off = 128; off > 0; off >>= 1) {
        if (tid < off) red[tid] += red[tid + off];
        __syncthreads();
    }
    int blkobj = red[0];

    int idx = b * 256 + tid;
    int valid = idx < N_PIX;
    int v = valid ? (prop[idx] != 0) : 0;
    unsigned objm = __ballot_sync(0xffffffffu, v);
    unsigned valm = __ballot_sync(0xffffffffu, valid);
    int lane = tid & 31, w = tid >> 5;
    __shared__ int wobj[8], wval[8];
    if (lane == 0) { wobj[w] = __popc(objm); wval[w] = __popc(valm); }
    __syncthreads();
    int objbase = 0, valbase = 0;
    for (int i = 0; i < w; i++) { objbase += wobj[i]; valbase += wval[i]; }
    unsigned ltm = (1u << lane) - 1u;
    if (valid) {
        if (v) {
            g_obj[blkobj + objbase + __popc(objm & ltm)] = idx;
        } else {
            int bg_before_blk = b * 256 - blkobj;
            int intra = (valbase - objbase) + (__popc(valm & ltm) - __popc(objm & ltm));
            g_bg[bg_before_blk + intra] = idx;
        }
    }
}

// block-level stats reduction
__device__ __forceinline__ void stats_block_reduce(ull* acc2, float* ssum, float* ssq,
                                                   float* gsum, float* gsq,
                                                   int tid, int lane, int warp) {
#pragma unroll 4
    for (int k = 0; k < 32; k++) {
        ull s = acc2[k];
        ull q = mul2(acc2[k], acc2[k]);
#pragma unroll
        for (int o = 16; o > 0; o >>= 1) {
            s = add2(s, __shfl_xor_sync(0xffffffffu, s, o));
            q = add2(q, __shfl_xor_sync(0xffffffffu, q, o));
        }
        if (lane == 0) {
            float2 sf = u2f(s), qf = u2f(q);
            ssum[warp * 64 + 2 * k]     = sf.x;
            ssum[warp * 64 + 2 * k + 1] = sf.y;
            ssq[warp * 64 + 2 * k]      = qf.x;
            ssq[warp * 64 + 2 * k + 1]  = qf.y;
        }
    }
    __syncthreads();
    if (tid < 64) {
        float t = 0.f;
#pragma unroll
        for (int w = 0; w < 8; w++) t += ssum[w * 64 + tid];
        atomicAdd(&gsum[tid], t);
    } else if (tid < 128) {
        int c = tid - 64;
        float t = 0.f;
#pragma unroll
        for (int w = 0; w < 8; w++) t += ssq[w * 64 + c];
        atomicAdd(&gsq[c], t);
    }
}

// ---------------- conv1: batched loads (MLP=16) + dual-layout store + fused BN1 stats ----------------
__global__ __launch_bounds__(256) void k_conv1(const float* __restrict__ x,
                                               const float* __restrict__ w) {
    extern __shared__ float ws[]; // transposed [c][e]
    __shared__ float ssum[512], ssq[512];
    int tid = threadIdx.x;
    for (int i = tid; i < E_CH * C_IN; i += 256) {
        int e = i >> 8, c = i & 255;
        ws[c * 64 + e] = w[i];
    }
    __syncthreads();
    int p = blockIdx.x * 256 + tid;
    bool valid = p < N_PIX;

    ull acc2[32];
#pragma unroll
    for (int i = 0; i < 32; i++) acc2[i] = 0ull;

    if (valid) {
        for (int c0 = 0; c0 < C_IN; c0 += 16) {
            float xr[16];
#pragma unroll
            for (int i = 0; i < 16; i++)
                xr[i] = __ldg(&x[(size_t)(c0 + i) * N_PIX + p]);
#pragma unroll
            for (int i = 0; i < 16; i++) {
                ull xd = fdup(xr[i]);
                const float* wr = &ws[(c0 + i) * 64];
#pragma unroll
                for (int k = 0; k < 16; k++) {
                    ulonglong2 wv = *(const ulonglong2*)&wr[k * 4];
                    fma2(acc2[2 * k],     wv.x, xd);
                    fma2(acc2[2 * k + 1], wv.y, xd);
                }
            }
        }
        ull* op = (ull*)&g_h[(size_t)p * 64];
#pragma unroll
        for (int i = 0; i < 32; i++) op[i] = acc2[i];
#pragma unroll
        for (int i = 0; i < 32; i++) {
            float2 f = u2f(acc2[i]);
            g_h_cp[(size_t)(2 * i) * N_PIX + p]     = f.x;
            g_h_cp[(size_t)(2 * i + 1) * N_PIX + p] = f.y;
        }
    }

    stats_block_reduce(acc2, ssum, ssq, g_sum1, g_sumsq1, tid, tid & 31, tid >> 5);
}

// ---------------- attention: r8 configuration (4 rows/warp, 384 threads) ----------------
#define ATT_THREADS 384
#define ATT_WARPS 12
#define SM_ATT_FLOATS (64 + 64 + 1152 * 3 + 14400 + 9600 * 3 + 300)
#define SM_ATT_BYTES (SM_ATT_FLOATS * 4)

__global__ __launch_bounds__(ATT_THREADS, 1) void k_attn(const float* __restrict__ wq,
                                                         const float* __restrict__ wkv,
                                                         const int* __restrict__ rand_inds,
                                                         const float* __restrict__ bn1_g,
                                                         const float* __restrict__ bn1_b) {
    extern __shared__ float sm[];
    float* sc1    = sm;                    // 64
    float* bi1    = sm + 64;               // 64
    float* wq_t   = sm + 128;              // 32*36
    float* wk_t   = wq_t + 1152;
    float* wv_t   = wk_t + 1152;
    float* p_rows = wv_t + 1152;           // 14400 (seq alias)
    float* q_s    = p_rows + 14400;        // 9600
    float* k_s    = q_s + 9600;            // 9600
    float* v_t    = k_s + 9600;            // 9600 : [d][300]
    int*   pix_s  = (int*)(v_t + 9600);    // 300
    float* seq_s  = p_rows;

    int tid = threadIdx.x, warp = tid >> 5, lane = tid & 31;
    int b = blockIdx.x;
    int head = b / CROP;
    int iblk = b - head * CROP;
    int hoff = head * DH;

    if (tid < 64) {
        float m = g_sum1[tid] * (1.f / (float)N_PIX);
        float var = g_sumsq1[tid] * (1.f / (float)N_PIX) - m * m;
        float sc = bn1_g[tid] * rsqrtf(var + 1e-5f);
        sc1[tid] = sc;
        bi1[tid] = bn1_b[tid] - m * sc;
    }
    const int* src = (iblk < CROP / 2) ? g_obj : g_bg;
    const int* ri = rand_inds + (size_t)head * N_PIX + (size_t)iblk * CROP;
    for (int j = tid; j < CROP; j += ATT_THREADS) pix_s[j] = src[ri[j]];
    for (int i = tid; i < 1024; i += ATT_THREADS) {
        int e = i >> 5, d = i & 31;
        wq_t[d * 36 + e] = wq[i];
    }
    for (int i = tid; i < 2048; i += ATT_THREADS) {
        int e = i >> 6, c = i & 63;
        if (c < 32) wk_t[c * 36 + e] = wkv[i];
        else        wv_t[(c - 32) * 36 + e] = wkv[i];
    }
    __syncthreads();

    // gather + BN1 + relu, XOR-swizzled [j][32]
    for (int u = tid; u < CROP * 8; u += ATT_THREADS) {
        int j = u >> 3, seg = u & 7;
        int ch = hoff + seg * 4;
        float4 v = *(const float4*)&g_h[(size_t)pix_s[j] * 64 + ch];
        float4 s4 = *(const float4*)&sc1[ch];
        float4 b4 = *(const float4*)&bi1[ch];
        v.x = fmaxf(fmaf(v.x, s4.x, b4.x), 0.f);
        v.y = fmaxf(fmaf(v.y, s4.y, b4.y), 0.f);
        v.z = fmaxf(fmaf(v.z, s4.z, b4.z), 0.f);
        v.w = fmaxf(fmaf(v.w, s4.w, b4.w), 0.f);
        int pc = seg ^ (j & 7);
        *(float4*)&seq_s[j * 32 + pc * 4] = v;
    }
    __syncthreads();

    // QKV with register-resident weights (d = lane)
    {
        ull rq[16], rk[16], rv[16];
#pragma unroll
        for (int e2 = 0; e2 < 8; e2++) {
            ulonglong2 t;
            t = *(const ulonglong2*)&wq_t[lane * 36 + e2 * 4]; rq[2*e2] = t.x; rq[2*e2+1] = t.y;
            t = *(const ulonglong2*)&wk_t[lane * 36 + e2 * 4]; rk[2*e2] = t.x; rk[2*e2+1] = t.y;
            t = *(const ulonglong2*)&wv_t[lane * 36 + e2 * 4]; rv[2*e2] = t.x; rv[2*e2+1] = t.y;
        }
        for (int j = warp; j < CROP; j += ATT_WARPS) {
            int sw2 = (j & 7) << 2;
            ull aq = 0, ak = 0, av = 0;
#pragma unroll
            for (int e4 = 0; e4 < 8; e4++) {
                ulonglong2 sp = *(const ulonglong2*)&seq_s[j * 32 + ((e4 << 2) ^ sw2)];
                fma2(aq, sp.x, rq[2*e4]);
                fma2(ak, sp.x, rk[2*e4]);
                fma2(av, sp.x, rv[2*e4]);
                fma2(aq, sp.y, rq[2*e4+1]);
                fma2(ak, sp.y, rk[2*e4+1]);
                fma2(av, sp.y, rv[2*e4+1]);
            }
            int wi = j * 32 + (lane ^ sw2);
            q_s[wi] = hsum2(aq);
            k_s[wi] = hsum2(ak);
            v_t[lane * 300 + j] = hsum2(av);
        }
    }
    __syncthreads();

    const float scale = 0.17677669529663687f; // 1/sqrt(32)
    float* pw = &p_rows[warp * 4 * 300];
    for (int rp = warp; rp < 75; rp += ATT_WARPS) {
        int r0 = rp * 4;
        ull a[4][10];
#pragma unroll
        for (int r = 0; r < 4; r++)
#pragma unroll
            for (int jj = 0; jj < 10; jj++) a[r][jj] = 0ull;

#pragma unroll
        for (int c = 0; c < 8; c++) {
            ull qx[4], qy[4];
#pragma unroll
            for (int r = 0; r < 4; r++) {
                int row = r0 + r;
                ulonglong2 t = *(const ulonglong2*)&q_s[row * 32 + ((c << 2) ^ ((row & 7) << 2))];
                qx[r] = t.x; qy[r] = t.y;
            }
#pragma unroll
            for (int jj = 0; jj < 10; jj++) {
                int j = lane + (jj << 5);
                int jc = (j < CROP) ? j : 0;
                ulonglong2 kv = *(const ulonglong2*)&k_s[jc * 32 + ((c << 2) ^ ((jc & 7) << 2))];
                fma2(a[0][jj], qx[0], kv.x);
                fma2(a[1][jj], qx[1], kv.x);
                fma2(a[2][jj], qx[2], kv.x);
                fma2(a[3][jj], qx[3], kv.x);
                fma2(a[0][jj], qy[0], kv.y);
                fma2(a[1][jj], qy[1], kv.y);
                fma2(a[2][jj], qy[2], kv.y);
                fma2(a[3][jj], qy[3], kv.y);
            }
        }
#pragma unroll
        for (int r = 0; r < 4; r++) {
            float sv[10];
            float mx = -1e30f;
#pragma unroll
            for (int jj = 0; jj < 10; jj++) {
                float s = hsum2(a[r][jj]) * scale;
                sv[jj] = s;
                if (lane + (jj << 5) < CROP) mx = fmaxf(mx, s);
            }
#pragma unroll
            for (int o = 16; o > 0; o >>= 1)
                mx = fmaxf(mx, __shfl_xor_sync(0xffffffffu, mx, o));
            float sum = 0.f;
#pragma unroll
            for (int jj = 0; jj < 10; jj++) {
                int j = lane + (jj << 5);
                float e = (j < CROP) ? __expf(sv[jj] - mx) : 0.f;
                sv[jj] = e;
                sum += e;
            }
#pragma unroll
            for (int o = 16; o > 0; o >>= 1)
                sum += __shfl_xor_sync(0xffffffffu, sum, o);
            float inv = 1.f / sum;
#pragma unroll
            for (int jj = 0; jj < 10; jj++) {
                int j = lane + (jj << 5);
                if (j < CROP) pw[r * 300 + j] = sv[jj] * inv;
            }
        }
        __syncwarp();
        ull oa[4] = {0, 0, 0, 0}, ob[4] = {0, 0, 0, 0};
        const float* vrow = &v_t[lane * 300];
#pragma unroll 5
        for (int j4 = 0; j4 < 75; j4++) {
            ulonglong2 vv = *(const ulonglong2*)&vrow[j4 * 4];
#pragma unroll
            for (int r = 0; r < 4; r++) {
                ulonglong2 pv = *(const ulonglong2*)&pw[r * 300 + j4 * 4];
                fma2(oa[r], pv.x, vv.x);
                fma2(ob[r], pv.y, vv.y);
            }
        }
        // scatter into channel-major g_new
#pragma unroll
        for (int r = 0; r < 4; r++) {
            float ov = hsum2(add2(oa[r], ob[r]));
            int t = (r0 + r) * 32 + lane;
            int d = t / 300, mm = t - d * 300;
            g_new[(size_t)(hoff + d) * N_PIX + pix_s[mm]] = ov;
        }
        __syncwarp();
    }
}

// ---------------- w_out (batched loads) ----------------
__global__ __launch_bounds__(256) void k_wout(const float* __restrict__ w_out,
                                              const float* __restrict__ b_out) {
    __shared__ float ws[4096]; // [c][d]
    __shared__ float bs[64];
    int tid = threadIdx.x;
    for (int i = tid; i < 4096; i += 256) ws[i] = w_out[i];
    if (tid < 64) bs[tid] = b_out[tid];
    __syncthreads();
    int p = blockIdx.x * 256 + tid;
    if (p >= N_PIX) return;

    ull acc2[32];
#pragma unroll
    for (int i = 0; i < 32; i++) acc2[i] = 0ull;

    for (int c0 = 0; c0 < 64; c0 += 8) {
        float xr[8];
#pragma unroll
        for (int i = 0; i < 8; i++)
            xr[i] = __ldg(&g_new[(size_t)(c0 + i) * N_PIX + p]);
#pragma unroll
        for (int i = 0; i < 8; i++) {
            ull xd = fdup(xr[i]);
            const float* wr = &ws[(c0 + i) * 64];
#pragma unroll
            for (int k = 0; k < 16; k++) {
                ulonglong2 wv = *(const ulonglong2*)&wr[k * 4];
                fma2(acc2[2 * k],     wv.x, xd);
                fma2(acc2[2 * k + 1], wv.y, xd);
            }
        }
    }
#pragma unroll
    for (int i = 0; i < 32; i++) {
        float2 f = u2f(acc2[i]);
        g_xa[(size_t)(2 * i) * N_PIX + p]     = fmaxf(f.x + bs[2 * i], 0.f);
        g_xa[(size_t)(2 * i + 1) * N_PIX + p] = fmaxf(f.y + bs[2 * i + 1], 0.f);
    }
}

// ---------------- conv2 (batched loads) + fused BN2 stats ----------------
__global__ __launch_bounds__(256) void k_conv2(const float* __restrict__ w2,
                                               const float* __restrict__ bn1_g,
                                               const float* __restrict__ bn1_b) {
    __shared__ float w2t[8192]; // [c][o]
    __shared__ float sc1[64], bi1[64];
    __shared__ float ssum[512], ssq[512];
    int tid = threadIdx.x;
    for (int i = tid; i < 8192; i += 256) {
        int c = i >> 6, o = i & 63;
        w2t[i] = w2[o * 128 + c];
    }
    if (tid < 64) {
        float m = g_sum1[tid] * (1.f / (float)N_PIX);
        float var = g_sumsq1[tid] * (1.f / (float)N_PIX) - m * m;
        float sc = bn1_g[tid] * rsqrtf(var + 1e-5f);
        sc1[tid] = sc;
        bi1[tid] = bn1_b[tid] - m * sc;
    }
    __syncthreads();
    int p = blockIdx.x * 256 + tid;
    bool valid = p < N_PIX;

    ull acc2[32];
#pragma unroll
    for (int i = 0; i < 32; i++) acc2[i] = 0ull;

    if (valid) {
        for (int c0 = 0; c0 < 64; c0 += 8) {
            float xr[8];
#pragma unroll
            for (int i = 0; i < 8; i++)
                xr[i] = __ldg(&g_xa[(size_t)(c0 + i) * N_PIX + p]);
#pragma unroll
            for (int i = 0; i < 8; i++) {
                ull xd = fdup(xr[i]);
                const float* wr = &w2t[(c0 + i) * 64];
#pragma unroll
                for (int k = 0; k < 16; k++) {
                    ulonglong2 wv = *(const ulonglong2*)&wr[k * 4];
                    fma2(acc2[2 * k],     wv.x, xd);
                    fma2(acc2[2 * k + 1], wv.y, xd);
                }
            }
        }
        for (int c0 = 0; c0 < 64; c0 += 8) {
            float xr[8];
#pragma unroll
            for (int i = 0; i < 8; i++)
                xr[i] = __ldg(&g_h_cp[(size_t)(c0 + i) * N_PIX + p]);
#pragma unroll
            for (int i = 0; i < 8; i++) {
                float hs = fmaxf(fmaf(xr[i], sc1[c0 + i], bi1[c0 + i]), 0.f);
                ull hd = fdup(hs);
                const float* wr = &w2t[(64 + c0 + i) * 64];
#pragma unroll
                for (int k = 0; k < 16; k++) {
                    ulonglong2 wv = *(const ulonglong2*)&wr[k * 4];
                    fma2(acc2[2 * k],     wv.x, hd);
                    fma2(acc2[2 * k + 1], wv.y, hd);
                }
            }
        }
#pragma unroll
        for (int i = 0; i < 32; i++) {
            float2 f = u2f(acc2[i]);
            g_outpre[(size_t)(2 * i) * N_PIX + p]     = f.x;
            g_outpre[(size_t)(2 * i + 1) * N_PIX + p] = f.y;
        }
    }

    stats_block_reduce(acc2, ssum, ssq, g_sum2, g_sumsq2, tid, tid & 31, tid >> 5);
}

// ---------------- BN2 apply ----------------
__global__ void k_apply2(const float* __restrict__ g, const float* __restrict__ b,
                         float* __restrict__ out) {
    __shared__ float ssc, sbi;
    int c = blockIdx.y;
    if (threadIdx.x == 0) {
        float m = g_sum2[c] * (1.f / (float)N_PIX);
        float var = g_sumsq2[c] * (1.f / (float)N_PIX) - m * m;
        float sc = g[c] * rsqrtf(var + 1e-5f);
        ssc = sc;
        sbi = b[c] - m * sc;
    }
    __syncthreads();
    int p = blockIdx.x * 256 + threadIdx.x;
    if (p >= N_PIX) return;
    float v = g_outpre[(size_t)c * N_PIX + p] * ssc + sbi;
    out[(size_t)c * N_PIX + p] = v > 0.f ? v : 0.f;
}

// ---------------- launch ----------------
extern "C" void kernel_launch(void* const* d_in, const int* in_sizes, int n_in,
                              void* d_out, int out_size) {
    const float* x         = (const float*)d_in[0];
    const int*   prop      = (const int*)d_in[1];
    const int*   rand_inds = (const int*)d_in[2];
    const float* w_conv1   = (const float*)d_in[3];
    const float* bn1_g     = (const float*)d_in[4];
    const float* bn1_b     = (const float*)d_in[5];
    const float* wq        = (const float*)d_in[6];
    const float* wkv       = (const float*)d_in[7];
    const float* w_out     = (const float*)d_in[8];
    const float* b_out     = (const float*)d_in[9];
    const float* w_conv2   = (const float*)d_in[10];
    const float* bn2_g     = (const float*)d_in[11];
    const float* bn2_b     = (const float*)d_in[12];
    float* out = (float*)d_out;

    size_t smem_c1 = (size_t)E_CH * C_IN * sizeof(float);
    cudaFuncSetAttribute(k_conv1, cudaFuncAttributeMaxDynamicSharedMemorySize, (int)smem_c1);
    cudaFuncSetAttribute(k_attn,  cudaFuncAttributeMaxDynamicSharedMemorySize, SM_ATT_BYTES);

    k_init<<<1, 256>>>();
    k_scanA<<<SCAN_B, 256>>>(prop);
    k_scanBC<<<SCAN_B, 256>>>(prop);
    k_conv1<<<(N_PIX + 255) / 256, 256, smem_c1>>>(x, w_conv1);
    k_attn<<<HEADS * CROP, ATT_THREADS, SM_ATT_BYTES>>>(wq, wkv, rand_inds, bn1_g, bn1_b);
    k_wout<<<(N_PIX + 255) / 256, 256>>>(w_out, b_out);
    k_conv2<<<(N_PIX + 255) / 256, 256>>>(w_conv2, bn1_g, bn1_b);
    dim3 g2((N_PIX + 255) / 256, E_CH);
    k_apply2<<<g2, 256>>>(bn2_g, bn2_b, out);
}

// round 11
// speedup vs baseline: 1.3483x; 1.1013x over previous
#include <cuda_runtime.h>
#include <math.h>

#define N_PIX    90000
#define HALF_PIX 45000
#define C_IN     256
#define E_CH     64
#define CROP     300
#define HEADS    2
#define DH       32

typedef unsigned long long ull;

__device__ __forceinline__ void fma2(ull& d, ull a, ull b) {
    asm("fma.rn.f32x2 %0, %1, %2, %0;" : "+l"(d) : "l"(a), "l"(b));
}
__device__ __forceinline__ ull add2(ull a, ull b) {
    ull r; asm("add.rn.f32x2 %0, %1, %2;" : "=l"(r) : "l"(a), "l"(b)); return r;
}
__device__ __forceinline__ ull mul2(ull a, ull b) {
    ull r; asm("mul.rn.f32x2 %0, %1, %2;" : "=l"(r) : "l"(a), "l"(b)); return r;
}
__device__ __forceinline__ ull fdup(float v) {
    ull r; asm("mov.b64 %0, {%1, %1};" : "=l"(r) : "f"(v)); return r;
}
__device__ __forceinline__ float2 u2f(ull v) {
    float2 f; asm("mov.b64 {%0, %1}, %2;" : "=f"(f.x), "=f"(f.y) : "l"(v)); return f;
}
__device__ __forceinline__ float hsum2(ull v) { float2 f = u2f(v); return f.x + f.y; }

// ---------------- scratch ----------------
__device__ float g_h[N_PIX * E_CH];        // [p][c] pre-BN1 (attn gather)
__device__ float g_h_cp[E_CH * N_PIX];     // [c][p] pre-BN1 (epilogue streaming)
__device__ float g_new[E_CH * N_PIX];      // [c][p] attention scatter target
__device__ float g_xa[E_CH * N_PIX];       // [d][p] relu(w_out . new + b)
__device__ float g_outpre[E_CH * N_PIX];   // [c][p] pre-BN2
__device__ int   g_obj[HALF_PIX];
__device__ int   g_bg[HALF_PIX];
__device__ int   g_blkcnt[360];
__device__ float g_sum1[E_CH], g_sumsq1[E_CH];
__device__ float g_sum2[E_CH], g_sumsq2[E_CH];

// ---------------- init ----------------
__global__ void k_init() {
    int t = threadIdx.x;
    if (t < 64) g_sum1[t] = 0.f;
    else if (t < 128) g_sumsq1[t - 64] = 0.f;
    else if (t < 192) g_sum2[t - 128] = 0.f;
    else if (t < 256) g_sumsq2[t - 192] = 0.f;
}

// ---------------- scanA ----------------
#define SCAN_B 352
__global__ void k_scanA(const int* __restrict__ prop) {
    int idx = blockIdx.x * 256 + threadIdx.x;
    int v = (idx < N_PIX) ? (prop[idx] != 0) : 0;
    unsigned m = __ballot_sync(0xffffffffu, v);
    __shared__ int wc[8];
    if ((threadIdx.x & 31) == 0) wc[threadIdx.x >> 5] = __popc(m);
    __syncthreads();
    if (threadIdx.x == 0) {
        int t = 0;
        for (int w = 0; w < 8; w++) t += wc[w];
        g_blkcnt[blockIdx.x] = t;
    }
}

// ---------------- scanBC ----------------
__global__ void k_scanBC(const int* __restrict__ prop) {
    int tid = threadIdx.x;
    int b = blockIdx.x;
    int acc = 0;
    for (int i = tid; i < b; i += 256) acc += g_blkcnt[i];
    __shared__ int red[256];
    red[tid] = acc;
    __syncthreads();
    for (int off = 128; off > 0; off >>= 1) {
        if (tid < off) red[tid] += red[tid + off];
        __syncthreads();
    }
    int blkobj = red[0];

    int idx = b * 256 + tid;
    int valid = idx < N_PIX;
    int v = valid ? (prop[idx] != 0) : 0;
    unsigned objm = __ballot_sync(0xffffffffu, v);
    unsigned valm = __ballot_sync(0xffffffffu, valid);
    int lane = tid & 31, w = tid >> 5;
    __shared__ int wobj[8], wval[8];
    if (lane == 0) { wobj[w] = __popc(objm); wval[w] = __popc(valm); }
    __syncthreads();
    int objbase = 0, valbase = 0;
    for (int i = 0; i < w; i++) { objbase += wobj[i]; valbase += wval[i]; }
    unsigned ltm = (1u << lane) - 1u;
    if (valid) {
        if (v) {
            g_obj[blkobj + objbase + __popc(objm & ltm)] = idx;
        } else {
            int bg_before_blk = b * 256 - blkobj;
            int intra = (valbase - objbase) + (__popc(valm & ltm) - __popc(objm & ltm));
            g_bg[bg_before_blk + intra] = idx;
        }
    }
}

// block-level stats reduction (32 channels, 16 ull accumulators)
__device__ __forceinline__ void stats_block_reduce16(ull* acc2, float* ssum, float* ssq,
                                                     float* gsum, float* gsq, int ebase,
                                                     int tid, int lane, int warp) {
#pragma unroll 4
    for (int k = 0; k < 16; k++) {
        ull s = acc2[k];
        ull q = mul2(acc2[k], acc2[k]);
#pragma unroll
        for (int o = 16; o > 0; o >>= 1) {
            s = add2(s, __shfl_xor_sync(0xffffffffu, s, o));
            q = add2(q, __shfl_xor_sync(0xffffffffu, q, o));
        }
        if (lane == 0) {
            float2 sf = u2f(s), qf = u2f(q);
            ssum[warp * 32 + 2 * k]     = sf.x;
            ssum[warp * 32 + 2 * k + 1] = sf.y;
            ssq[warp * 32 + 2 * k]      = qf.x;
            ssq[warp * 32 + 2 * k + 1]  = qf.y;
        }
    }
    __syncthreads();
    if (tid < 32) {
        float t = 0.f;
#pragma unroll
        for (int w = 0; w < 8; w++) t += ssum[w * 32 + tid];
        atomicAdd(&gsum[ebase + tid], t);
    } else if (tid < 64) {
        int c = tid - 32;
        float t = 0.f;
#pragma unroll
        for (int w = 0; w < 8; w++) t += ssq[w * 32 + c];
        atomicAdd(&gsq[ebase + c], t);
    }
}

// block-level stats reduction (64 channels, 32 ull accumulators)
__device__ __forceinline__ void stats_block_reduce(ull* acc2, float* ssum, float* ssq,
                                                   float* gsum, float* gsq,
                                                   int tid, int lane, int warp) {
#pragma unroll 4
    for (int k = 0; k < 32; k++) {
        ull s = acc2[k];
        ull q = mul2(acc2[k], acc2[k]);
#pragma unroll
        for (int o = 16; o > 0; o >>= 1) {
            s = add2(s, __shfl_xor_sync(0xffffffffu, s, o));
            q = add2(q, __shfl_xor_sync(0xffffffffu, q, o));
        }
        if (lane == 0) {
            float2 sf = u2f(s), qf = u2f(q);
            ssum[warp * 64 + 2 * k]     = sf.x;
            ssum[warp * 64 + 2 * k + 1] = sf.y;
            ssq[warp * 64 + 2 * k]      = qf.x;
            ssq[warp * 64 + 2 * k + 1]  = qf.y;
        }
    }
    __syncthreads();
    if (tid < 64) {
        float t = 0.f;
#pragma unroll
        for (int w = 0; w < 8; w++) t += ssum[w * 64 + tid];
        atomicAdd(&gsum[tid], t);
    } else if (tid < 128) {
        int c = tid - 64;
        float t = 0.f;
#pragma unroll
        for (int w = 0; w < 8; w++) t += ssq[w * 64 + c];
        atomicAdd(&gsq[c], t);
    }
}

// ---------------- conv1: e-split halves (blockIdx.y), 3 CTAs/SM ----------------
__global__ __launch_bounds__(256, 3) void k_conv1(const float* __restrict__ x,
                                                  const float* __restrict__ w) {
    __shared__ float ws[C_IN * 32];      // [c][e'] for this half (32 KB)
    __shared__ float ssum[256], ssq[256];
    int tid = threadIdx.x;
    int ebase = blockIdx.y * 32;
    for (int i = tid; i < C_IN * 32; i += 256) {
        int c = i >> 5, e = i & 31;
        ws[c * 32 + e] = w[(ebase + e) * C_IN + c];
    }
    __syncthreads();
    int p = blockIdx.x * 256 + tid;
    bool valid = p < N_PIX;

    ull acc2[16];
#pragma unroll
    for (int i = 0; i < 16; i++) acc2[i] = 0ull;

    if (valid) {
        for (int c0 = 0; c0 < C_IN; c0 += 16) {
            float xr[16];
#pragma unroll
            for (int i = 0; i < 16; i++)
                xr[i] = __ldg(&x[(size_t)(c0 + i) * N_PIX + p]);
#pragma unroll
            for (int i = 0; i < 16; i++) {
                ull xd = fdup(xr[i]);
                const float* wr = &ws[(c0 + i) * 32];
#pragma unroll
                for (int k = 0; k < 8; k++) {
                    ulonglong2 wv = *(const ulonglong2*)&wr[k * 4];
                    fma2(acc2[2 * k],     wv.x, xd);
                    fma2(acc2[2 * k + 1], wv.y, xd);
                }
            }
        }
        // row-major store (attn gather): 32 floats at offset p*64 + ebase
        ull* op = (ull*)&g_h[(size_t)p * 64 + ebase];
#pragma unroll
        for (int i = 0; i < 16; i++) op[i] = acc2[i];
        // channel-major store
#pragma unroll
        for (int i = 0; i < 16; i++) {
            float2 f = u2f(acc2[i]);
            g_h_cp[(size_t)(ebase + 2 * i) * N_PIX + p]     = f.x;
            g_h_cp[(size_t)(ebase + 2 * i + 1) * N_PIX + p] = f.y;
        }
    }

    stats_block_reduce16(acc2, ssum, ssq, g_sum1, g_sumsq1, ebase, tid, tid & 31, tid >> 5);
}

// ---------------- attention: r8 configuration (4 rows/warp, 384 threads) ----------------
#define ATT_THREADS 384
#define ATT_WARPS 12
#define SM_ATT_FLOATS (64 + 64 + 1152 * 3 + 14400 + 9600 * 3 + 300)
#define SM_ATT_BYTES (SM_ATT_FLOATS * 4)

__global__ __launch_bounds__(ATT_THREADS, 1) void k_attn(const float* __restrict__ wq,
                                                         const float* __restrict__ wkv,
                                                         const int* __restrict__ rand_inds,
                                                         const float* __restrict__ bn1_g,
                                                         const float* __restrict__ bn1_b) {
    extern __shared__ float sm[];
    float* sc1    = sm;                    // 64
    float* bi1    = sm + 64;               // 64
    float* wq_t   = sm + 128;              // 32*36
    float* wk_t   = wq_t + 1152;
    float* wv_t   = wk_t + 1152;
    float* p_rows = wv_t + 1152;           // 14400 (seq alias)
    float* q_s    = p_rows + 14400;        // 9600
    float* k_s    = q_s + 9600;            // 9600
    float* v_t    = k_s + 9600;            // 9600 : [d][300]
    int*   pix_s  = (int*)(v_t + 9600);    // 300
    float* seq_s  = p_rows;

    int tid = threadIdx.x, warp = tid >> 5, lane = tid & 31;
    int b = blockIdx.x;
    int head = b / CROP;
    int iblk = b - head * CROP;
    int hoff = head * DH;

    if (tid < 64) {
        float m = g_sum1[tid] * (1.f / (float)N_PIX);
        float var = g_sumsq1[tid] * (1.f / (float)N_PIX) - m * m;
        float sc = bn1_g[tid] * rsqrtf(var + 1e-5f);
        sc1[tid] = sc;
        bi1[tid] = bn1_b[tid] - m * sc;
    }
    const int* src = (iblk < CROP / 2) ? g_obj : g_bg;
    const int* ri = rand_inds + (size_t)head * N_PIX + (size_t)iblk * CROP;
    for (int j = tid; j < CROP; j += ATT_THREADS) pix_s[j] = src[ri[j]];
    for (int i = tid; i < 1024; i += ATT_THREADS) {
        int e = i >> 5, d = i & 31;
        wq_t[d * 36 + e] = wq[i];
    }
    for (int i = tid; i < 2048; i += ATT_THREADS) {
        int e = i >> 6, c = i & 63;
        if (c < 32) wk_t[c * 36 + e] = wkv[i];
        else        wv_t[(c - 32) * 36 + e] = wkv[i];
    }
    __syncthreads();

    // gather + BN1 + relu, XOR-swizzled [j][32]
    for (int u = tid; u < CROP * 8; u += ATT_THREADS) {
        int j = u >> 3, seg = u & 7;
        int ch = hoff + seg * 4;
        float4 v = *(const float4*)&g_h[(size_t)pix_s[j] * 64 + ch];
        float4 s4 = *(const float4*)&sc1[ch];
        float4 b4 = *(const float4*)&bi1[ch];
        v.x = fmaxf(fmaf(v.x, s4.x, b4.x), 0.f);
        v.y = fmaxf(fmaf(v.y, s4.y, b4.y), 0.f);
        v.z = fmaxf(fmaf(v.z, s4.z, b4.z), 0.f);
        v.w = fmaxf(fmaf(v.w, s4.w, b4.w), 0.f);
        int pc = seg ^ (j & 7);
        *(float4*)&seq_s[j * 32 + pc * 4] = v;
    }
    __syncthreads();

    // QKV with register-resident weights (d = lane)
    {
        ull rq[16], rk[16], rv[16];
#pragma unroll
        for (int e2 = 0; e2 < 8; e2++) {
            ulonglong2 t;
            t = *(const ulonglong2*)&wq_t[lane * 36 + e2 * 4]; rq[2*e2] = t.x; rq[2*e2+1] = t.y;
            t = *(const ulonglong2*)&wk_t[lane * 36 + e2 * 4]; rk[2*e2] = t.x; rk[2*e2+1] = t.y;
            t = *(const ulonglong2*)&wv_t[lane * 36 + e2 * 4]; rv[2*e2] = t.x; rv[2*e2+1] = t.y;
        }
        for (int j = warp; j < CROP; j += ATT_WARPS) {
            int sw2 = (j & 7) << 2;
            ull aq = 0, ak = 0, av = 0;
#pragma unroll
            for (int e4 = 0; e4 < 8; e4++) {
                ulonglong2 sp = *(const ulonglong2*)&seq_s[j * 32 + ((e4 << 2) ^ sw2)];
                fma2(aq, sp.x, rq[2*e4]);
                fma2(ak, sp.x, rk[2*e4]);
                fma2(av, sp.x, rv[2*e4]);
                fma2(aq, sp.y, rq[2*e4+1]);
                fma2(ak, sp.y, rk[2*e4+1]);
                fma2(av, sp.y, rv[2*e4+1]);
            }
            int wi = j * 32 + (lane ^ sw2);
            q_s[wi] = hsum2(aq);
            k_s[wi] = hsum2(ak);
            v_t[lane * 300 + j] = hsum2(av);
        }
    }
    __syncthreads();

    const float scale = 0.17677669529663687f; // 1/sqrt(32)
    float* pw = &p_rows[warp * 4 * 300];
    for (int rp = warp; rp < 75; rp += ATT_WARPS) {
        int r0 = rp * 4;
        ull a[4][10];
#pragma unroll
        for (int r = 0; r < 4; r++)
#pragma unroll
            for (int jj = 0; jj < 10; jj++) a[r][jj] = 0ull;

#pragma unroll
        for (int c = 0; c < 8; c++) {
            ull qx[4], qy[4];
#pragma unroll
            for (int r = 0; r < 4; r++) {
                int row = r0 + r;
                ulonglong2 t = *(const ulonglong2*)&q_s[row * 32 + ((c << 2) ^ ((row & 7) << 2))];
                qx[r] = t.x; qy[r] = t.y;
            }
#pragma unroll
            for (int jj = 0; jj < 10; jj++) {
                int j = lane + (jj << 5);
                int jc = (j < CROP) ? j : 0;
                ulonglong2 kv = *(const ulonglong2*)&k_s[jc * 32 + ((c << 2) ^ ((jc & 7) << 2))];
                fma2(a[0][jj], qx[0], kv.x);
                fma2(a[1][jj], qx[1], kv.x);
                fma2(a[2][jj], qx[2], kv.x);
                fma2(a[3][jj], qx[3], kv.x);
                fma2(a[0][jj], qy[0], kv.y);
                fma2(a[1][jj], qy[1], kv.y);
                fma2(a[2][jj], qy[2], kv.y);
                fma2(a[3][jj], qy[3], kv.y);
            }
        }
#pragma unroll
        for (int r = 0; r < 4; r++) {
            float sv[10];
            float mx = -1e30f;
#pragma unroll
            for (int jj = 0; jj < 10; jj++) {
                float s = hsum2(a[r][jj]) * scale;
                sv[jj] = s;
                if (lane + (jj << 5) < CROP) mx = fmaxf(mx, s);
            }
#pragma unroll
            for (int o = 16; o > 0; o >>= 1)
                mx = fmaxf(mx, __shfl_xor_sync(0xffffffffu, mx, o));
            float sum = 0.f;
#pragma unroll
            for (int jj = 0; jj < 10; jj++) {
                int j = lane + (jj << 5);
                float e = (j < CROP) ? __expf(sv[jj] - mx) : 0.f;
                sv[jj] = e;
                sum += e;
            }
#pragma unroll
            for (int o = 16; o > 0; o >>= 1)
                sum += __shfl_xor_sync(0xffffffffu, sum, o);
            float inv = 1.f / sum;
#pragma unroll
            for (int jj = 0; jj < 10; jj++) {
                int j = lane + (jj << 5);
                if (j < CROP) pw[r * 300 + j] = sv[jj] * inv;
            }
        }
        __syncwarp();
        ull oa[4] = {0, 0, 0, 0}, ob[4] = {0, 0, 0, 0};
        const float* vrow = &v_t[lane * 300];
#pragma unroll 5
        for (int j4 = 0; j4 < 75; j4++) {
            ulonglong2 vv = *(const ulonglong2*)&vrow[j4 * 4];
#pragma unroll
            for (int r = 0; r < 4; r++) {
                ulonglong2 pv = *(const ulonglong2*)&pw[r * 300 + j4 * 4];
                fma2(oa[r], pv.x, vv.x);
                fma2(ob[r], pv.y, vv.y);
            }
        }
        // scatter into channel-major g_new
#pragma unroll
        for (int r = 0; r < 4; r++) {
            float ov = hsum2(add2(oa[r], ob[r]));
            int t = (r0 + r) * 32 + lane;
            int d = t / 300, mm = t - d * 300;
            g_new[(size_t)(hoff + d) * N_PIX + pix_s[mm]] = ov;
        }
        __syncwarp();
    }
}

// ---------------- w_out (batched loads) ----------------
__global__ __launch_bounds__(256) void k_wout(const float* __restrict__ w_out,
                                              const float* __restrict__ b_out) {
    __shared__ float ws[4096]; // [c][d]
    __shared__ float bs[64];
    int tid = threadIdx.x;
    for (int i = tid; i < 4096; i += 256) ws[i] = w_out[i];
    if (tid < 64) bs[tid] = b_out[tid];
    __syncthreads();
    int p = blockIdx.x * 256 + tid;
    if (p >= N_PIX) return;

    ull acc2[32];
#pragma unroll
    for (int i = 0; i < 32; i++) acc2[i] = 0ull;

    for (int c0 = 0; c0 < 64; c0 += 8) {
        float xr[8];
#pragma unroll
        for (int i = 0; i < 8; i++)
            xr[i] = __ldg(&g_new[(size_t)(c0 + i) * N_PIX + p]);
#pragma unroll
        for (int i = 0; i < 8; i++) {
            ull xd = fdup(xr[i]);
            const float* wr = &ws[(c0 + i) * 64];
#pragma unroll
            for (int k = 0; k < 16; k++) {
                ulonglong2 wv = *(const ulonglong2*)&wr[k * 4];
                fma2(acc2[2 * k],     wv.x, xd);
                fma2(acc2[2 * k + 1], wv.y, xd);
            }
        }
    }
#pragma unroll
    for (int i = 0; i < 32; i++) {
        float2 f = u2f(acc2[i]);
        g_xa[(size_t)(2 * i) * N_PIX + p]     = fmaxf(f.x + bs[2 * i], 0.f);
        g_xa[(size_t)(2 * i + 1) * N_PIX + p] = fmaxf(f.y + bs[2 * i + 1], 0.f);
    }
}

// ---------------- conv2 (batched loads) + fused BN2 stats ----------------
__global__ __launch_bounds__(256) void k_conv2(const float* __restrict__ w2,
                                               const float* __restrict__ bn1_g,
                                               const float* __restrict__ bn1_b) {
    __shared__ float w2t[8192]; // [c][o]
    __shared__ float sc1[64], bi1[64];
    __shared__ float ssum[512], ssq[512];
    int tid = threadIdx.x;
    for (int i = tid; i < 8192; i += 256) {
        int c = i >> 6, o = i & 63;
        w2t[i] = w2[o * 128 + c];
    }
    if (tid < 64) {
        float m = g_sum1[tid] * (1.f / (float)N_PIX);
        float var = g_sumsq1[tid] * (1.f / (float)N_PIX) - m * m;
        float sc = bn1_g[tid] * rsqrtf(var + 1e-5f);
        sc1[tid] = sc;
        bi1[tid] = bn1_b[tid] - m * sc;
    }
    __syncthreads();
    int p = blockIdx.x * 256 + tid;
    bool valid = p < N_PIX;

    ull acc2[32];
#pragma unroll
    for (int i = 0; i < 32; i++) acc2[i] = 0ull;

    if (valid) {
        for (int c0 = 0; c0 < 64; c0 += 8) {
            float xr[8];
#pragma unroll
            for (int i = 0; i < 8; i++)
                xr[i] = __ldg(&g_xa[(size_t)(c0 + i) * N_PIX + p]);
#pragma unroll
            for (int i = 0; i < 8; i++) {
                ull xd = fdup(xr[i]);
                const float* wr = &w2t[(c0 + i) * 64];
#pragma unroll
                for (int k = 0; k < 16; k++) {
                    ulonglong2 wv = *(const ulonglong2*)&wr[k * 4];
                    fma2(acc2[2 * k],     wv.x, xd);
                    fma2(acc2[2 * k + 1], wv.y, xd);
                }
            }
        }
        for (int c0 = 0; c0 < 64; c0 += 8) {
            float xr[8];
#pragma unroll
            for (int i = 0; i < 8; i++)
                xr[i] = __ldg(&g_h_cp[(size_t)(c0 + i) * N_PIX + p]);
#pragma unroll
            for (int i = 0; i < 8; i++) {
                float hs = fmaxf(fmaf(xr[i], sc1[c0 + i], bi1[c0 + i]), 0.f);
                ull hd = fdup(hs);
                const float* wr = &w2t[(64 + c0 + i) * 64];
#pragma unroll
                for (int k = 0; k < 16; k++) {
                    ulonglong2 wv = *(const ulonglong2*)&wr[k * 4];
                    fma2(acc2[2 * k],     wv.x, hd);
                    fma2(acc2[2 * k + 1], wv.y, hd);
                }
            }
        }
#pragma unroll
        for (int i = 0; i < 32; i++) {
            float2 f = u2f(acc2[i]);
            g_outpre[(size_t)(2 * i) * N_PIX + p]     = f.x;
            g_outpre[(size_t)(2 * i + 1) * N_PIX + p] = f.y;
        }
    }

    stats_block_reduce(acc2, ssum, ssq, g_sum2, g_sumsq2, tid, tid & 31, tid >> 5);
}

// ---------------- BN2 apply ----------------
__global__ void k_apply2(const float* __restrict__ g, const float* __restrict__ b,
                         float* __restrict__ out) {
    __shared__ float ssc, sbi;
    int c = blockIdx.y;
    if (threadIdx.x == 0) {
        float m = g_sum2[c] * (1.f / (float)N_PIX);
        float var = g_sumsq2[c] * (1.f / (float)N_PIX) - m * m;
        float sc = g[c] * rsqrtf(var + 1e-5f);
        ssc = sc;
        sbi = b[c] - m * sc;
    }
    __syncthreads();
    int p = blockIdx.x * 256 + threadIdx.x;
    if (p >= N_PIX) return;
    float v = g_outpre[(size_t)c * N_PIX + p] * ssc + sbi;
    out[(size_t)c * N_PIX + p] = v > 0.f ? v : 0.f;
}

// ---------------- launch ----------------
extern "C" void kernel_launch(void* const* d_in, const int* in_sizes, int n_in,
                              void* d_out, int out_size) {
    const float* x         = (const float*)d_in[0];
    const int*   prop      = (const int*)d_in[1];
    const int*   rand_inds = (const int*)d_in[2];
    const float* w_conv1   = (const float*)d_in[3];
    const float* bn1_g     = (const float*)d_in[4];
    const float* bn1_b     = (const float*)d_in[5];
    const float* wq        = (const float*)d_in[6];
    const float* wkv       = (const float*)d_in[7];
    const float* w_out     = (const float*)d_in[8];
    const float* b_out     = (const float*)d_in[9];
    const float* w_conv2   = (const float*)d_in[10];
    const float* bn2_g     = (const float*)d_in[11];
    const float* bn2_b     = (const float*)d_in[12];
    float* out = (float*)d_out;

    cudaFuncSetAttribute(k_attn, cudaFuncAttributeMaxDynamicSharedMemorySize, SM_ATT_BYTES);

    k_init<<<1, 256>>>();
    k_scanA<<<SCAN_B, 256>>>(prop);
    k_scanBC<<<SCAN_B, 256>>>(prop);
    dim3 gc1((N_PIX + 255) / 256, 2);
    k_conv1<<<gc1, 256>>>(x, w_conv1);
    k_attn<<<HEADS * CROP, ATT_THREADS, SM_ATT_BYTES>>>(wq, wkv, rand_inds, bn1_g, bn1_b);
    k_wout<<<(N_PIX + 255) / 256, 256>>>(w_out, b_out);
    k_conv2<<<(N_PIX + 255) / 256, 256>>>(w_conv2, bn1_g, bn1_b);
    dim3 g2((N_PIX + 255) / 256, E_CH);
    k_apply2<<<g2, 256>>>(bn2_g, bn2_b, out);
}

// round 12
// speedup vs baseline: 1.4159x; 1.0501x over previous
#include <cuda_runtime.h>
#include <math.h>

#define N_PIX    90000
#define HALF_PIX 45000
#define C_IN     256
#define E_CH     64
#define CROP     300
#define HEADS    2
#define DH       32

typedef unsigned long long ull;

__device__ __forceinline__ void fma2(ull& d, ull a, ull b) {
    asm("fma.rn.f32x2 %0, %1, %2, %0;" : "+l"(d) : "l"(a), "l"(b));
}
__device__ __forceinline__ ull add2(ull a, ull b) {
    ull r; asm("add.rn.f32x2 %0, %1, %2;" : "=l"(r) : "l"(a), "l"(b)); return r;
}
__device__ __forceinline__ ull mul2(ull a, ull b) {
    ull r; asm("mul.rn.f32x2 %0, %1, %2;" : "=l"(r) : "l"(a), "l"(b)); return r;
}
__device__ __forceinline__ ull fdup(float v) {
    ull r; asm("mov.b64 %0, {%1, %1};" : "=l"(r) : "f"(v)); return r;
}
__device__ __forceinline__ float2 u2f(ull v) {
    float2 f; asm("mov.b64 {%0, %1}, %2;" : "=f"(f.x), "=f"(f.y) : "l"(v)); return f;
}
__device__ __forceinline__ float hsum2(ull v) { float2 f = u2f(v); return f.x + f.y; }

// ---------------- scratch ----------------
__device__ float g_h[N_PIX * E_CH];        // [p][c] pre-BN1 (attn gather)
__device__ float g_h_cp[E_CH * N_PIX];     // [c][p] pre-BN1 (epilogue streaming)
__device__ float g_new[E_CH * N_PIX];      // [c][p] attention scatter target
__device__ float g_xa[E_CH * N_PIX];       // [d][p] relu(w_out . new + b)
__device__ float g_outpre[E_CH * N_PIX];   // [c][p] pre-BN2
__device__ int   g_obj[HALF_PIX];
__device__ int   g_bg[HALF_PIX];
__device__ int   g_blkcnt[360];
__device__ float g_sum1[E_CH], g_sumsq1[E_CH];
__device__ float g_sum2[E_CH], g_sumsq2[E_CH];

// ---------------- init ----------------
__global__ void k_init() {
    int t = threadIdx.x;
    if (t < 64) g_sum1[t] = 0.f;
    else if (t < 128) g_sumsq1[t - 64] = 0.f;
    else if (t < 192) g_sum2[t - 128] = 0.f;
    else if (t < 256) g_sumsq2[t - 192] = 0.f;
}

// ---------------- scanA ----------------
#define SCAN_B 352
__global__ void k_scanA(const int* __restrict__ prop) {
    int idx = blockIdx.x * 256 + threadIdx.x;
    int v = (idx < N_PIX) ? (prop[idx] != 0) : 0;
    unsigned m = __ballot_sync(0xffffffffu, v);
    __shared__ int wc[8];
    if ((threadIdx.x & 31) == 0) wc[threadIdx.x >> 5] = __popc(m);
    __syncthreads();
    if (threadIdx.x == 0) {
        int t = 0;
        for (int w = 0; w < 8; w++) t += wc[w];
        g_blkcnt[blockIdx.x] = t;
    }
}

// ---------------- scanBC ----------------
__global__ void k_scanBC(const int* __restrict__ prop) {
    int tid = threadIdx.x;
    int b = blockIdx.x;
    int acc = 0;
    for (int i = tid; i < b; i += 256) acc += g_blkcnt[i];
    __shared__ int red[256];
    red[tid] = acc;
    __syncthreads();
    for (int off = 128; off > 0; off >>= 1) {
        if (tid < off) red[tid] += red[tid + off];
        __syncthreads();
    }
    int blkobj = red[0];

    int idx = b * 256 + tid;
    int valid = idx < N_PIX;
    int v = valid ? (prop[idx] != 0) : 0;
    unsigned objm = __ballot_sync(0xffffffffu, v);
    unsigned valm = __ballot_sync(0xffffffffu, valid);
    int lane = tid & 31, w = tid >> 5;
    __shared__ int wobj[8], wval[8];
    if (lane == 0) { wobj[w] = __popc(objm); wval[w] = __popc(valm); }
    __syncthreads();
    int objbase = 0, valbase = 0;
    for (int i = 0; i < w; i++) { objbase += wobj[i]; valbase += wval[i]; }
    unsigned ltm = (1u << lane) - 1u;
    if (valid) {
        if (v) {
            g_obj[blkobj + objbase + __popc(objm & ltm)] = idx;
        } else {
            int bg_before_blk = b * 256 - blkobj;
            int intra = (valbase - objbase) + (__popc(valm & ltm) - __popc(objm & ltm));
            g_bg[bg_before_blk + intra] = idx;
        }
    }
}

// stats reduce for 16 channels (8 ull) at gsum[ebase..]
__device__ __forceinline__ void stats_block_reduce8(ull* s8, ull* q8, float* ssum, float* ssq,
                                                    float* gsum, float* gsq, int ebase,
                                                    int tid, int lane, int warp) {
#pragma unroll
    for (int k = 0; k < 8; k++) {
        ull s = s8[k];
        ull q = q8[k];
#pragma unroll
        for (int o = 16; o > 0; o >>= 1) {
            s = add2(s, __shfl_xor_sync(0xffffffffu, s, o));
            q = add2(q, __shfl_xor_sync(0xffffffffu, q, o));
        }
        if (lane == 0) {
            float2 sf = u2f(s), qf = u2f(q);
            ssum[warp * 16 + 2 * k]     = sf.x;
            ssum[warp * 16 + 2 * k + 1] = sf.y;
            ssq[warp * 16 + 2 * k]      = qf.x;
            ssq[warp * 16 + 2 * k + 1]  = qf.y;
        }
    }
    __syncthreads();
    if (tid < 16) {
        float t = 0.f;
#pragma unroll
        for (int w = 0; w < 8; w++) t += ssum[w * 16 + tid];
        atomicAdd(&gsum[ebase + tid], t);
    } else if (tid < 32) {
        int c = tid - 16;
        float t = 0.f;
#pragma unroll
        for (int w = 0; w < 8; w++) t += ssq[w * 16 + c];
        atomicAdd(&gsq[ebase + c], t);
    }
}

// stats reduce for 64 channels (32 ull)
__device__ __forceinline__ void stats_block_reduce(ull* acc2, float* ssum, float* ssq,
                                                   float* gsum, float* gsq,
                                                   int tid, int lane, int warp) {
#pragma unroll 4
    for (int k = 0; k < 32; k++) {
        ull s = acc2[k];
        ull q = mul2(acc2[k], acc2[k]);
#pragma unroll
        for (int o = 16; o > 0; o >>= 1) {
            s = add2(s, __shfl_xor_sync(0xffffffffu, s, o));
            q = add2(q, __shfl_xor_sync(0xffffffffu, q, o));
        }
        if (lane == 0) {
            float2 sf = u2f(s), qf = u2f(q);
            ssum[warp * 64 + 2 * k]     = sf.x;
            ssum[warp * 64 + 2 * k + 1] = sf.y;
            ssq[warp * 64 + 2 * k]      = qf.x;
            ssq[warp * 64 + 2 * k + 1]  = qf.y;
        }
    }
    __syncthreads();
    if (tid < 64) {
        float t = 0.f;
#pragma unroll
        for (int w = 0; w < 8; w++) t += ssum[w * 64 + tid];
        atomicAdd(&gsum[tid], t);
    } else if (tid < 128) {
        int c = tid - 64;
        float t = 0.f;
#pragma unroll
        for (int w = 0; w < 8; w++) t += ssq[w * 64 + c];
        atomicAdd(&gsq[c], t);
    }
}

// ---------------- conv1: 4 pixels/thread, 16 outputs/CTA (blockIdx.y of 4) ----------------
__global__ __launch_bounds__(256, 2) void k_conv1(const float* __restrict__ x,
                                                  const float* __restrict__ w) {
    __shared__ float ws[C_IN * 16];      // [c][e'] 16 KB
    __shared__ float ssum[128], ssq[128];
    int tid = threadIdx.x;
    int ebase = blockIdx.y * 16;
    for (int i = tid; i < C_IN * 16; i += 256) {
        int c = i >> 4, e = i & 15;
        ws[c * 16 + e] = w[(ebase + e) * C_IN + c];
    }
    __syncthreads();
    int p0 = (blockIdx.x * 256 + tid) * 4;
    bool valid = p0 < N_PIX;

    ull acc[4][8];
#pragma unroll
    for (int px = 0; px < 4; px++)
#pragma unroll
        for (int i = 0; i < 8; i++) acc[px][i] = 0ull;

    if (valid) {
        for (int c0 = 0; c0 < C_IN; c0 += 4) {
            float4 xr[4];
#pragma unroll
            for (int i = 0; i < 4; i++)
                xr[i] = __ldg((const float4*)&x[(size_t)(c0 + i) * N_PIX + p0]);
#pragma unroll
            for (int i = 0; i < 4; i++) {
                const ulonglong2* wr = (const ulonglong2*)&ws[(c0 + i) * 16];
                ulonglong2 w0 = wr[0], w1 = wr[1], w2 = wr[2], w3 = wr[3];
                float xs[4] = {xr[i].x, xr[i].y, xr[i].z, xr[i].w};
#pragma unroll
                for (int px = 0; px < 4; px++) {
                    ull xd = fdup(xs[px]);
                    fma2(acc[px][0], w0.x, xd);
                    fma2(acc[px][1], w0.y, xd);
                    fma2(acc[px][2], w1.x, xd);
                    fma2(acc[px][3], w1.y, xd);
                    fma2(acc[px][4], w2.x, xd);
                    fma2(acc[px][5], w2.y, xd);
                    fma2(acc[px][6], w3.x, xd);
                    fma2(acc[px][7], w3.y, xd);
                }
            }
        }
        // row-major stores for attn gather
#pragma unroll
        for (int px = 0; px < 4; px++) {
            ull* op = (ull*)&g_h[(size_t)(p0 + px) * 64 + ebase];
#pragma unroll
            for (int i = 0; i < 8; i++) op[i] = acc[px][i];
        }
        // channel-major stores: float4 per channel (coalesced)
#pragma unroll
        for (int i = 0; i < 8; i++) {
            float2 f0 = u2f(acc[0][i]), f1 = u2f(acc[1][i]);
            float2 f2 = u2f(acc[2][i]), f3 = u2f(acc[3][i]);
            *(float4*)&g_h_cp[(size_t)(ebase + 2 * i) * N_PIX + p0] =
                make_float4(f0.x, f1.x, f2.x, f3.x);
            *(float4*)&g_h_cp[(size_t)(ebase + 2 * i + 1) * N_PIX + p0] =
                make_float4(f0.y, f1.y, f2.y, f3.y);
        }
    }

    // BN1 stats: combine 4 px then block-reduce
    ull s8[8], q8[8];
#pragma unroll
    for (int i = 0; i < 8; i++) {
        s8[i] = add2(add2(acc[0][i], acc[1][i]), add2(acc[2][i], acc[3][i]));
        q8[i] = add2(add2(mul2(acc[0][i], acc[0][i]), mul2(acc[1][i], acc[1][i])),
                     add2(mul2(acc[2][i], acc[2][i]), mul2(acc[3][i], acc[3][i])));
    }
    stats_block_reduce8(s8, q8, ssum, ssq, g_sum1, g_sumsq1, ebase, tid, tid & 31, tid >> 5);
}

// ---------------- attention: r8 configuration (4 rows/warp, 384 threads) ----------------
#define ATT_THREADS 384
#define ATT_WARPS 12
#define SM_ATT_FLOATS (64 + 64 + 1152 * 3 + 14400 + 9600 * 3 + 300)
#define SM_ATT_BYTES (SM_ATT_FLOATS * 4)

__global__ __launch_bounds__(ATT_THREADS, 1) void k_attn(const float* __restrict__ wq,
                                                         const float* __restrict__ wkv,
                                                         const int* __restrict__ rand_inds,
                                                         const float* __restrict__ bn1_g,
                                                         const float* __restrict__ bn1_b) {
    extern __shared__ float sm[];
    float* sc1    = sm;                    // 64
    float* bi1    = sm + 64;               // 64
    float* wq_t   = sm + 128;              // 32*36
    float* wk_t   = wq_t + 1152;
    float* wv_t   = wk_t + 1152;
    float* p_rows = wv_t + 1152;           // 14400 (seq alias)
    float* q_s    = p_rows + 14400;        // 9600
    float* k_s    = q_s + 9600;            // 9600
    float* v_t    = k_s + 9600;            // 9600 : [d][300]
    int*   pix_s  = (int*)(v_t + 9600);    // 300
    float* seq_s  = p_rows;

    int tid = threadIdx.x, warp = tid >> 5, lane = tid & 31;
    int b = blockIdx.x;
    int head = b / CROP;
    int iblk = b - head * CROP;
    int hoff = head * DH;

    if (tid < 64) {
        float m = g_sum1[tid] * (1.f / (float)N_PIX);
        float var = g_sumsq1[tid] * (1.f / (float)N_PIX) - m * m;
        float sc = bn1_g[tid] * rsqrtf(var + 1e-5f);
        sc1[tid] = sc;
        bi1[tid] = bn1_b[tid] - m * sc;
    }
    const int* src = (iblk < CROP / 2) ? g_obj : g_bg;
    const int* ri = rand_inds + (size_t)head * N_PIX + (size_t)iblk * CROP;
    for (int j = tid; j < CROP; j += ATT_THREADS) pix_s[j] = src[ri[j]];
    for (int i = tid; i < 1024; i += ATT_THREADS) {
        int e = i >> 5, d = i & 31;
        wq_t[d * 36 + e] = wq[i];
    }
    for (int i = tid; i < 2048; i += ATT_THREADS) {
        int e = i >> 6, c = i & 63;
        if (c < 32) wk_t[c * 36 + e] = wkv[i];
        else        wv_t[(c - 32) * 36 + e] = wkv[i];
    }
    __syncthreads();

    // gather + BN1 + relu, XOR-swizzled [j][32]
    for (int u = tid; u < CROP * 8; u += ATT_THREADS) {
        int j = u >> 3, seg = u & 7;
        int ch = hoff + seg * 4;
        float4 v = *(const float4*)&g_h[(size_t)pix_s[j] * 64 + ch];
        float4 s4 = *(const float4*)&sc1[ch];
        float4 b4 = *(const float4*)&bi1[ch];
        v.x = fmaxf(fmaf(v.x, s4.x, b4.x), 0.f);
        v.y = fmaxf(fmaf(v.y, s4.y, b4.y), 0.f);
        v.z = fmaxf(fmaf(v.z, s4.z, b4.z), 0.f);
        v.w = fmaxf(fmaf(v.w, s4.w, b4.w), 0.f);
        int pc = seg ^ (j & 7);
        *(float4*)&seq_s[j * 32 + pc * 4] = v;
    }
    __syncthreads();

    // QKV with register-resident weights (d = lane)
    {
        ull rq[16], rk[16], rv[16];
#pragma unroll
        for (int e2 = 0; e2 < 8; e2++) {
            ulonglong2 t;
            t = *(const ulonglong2*)&wq_t[lane * 36 + e2 * 4]; rq[2*e2] = t.x; rq[2*e2+1] = t.y;
            t = *(const ulonglong2*)&wk_t[lane * 36 + e2 * 4]; rk[2*e2] = t.x; rk[2*e2+1] = t.y;
            t = *(const ulonglong2*)&wv_t[lane * 36 + e2 * 4]; rv[2*e2] = t.x; rv[2*e2+1] = t.y;
        }
        for (int j = warp; j < CROP; j += ATT_WARPS) {
            int sw2 = (j & 7) << 2;
            ull aq = 0, ak = 0, av = 0;
#pragma unroll
            for (int e4 = 0; e4 < 8; e4++) {
                ulonglong2 sp = *(const ulonglong2*)&seq_s[j * 32 + ((e4 << 2) ^ sw2)];
                fma2(aq, sp.x, rq[2*e4]);
                fma2(ak, sp.x, rk[2*e4]);
                fma2(av, sp.x, rv[2*e4]);
                fma2(aq, sp.y, rq[2*e4+1]);
                fma2(ak, sp.y, rk[2*e4+1]);
                fma2(av, sp.y, rv[2*e4+1]);
            }
            int wi = j * 32 + (lane ^ sw2);
            q_s[wi] = hsum2(aq);
            k_s[wi] = hsum2(ak);
            v_t[lane * 300 + j] = hsum2(av);
        }
    }
    __syncthreads();

    const float scale = 0.17677669529663687f; // 1/sqrt(32)
    float* pw = &p_rows[warp * 4 * 300];
    for (int rp = warp; rp < 75; rp += ATT_WARPS) {
        int r0 = rp * 4;
        ull a[4][10];
#pragma unroll
        for (int r = 0; r < 4; r++)
#pragma unroll
            for (int jj = 0; jj < 10; jj++) a[r][jj] = 0ull;

#pragma unroll
        for (int c = 0; c < 8; c++) {
            ull qx[4], qy[4];
#pragma unroll
            for (int r = 0; r < 4; r++) {
                int row = r0 + r;
                ulonglong2 t = *(const ulonglong2*)&q_s[row * 32 + ((c << 2) ^ ((row & 7) << 2))];
                qx[r] = t.x; qy[r] = t.y;
            }
#pragma unroll
            for (int jj = 0; jj < 10; jj++) {
                int j = lane + (jj << 5);
                int jc = (j < CROP) ? j : 0;
                ulonglong2 kv = *(const ulonglong2*)&k_s[jc * 32 + ((c << 2) ^ ((jc & 7) << 2))];
                fma2(a[0][jj], qx[0], kv.x);
                fma2(a[1][jj], qx[1], kv.x);
                fma2(a[2][jj], qx[2], kv.x);
                fma2(a[3][jj], qx[3], kv.x);
                fma2(a[0][jj], qy[0], kv.y);
                fma2(a[1][jj], qy[1], kv.y);
                fma2(a[2][jj], qy[2], kv.y);
                fma2(a[3][jj], qy[3], kv.y);
            }
        }
#pragma unroll
        for (int r = 0; r < 4; r++) {
            float sv[10];
            float mx = -1e30f;
#pragma unroll
            for (int jj = 0; jj < 10; jj++) {
                float s = hsum2(a[r][jj]) * scale;
                sv[jj] = s;
                if (lane + (jj << 5) < CROP) mx = fmaxf(mx, s);
            }
#pragma unroll
            for (int o = 16; o > 0; o >>= 1)
                mx = fmaxf(mx, __shfl_xor_sync(0xffffffffu, mx, o));
            float sum = 0.f;
#pragma unroll
            for (int jj = 0; jj < 10; jj++) {
                int j = lane + (jj << 5);
                float e = (j < CROP) ? __expf(sv[jj] - mx) : 0.f;
                sv[jj] = e;
                sum += e;
            }
#pragma unroll
            for (int o = 16; o > 0; o >>= 1)
                sum += __shfl_xor_sync(0xffffffffu, sum, o);
            float inv = 1.f / sum;
#pragma unroll
            for (int jj = 0; jj < 10; jj++) {
                int j = lane + (jj << 5);
                if (j < CROP) pw[r * 300 + j] = sv[jj] * inv;
            }
        }
        __syncwarp();
        ull oa[4] = {0, 0, 0, 0}, ob[4] = {0, 0, 0, 0};
        const float* vrow = &v_t[lane * 300];
#pragma unroll 5
        for (int j4 = 0; j4 < 75; j4++) {
            ulonglong2 vv = *(const ulonglong2*)&vrow[j4 * 4];
#pragma unroll
            for (int r = 0; r < 4; r++) {
                ulonglong2 pv = *(const ulonglong2*)&pw[r * 300 + j4 * 4];
                fma2(oa[r], pv.x, vv.x);
                fma2(ob[r], pv.y, vv.y);
            }
        }
#pragma unroll
        for (int r = 0; r < 4; r++) {
            float ov = hsum2(add2(oa[r], ob[r]));
            int t = (r0 + r) * 32 + lane;
            int d = t / 300, mm = t - d * 300;
            g_new[(size_t)(hoff + d) * N_PIX + pix_s[mm]] = ov;
        }
        __syncwarp();
    }
}

// ---------------- w_out (batched loads) ----------------
__global__ __launch_bounds__(256) void k_wout(const float* __restrict__ w_out,
                                              const float* __restrict__ b_out) {
    __shared__ float ws[4096]; // [c][d]
    __shared__ float bs[64];
    int tid = threadIdx.x;
    for (int i = tid; i < 4096; i += 256) ws[i] = w_out[i];
    if (tid < 64) bs[tid] = b_out[tid];
    __syncthreads();
    int p = blockIdx.x * 256 + tid;
    if (p >= N_PIX) return;

    ull acc2[32];
#pragma unroll
    for (int i = 0; i < 32; i++) acc2[i] = 0ull;

    for (int c0 = 0; c0 < 64; c0 += 8) {
        float xr[8];
#pragma unroll
        for (int i = 0; i < 8; i++)
            xr[i] = __ldg(&g_new[(size_t)(c0 + i) * N_PIX + p]);
#pragma unroll
        for (int i = 0; i < 8; i++) {
            ull xd = fdup(xr[i]);
            const float* wr = &ws[(c0 + i) * 64];
#pragma unroll
            for (int k = 0; k < 16; k++) {
                ulonglong2 wv = *(const ulonglong2*)&wr[k * 4];
                fma2(acc2[2 * k],     wv.x, xd);
                fma2(acc2[2 * k + 1], wv.y, xd);
            }
        }
    }
#pragma unroll
    for (int i = 0; i < 32; i++) {
        float2 f = u2f(acc2[i]);
        g_xa[(size_t)(2 * i) * N_PIX + p]     = fmaxf(f.x + bs[2 * i], 0.f);
        g_xa[(size_t)(2 * i + 1) * N_PIX + p] = fmaxf(f.y + bs[2 * i + 1], 0.f);
    }
}

// ---------------- conv2 (batched loads) + fused BN2 stats ----------------
__global__ __launch_bounds__(256) void k_conv2(const float* __restrict__ w2,
                                               const float* __restrict__ bn1_g,
                                               const float* __restrict__ bn1_b) {
    __shared__ float w2t[8192]; // [c][o]
    __shared__ float sc1[64], bi1[64];
    __shared__ float ssum[512], ssq[512];
    int tid = threadIdx.x;
    for (int i = tid; i < 8192; i += 256) {
        int c = i >> 6, o = i & 63;
        w2t[i] = w2[o * 128 + c];
    }
    if (tid < 64) {
        float m = g_sum1[tid] * (1.f / (float)N_PIX);
        float var = g_sumsq1[tid] * (1.f / (float)N_PIX) - m * m;
        float sc = bn1_g[tid] * rsqrtf(var + 1e-5f);
        sc1[tid] = sc;
        bi1[tid] = bn1_b[tid] - m * sc;
    }
    __syncthreads();
    int p = blockIdx.x * 256 + tid;
    bool valid = p < N_PIX;

    ull acc2[32];
#pragma unroll
    for (int i = 0; i < 32; i++) acc2[i] = 0ull;

    if (valid) {
        for (int c0 = 0; c0 < 64; c0 += 8) {
            float xr[8];
#pragma unroll
            for (int i = 0; i < 8; i++)
                xr[i] = __ldg(&g_xa[(size_t)(c0 + i) * N_PIX + p]);
#pragma unroll
            for (int i = 0; i < 8; i++) {
                ull xd = fdup(xr[i]);
                const float* wr = &w2t[(c0 + i) * 64];
#pragma unroll
                for (int k = 0; k < 16; k++) {
                    ulonglong2 wv = *(const ulonglong2*)&wr[k * 4];
                    fma2(acc2[2 * k],     wv.x, xd);
                    fma2(acc2[2 * k + 1], wv.y, xd);
                }
            }
        }
        for (int c0 = 0; c0 < 64; c0 += 8) {
            float xr[8];
#pragma unroll
            for (int i = 0; i < 8; i++)
                xr[i] = __ldg(&g_h_cp[(size_t)(c0 + i) * N_PIX + p]);
#pragma unroll
            for (int i = 0; i < 8; i++) {
                float hs = fmaxf(fmaf(xr[i], sc1[c0 + i], bi1[c0 + i]), 0.f);
                ull hd = fdup(hs);
                const float* wr = &w2t[(64 + c0 + i) * 64];
#pragma unroll
                for (int k = 0; k < 16; k++) {
                    ulonglong2 wv = *(const ulonglong2*)&wr[k * 4];
                    fma2(acc2[2 * k],     wv.x, hd);
                    fma2(acc2[2 * k + 1], wv.y, hd);
                }
            }
        }
#pragma unroll
        for (int i = 0; i < 32; i++) {
            float2 f = u2f(acc2[i]);
            g_outpre[(size_t)(2 * i) * N_PIX + p]     = f.x;
            g_outpre[(size_t)(2 * i + 1) * N_PIX + p] = f.y;
        }
    }

    stats_block_reduce(acc2, ssum, ssq, g_sum2, g_sumsq2, tid, tid & 31, tid >> 5);
}

// ---------------- BN2 apply ----------------
__global__ void k_apply2(const float* __restrict__ g, const float* __restrict__ b,
                         float* __restrict__ out) {
    __shared__ float ssc, sbi;
    int c = blockIdx.y;
    if (threadIdx.x == 0) {
        float m = g_sum2[c] * (1.f / (float)N_PIX);
        float var = g_sumsq2[c] * (1.f / (float)N_PIX) - m * m;
        float sc = g[c] * rsqrtf(var + 1e-5f);
        ssc = sc;
        sbi = b[c] - m * sc;
    }
    __syncthreads();
    int p = blockIdx.x * 256 + threadIdx.x;
    if (p >= N_PIX) return;
    float v = g_outpre[(size_t)c * N_PIX + p] * ssc + sbi;
    out[(size_t)c * N_PIX + p] = v > 0.f ? v : 0.f;
}

// ---------------- launch ----------------
extern "C" void kernel_launch(void* const* d_in, const int* in_sizes, int n_in,
                              void* d_out, int out_size) {
    const float* x         = (const float*)d_in[0];
    const int*   prop      = (const int*)d_in[1];
    const int*   rand_inds = (const int*)d_in[2];
    const float* w_conv1   = (const float*)d_in[3];
    const float* bn1_g     = (const float*)d_in[4];
    const float* bn1_b     = (const float*)d_in[5];
    const float* wq        = (const float*)d_in[6];
    const float* wkv       = (const float*)d_in[7];
    const float* w_out     = (const float*)d_in[8];
    const float* b_out     = (const float*)d_in[9];
    const float* w_conv2   = (const float*)d_in[10];
    const float* bn2_g     = (const float*)d_in[11];
    const float* bn2_b     = (const float*)d_in[12];
    float* out = (float*)d_out;

    cudaFuncSetAttribute(k_attn, cudaFuncAttributeMaxDynamicSharedMemorySize, SM_ATT_BYTES);

    k_init<<<1, 256>>>();
    k_scanA<<<SCAN_B, 256>>>(prop);
    k_scanBC<<<SCAN_B, 256>>>(prop);
    dim3 gc1((N_PIX / 4 + 255) / 256, 4);
    k_conv1<<<gc1, 256>>>(x, w_conv1);
    k_attn<<<HEADS * CROP, ATT_THREADS, SM_ATT_BYTES>>>(wq, wkv, rand_inds, bn1_g, bn1_b);
    k_wout<<<(N_PIX + 255) / 256, 256>>>(w_out, b_out);
    k_conv2<<<(N_PIX + 255) / 256, 256>>>(w_conv2, bn1_g, bn1_b);
    dim3 g2((N_PIX + 255) / 256, E_CH);
    k_apply2<<<g2, 256>>>(bn2_g, bn2_b, out);
}

// round 13
// speedup vs baseline: 1.4907x; 1.0528x over previous
#include <cuda_runtime.h>
#include <math.h>

#define N_PIX    90000
#define HALF_PIX 45000
#define C_IN     256
#define E_CH     64
#define CROP     300
#define HEADS    2
#define DH       32

typedef unsigned long long ull;

__device__ __forceinline__ void fma2(ull& d, ull a, ull b) {
    asm("fma.rn.f32x2 %0, %1, %2, %0;" : "+l"(d) : "l"(a), "l"(b));
}
__device__ __forceinline__ ull add2(ull a, ull b) {
    ull r; asm("add.rn.f32x2 %0, %1, %2;" : "=l"(r) : "l"(a), "l"(b)); return r;
}
__device__ __forceinline__ ull mul2(ull a, ull b) {
    ull r; asm("mul.rn.f32x2 %0, %1, %2;" : "=l"(r) : "l"(a), "l"(b)); return r;
}
__device__ __forceinline__ ull fdup(float v) {
    ull r; asm("mov.b64 %0, {%1, %1};" : "=l"(r) : "f"(v)); return r;
}
__device__ __forceinline__ float2 u2f(ull v) {
    float2 f; asm("mov.b64 {%0, %1}, %2;" : "=f"(f.x), "=f"(f.y) : "l"(v)); return f;
}
__device__ __forceinline__ float hsum2(ull v) { float2 f = u2f(v); return f.x + f.y; }

// ---------------- scratch ----------------
__device__ float g_h[N_PIX * E_CH];        // [p][c] pre-BN1 (attn gather)
__device__ float g_h_cp[E_CH * N_PIX];     // [c][p] pre-BN1 (epilogue streaming)
__device__ float g_new[E_CH * N_PIX];      // [c][p] attention scatter target
__device__ float g_xa[E_CH * N_PIX];       // [d][p] relu(w_out . new + b)
__device__ float g_outpre[E_CH * N_PIX];   // [c][p] pre-BN2
__device__ int   g_obj[HALF_PIX];
__device__ int   g_bg[HALF_PIX];
__device__ int   g_blkcnt[360];
__device__ float g_sum1[E_CH], g_sumsq1[E_CH];
__device__ float g_sum2[E_CH], g_sumsq2[E_CH];

// ---------------- init ----------------
__global__ void k_init() {
    int t = threadIdx.x;
    if (t < 64) g_sum1[t] = 0.f;
    else if (t < 128) g_sumsq1[t - 64] = 0.f;
    else if (t < 192) g_sum2[t - 128] = 0.f;
    else if (t < 256) g_sumsq2[t - 192] = 0.f;
}

// ---------------- scanA ----------------
#define SCAN_B 352
__global__ void k_scanA(const int* __restrict__ prop) {
    int idx = blockIdx.x * 256 + threadIdx.x;
    int v = (idx < N_PIX) ? (prop[idx] != 0) : 0;
    unsigned m = __ballot_sync(0xffffffffu, v);
    __shared__ int wc[8];
    if ((threadIdx.x & 31) == 0) wc[threadIdx.x >> 5] = __popc(m);
    __syncthreads();
    if (threadIdx.x == 0) {
        int t = 0;
        for (int w = 0; w < 8; w++) t += wc[w];
        g_blkcnt[blockIdx.x] = t;
    }
}

// ---------------- scanBC ----------------
__global__ void k_scanBC(const int* __restrict__ prop) {
    int tid = threadIdx.x;
    int b = blockIdx.x;
    int acc = 0;
    for (int i = tid; i < b; i += 256) acc += g_blkcnt[i];
    __shared__ int red[256];
    red[tid] = acc;
    __syncthreads();
    for (int off = 128; off > 0; off >>= 1) {
        if (tid < off) red[tid] += red[tid + off];
        __syncthreads();
    }
    int blkobj = red[0];

    int idx = b * 256 + tid;
    int valid = idx < N_PIX;
    int v = valid ? (prop[idx] != 0) : 0;
    unsigned objm = __ballot_sync(0xffffffffu, v);
    unsigned valm = __ballot_sync(0xffffffffu, valid);
    int lane = tid & 31, w = tid >> 5;
    __shared__ int wobj[8], wval[8];
    if (lane == 0) { wobj[w] = __popc(objm); wval[w] = __popc(valm); }
    __syncthreads();
    int objbase = 0, valbase = 0;
    for (int i = 0; i < w; i++) { objbase += wobj[i]; valbase += wval[i]; }
    unsigned ltm = (1u << lane) - 1u;
    if (valid) {
        if (v) {
            g_obj[blkobj + objbase + __popc(objm & ltm)] = idx;
        } else {
            int bg_before_blk = b * 256 - blkobj;
            int intra = (valbase - objbase) + (__popc(valm & ltm) - __popc(objm & ltm));
            g_bg[bg_before_blk + intra] = idx;
        }
    }
}

// stats reduce for 8 channels (4 ull) at gsum[ebase..]
__device__ __forceinline__ void stats_block_reduce4(ull* s4, ull* q4, float* ssum, float* ssq,
                                                    float* gsum, float* gsq, int ebase,
                                                    int tid, int lane, int warp) {
#pragma unroll
    for (int k = 0; k < 4; k++) {
        ull s = s4[k];
        ull q = q4[k];
#pragma unroll
        for (int o = 16; o > 0; o >>= 1) {
            s = add2(s, __shfl_xor_sync(0xffffffffu, s, o));
            q = add2(q, __shfl_xor_sync(0xffffffffu, q, o));
        }
        if (lane == 0) {
            float2 sf = u2f(s), qf = u2f(q);
            ssum[warp * 8 + 2 * k]     = sf.x;
            ssum[warp * 8 + 2 * k + 1] = sf.y;
            ssq[warp * 8 + 2 * k]      = qf.x;
            ssq[warp * 8 + 2 * k + 1]  = qf.y;
        }
    }
    __syncthreads();
    if (tid < 8) {
        float t = 0.f;
#pragma unroll
        for (int w = 0; w < 8; w++) t += ssum[w * 8 + tid];
        atomicAdd(&gsum[ebase + tid], t);
    } else if (tid < 16) {
        int c = tid - 8;
        float t = 0.f;
#pragma unroll
        for (int w = 0; w < 8; w++) t += ssq[w * 8 + c];
        atomicAdd(&gsq[ebase + c], t);
    }
}

// stats reduce for 64 channels (32 ull)
__device__ __forceinline__ void stats_block_reduce(ull* acc2, float* ssum, float* ssq,
                                                   float* gsum, float* gsq,
                                                   int tid, int lane, int warp) {
#pragma unroll 4
    for (int k = 0; k < 32; k++) {
        ull s = acc2[k];
        ull q = mul2(acc2[k], acc2[k]);
#pragma unroll
        for (int o = 16; o > 0; o >>= 1) {
            s = add2(s, __shfl_xor_sync(0xffffffffu, s, o));
            q = add2(q, __shfl_xor_sync(0xffffffffu, q, o));
        }
        if (lane == 0) {
            float2 sf = u2f(s), qf = u2f(q);
            ssum[warp * 64 + 2 * k]     = sf.x;
            ssum[warp * 64 + 2 * k + 1] = sf.y;
            ssq[warp * 64 + 2 * k]      = qf.x;
            ssq[warp * 64 + 2 * k + 1]  = qf.y;
        }
    }
    __syncthreads();
    if (tid < 64) {
        float t = 0.f;
#pragma unroll
        for (int w = 0; w < 8; w++) t += ssum[w * 64 + tid];
        atomicAdd(&gsum[tid], t);
    } else if (tid < 128) {
        int c = tid - 64;
        float t = 0.f;
#pragma unroll
        for (int w = 0; w < 8; w++) t += ssq[w * 64 + c];
        atomicAdd(&gsq[c], t);
    }
}

// ---------------- conv1: 4 px/thread, 8 outputs/CTA (blockIdx.y of 8), 3 CTAs/SM ----------------
__global__ __launch_bounds__(256, 3) void k_conv1(const float* __restrict__ x,
                                                  const float* __restrict__ w) {
    __shared__ float ws[C_IN * 8];       // [c][e'] 8 KB
    __shared__ float ssum[64], ssq[64];
    int tid = threadIdx.x;
    int ebase = blockIdx.y * 8;
    for (int i = tid; i < C_IN * 8; i += 256) {
        int c = i >> 3, e = i & 7;
        ws[c * 8 + e] = w[(ebase + e) * C_IN + c];
    }
    __syncthreads();
    int p0 = (blockIdx.x * 256 + tid) * 4;
    bool valid = p0 < N_PIX;

    ull acc[4][4];
#pragma unroll
    for (int px = 0; px < 4; px++)
#pragma unroll
        for (int i = 0; i < 4; i++) acc[px][i] = 0ull;

    if (valid) {
        for (int c0 = 0; c0 < C_IN; c0 += 4) {
            float4 xr[4];
#pragma unroll
            for (int i = 0; i < 4; i++)
                xr[i] = __ldg((const float4*)&x[(size_t)(c0 + i) * N_PIX + p0]);
#pragma unroll
            for (int i = 0; i < 4; i++) {
                const ulonglong2* wr = (const ulonglong2*)&ws[(c0 + i) * 8];
                ulonglong2 w0 = wr[0], w1 = wr[1];
                float xs[4] = {xr[i].x, xr[i].y, xr[i].z, xr[i].w};
#pragma unroll
                for (int px = 0; px < 4; px++) {
                    ull xd = fdup(xs[px]);
                    fma2(acc[px][0], w0.x, xd);
                    fma2(acc[px][1], w0.y, xd);
                    fma2(acc[px][2], w1.x, xd);
                    fma2(acc[px][3], w1.y, xd);
                }
            }
        }
        // row-major stores for attn gather (8 floats at p*64+ebase; 32B aligned)
#pragma unroll
        for (int px = 0; px < 4; px++) {
            ull* op = (ull*)&g_h[(size_t)(p0 + px) * 64 + ebase];
#pragma unroll
            for (int i = 0; i < 4; i++) op[i] = acc[px][i];
        }
        // channel-major stores: float4 per channel (coalesced)
#pragma unroll
        for (int i = 0; i < 4; i++) {
            float2 f0 = u2f(acc[0][i]), f1 = u2f(acc[1][i]);
            float2 f2 = u2f(acc[2][i]), f3 = u2f(acc[3][i]);
            *(float4*)&g_h_cp[(size_t)(ebase + 2 * i) * N_PIX + p0] =
                make_float4(f0.x, f1.x, f2.x, f3.x);
            *(float4*)&g_h_cp[(size_t)(ebase + 2 * i + 1) * N_PIX + p0] =
                make_float4(f0.y, f1.y, f2.y, f3.y);
        }
    }

    // BN1 stats: combine 4 px then block-reduce
    ull s4[4], q4[4];
#pragma unroll
    for (int i = 0; i < 4; i++) {
        s4[i] = add2(add2(acc[0][i], acc[1][i]), add2(acc[2][i], acc[3][i]));
        q4[i] = add2(add2(mul2(acc[0][i], acc[0][i]), mul2(acc[1][i], acc[1][i])),
                     add2(mul2(acc[2][i], acc[2][i]), mul2(acc[3][i], acc[3][i])));
    }
    stats_block_reduce4(s4, q4, ssum, ssq, g_sum1, g_sumsq1, ebase, tid, tid & 31, tid >> 5);
}

// ---------------- attention: r8 configuration (4 rows/warp, 384 threads) ----------------
#define ATT_THREADS 384
#define ATT_WARPS 12
#define SM_ATT_FLOATS (64 + 64 + 1152 * 3 + 14400 + 9600 * 3 + 300)
#define SM_ATT_BYTES (SM_ATT_FLOATS * 4)

__global__ __launch_bounds__(ATT_THREADS, 1) void k_attn(const float* __restrict__ wq,
                                                         const float* __restrict__ wkv,
                                                         const int* __restrict__ rand_inds,
                                                         const float* __restrict__ bn1_g,
                                                         const float* __restrict__ bn1_b) {
    extern __shared__ float sm[];
    float* sc1    = sm;                    // 64
    float* bi1    = sm + 64;               // 64
    float* wq_t   = sm + 128;              // 32*36
    float* wk_t   = wq_t + 1152;
    float* wv_t   = wk_t + 1152;
    float* p_rows = wv_t + 1152;           // 14400 (seq alias)
    float* q_s    = p_rows + 14400;        // 9600
    float* k_s    = q_s + 9600;            // 9600
    float* v_t    = k_s + 9600;            // 9600 : [d][300]
    int*   pix_s  = (int*)(v_t + 9600);    // 300
    float* seq_s  = p_rows;

    int tid = threadIdx.x, warp = tid >> 5, lane = tid & 31;
    int b = blockIdx.x;
    int head = b / CROP;
    int iblk = b - head * CROP;
    int hoff = head * DH;

    if (tid < 64) {
        float m = g_sum1[tid] * (1.f / (float)N_PIX);
        float var = g_sumsq1[tid] * (1.f / (float)N_PIX) - m * m;
        float sc = bn1_g[tid] * rsqrtf(var + 1e-5f);
        sc1[tid] = sc;
        bi1[tid] = bn1_b[tid] - m * sc;
    }
    const int* src = (iblk < CROP / 2) ? g_obj : g_bg;
    const int* ri = rand_inds + (size_t)head * N_PIX + (size_t)iblk * CROP;
    for (int j = tid; j < CROP; j += ATT_THREADS) pix_s[j] = src[ri[j]];
    for (int i = tid; i < 1024; i += ATT_THREADS) {
        int e = i >> 5, d = i & 31;
        wq_t[d * 36 + e] = wq[i];
    }
    for (int i = tid; i < 2048; i += ATT_THREADS) {
        int e = i >> 6, c = i & 63;
        if (c < 32) wk_t[c * 36 + e] = wkv[i];
        else        wv_t[(c - 32) * 36 + e] = wkv[i];
    }
    __syncthreads();

    // gather + BN1 + relu, XOR-swizzled [j][32]
    for (int u = tid; u < CROP * 8; u += ATT_THREADS) {
        int j = u >> 3, seg = u & 7;
        int ch = hoff + seg * 4;
        float4 v = *(const float4*)&g_h[(size_t)pix_s[j] * 64 + ch];
        float4 s4 = *(const float4*)&sc1[ch];
        float4 b4 = *(const float4*)&bi1[ch];
        v.x = fmaxf(fmaf(v.x, s4.x, b4.x), 0.f);
        v.y = fmaxf(fmaf(v.y, s4.y, b4.y), 0.f);
        v.z = fmaxf(fmaf(v.z, s4.z, b4.z), 0.f);
        v.w = fmaxf(fmaf(v.w, s4.w, b4.w), 0.f);
        int pc = seg ^ (j & 7);
        *(float4*)&seq_s[j * 32 + pc * 4] = v;
    }
    __syncthreads();

    // QKV with register-resident weights (d = lane)
    {
        ull rq[16], rk[16], rv[16];
#pragma unroll
        for (int e2 = 0; e2 < 8; e2++) {
            ulonglong2 t;
            t = *(const ulonglong2*)&wq_t[lane * 36 + e2 * 4]; rq[2*e2] = t.x; rq[2*e2+1] = t.y;
            t = *(const ulonglong2*)&wk_t[lane * 36 + e2 * 4]; rk[2*e2] = t.x; rk[2*e2+1] = t.y;
            t = *(const ulonglong2*)&wv_t[lane * 36 + e2 * 4]; rv[2*e2] = t.x; rv[2*e2+1] = t.y;
        }
        for (int j = warp; j < CROP; j += ATT_WARPS) {
            int sw2 = (j & 7) << 2;
            ull aq = 0, ak = 0, av = 0;
#pragma unroll
            for (int e4 = 0; e4 < 8; e4++) {
                ulonglong2 sp = *(const ulonglong2*)&seq_s[j * 32 + ((e4 << 2) ^ sw2)];
                fma2(aq, sp.x, rq[2*e4]);
                fma2(ak, sp.x, rk[2*e4]);
                fma2(av, sp.x, rv[2*e4]);
                fma2(aq, sp.y, rq[2*e4+1]);
                fma2(ak, sp.y, rk[2*e4+1]);
                fma2(av, sp.y, rv[2*e4+1]);
            }
            int wi = j * 32 + (lane ^ sw2);
            q_s[wi] = hsum2(aq);
            k_s[wi] = hsum2(ak);
            v_t[lane * 300 + j] = hsum2(av);
        }
    }
    __syncthreads();

    const float scale = 0.17677669529663687f; // 1/sqrt(32)
    float* pw = &p_rows[warp * 4 * 300];
    for (int rp = warp; rp < 75; rp += ATT_WARPS) {
        int r0 = rp * 4;
        ull a[4][10];
#pragma unroll
        for (int r = 0; r < 4; r++)
#pragma unroll
            for (int jj = 0; jj < 10; jj++) a[r][jj] = 0ull;

#pragma unroll
        for (int c = 0; c < 8; c++) {
            ull qx[4], qy[4];
#pragma unroll
            for (int r = 0; r < 4; r++) {
                int row = r0 + r;
                ulonglong2 t = *(const ulonglong2*)&q_s[row * 32 + ((c << 2) ^ ((row & 7) << 2))];
                qx[r] = t.x; qy[r] = t.y;
            }
#pragma unroll
            for (int jj = 0; jj < 10; jj++) {
                int j = lane + (jj << 5);
                int jc = (j < CROP) ? j : 0;
                ulonglong2 kv = *(const ulonglong2*)&k_s[jc * 32 + ((c << 2) ^ ((jc & 7) << 2))];
                fma2(a[0][jj], qx[0], kv.x);
                fma2(a[1][jj], qx[1], kv.x);
                fma2(a[2][jj], qx[2], kv.x);
                fma2(a[3][jj], qx[3], kv.x);
                fma2(a[0][jj], qy[0], kv.y);
                fma2(a[1][jj], qy[1], kv.y);
                fma2(a[2][jj], qy[2], kv.y);
                fma2(a[3][jj], qy[3], kv.y);
            }
        }
#pragma unroll
        for (int r = 0; r < 4; r++) {
            float sv[10];
            float mx = -1e30f;
#pragma unroll
            for (int jj = 0; jj < 10; jj++) {
                float s = hsum2(a[r][jj]) * scale;
                sv[jj] = s;
                if (lane + (jj << 5) < CROP) mx = fmaxf(mx, s);
            }
#pragma unroll
            for (int o = 16; o > 0; o >>= 1)
                mx = fmaxf(mx, __shfl_xor_sync(0xffffffffu, mx, o));
            float sum = 0.f;
#pragma unroll
            for (int jj = 0; jj < 10; jj++) {
                int j = lane + (jj << 5);
                float e = (j < CROP) ? __expf(sv[jj] - mx) : 0.f;
                sv[jj] = e;
                sum += e;
            }
#pragma unroll
            for (int o = 16; o > 0; o >>= 1)
                sum += __shfl_xor_sync(0xffffffffu, sum, o);
            float inv = 1.f / sum;
#pragma unroll
            for (int jj = 0; jj < 10; jj++) {
                int j = lane + (jj << 5);
                if (j < CROP) pw[r * 300 + j] = sv[jj] * inv;
            }
        }
        __syncwarp();
        ull oa[4] = {0, 0, 0, 0}, ob[4] = {0, 0, 0, 0};
        const float* vrow = &v_t[lane * 300];
#pragma unroll 5
        for (int j4 = 0; j4 < 75; j4++) {
            ulonglong2 vv = *(const ulonglong2*)&vrow[j4 * 4];
#pragma unroll
            for (int r = 0; r < 4; r++) {
                ulonglong2 pv = *(const ulonglong2*)&pw[r * 300 + j4 * 4];
                fma2(oa[r], pv.x, vv.x);
                fma2(ob[r], pv.y, vv.y);
            }
        }
#pragma unroll
        for (int r = 0; r < 4; r++) {
            float ov = hsum2(add2(oa[r], ob[r]));
            int t = (r0 + r) * 32 + lane;
            int d = t / 300, mm = t - d * 300;
            g_new[(size_t)(hoff + d) * N_PIX + pix_s[mm]] = ov;
        }
        __syncwarp();
    }
}

// ---------------- w_out (batched loads) ----------------
__global__ __launch_bounds__(256) void k_wout(const float* __restrict__ w_out,
                                              const float* __restrict__ b_out) {
    __shared__ float ws[4096]; // [c][d]
    __shared__ float bs[64];
    int tid = threadIdx.x;
    for (int i = tid; i < 4096; i += 256) ws[i] = w_out[i];
    if (tid < 64) bs[tid] = b_out[tid];
    __syncthreads();
    int p = blockIdx.x * 256 + tid;
    if (p >= N_PIX) return;

    ull acc2[32];
#pragma unroll
    for (int i = 0; i < 32; i++) acc2[i] = 0ull;

    for (int c0 = 0; c0 < 64; c0 += 8) {
        float xr[8];
#pragma unroll
        for (int i = 0; i < 8; i++)
            xr[i] = __ldg(&g_new[(size_t)(c0 + i) * N_PIX + p]);
#pragma unroll
        for (int i = 0; i < 8; i++) {
            ull xd = fdup(xr[i]);
            const float* wr = &ws[(c0 + i) * 64];
#pragma unroll
            for (int k = 0; k < 16; k++) {
                ulonglong2 wv = *(const ulonglong2*)&wr[k * 4];
                fma2(acc2[2 * k],     wv.x, xd);
                fma2(acc2[2 * k + 1], wv.y, xd);
            }
        }
    }
#pragma unroll
    for (int i = 0; i < 32; i++) {
        float2 f = u2f(acc2[i]);
        g_xa[(size_t)(2 * i) * N_PIX + p]     = fmaxf(f.x + bs[2 * i], 0.f);
        g_xa[(size_t)(2 * i + 1) * N_PIX + p] = fmaxf(f.y + bs[2 * i + 1], 0.f);
    }
}

// ---------------- conv2 (batched loads) + fused BN2 stats ----------------
__global__ __launch_bounds__(256) void k_conv2(const float* __restrict__ w2,
                                               const float* __restrict__ bn1_g,
                                               const float* __restrict__ bn1_b) {
    __shared__ float w2t[8192]; // [c][o]
    __shared__ float sc1[64], bi1[64];
    __shared__ float ssum[512], ssq[512];
    int tid = threadIdx.x;
    for (int i = tid; i < 8192; i += 256) {
        int c = i >> 6, o = i & 63;
        w2t[i] = w2[o * 128 + c];
    }
    if (tid < 64) {
        float m = g_sum1[tid] * (1.f / (float)N_PIX);
        float var = g_sumsq1[tid] * (1.f / (float)N_PIX) - m * m;
        float sc = bn1_g[tid] * rsqrtf(var + 1e-5f);
        sc1[tid] = sc;
        bi1[tid] = bn1_b[tid] - m * sc;
    }
    __syncthreads();
    int p = blockIdx.x * 256 + tid;
    bool valid = p < N_PIX;

    ull acc2[32];
#pragma unroll
    for (int i = 0; i < 32; i++) acc2[i] = 0ull;

    if (valid) {
        for (int c0 = 0; c0 < 64; c0 += 8) {
            float xr[8];
#pragma unroll
            for (int i = 0; i < 8; i++)
                xr[i] = __ldg(&g_xa[(size_t)(c0 + i) * N_PIX + p]);
#pragma unroll
            for (int i = 0; i < 8; i++) {
                ull xd = fdup(xr[i]);
                const float* wr = &w2t[(c0 + i) * 64];
#pragma unroll
                for (int k = 0; k < 16; k++) {
                    ulonglong2 wv = *(const ulonglong2*)&wr[k * 4];
                    fma2(acc2[2 * k],     wv.x, xd);
                    fma2(acc2[2 * k + 1], wv.y, xd);
                }
            }
        }
        for (int c0 = 0; c0 < 64; c0 += 8) {
            float xr[8];
#pragma unroll
            for (int i = 0; i < 8; i++)
                xr[i] = __ldg(&g_h_cp[(size_t)(c0 + i) * N_PIX + p]);
#pragma unroll
            for (int i = 0; i < 8; i++) {
                float hs = fmaxf(fmaf(xr[i], sc1[c0 + i], bi1[c0 + i]), 0.f);
                ull hd = fdup(hs);
                const float* wr = &w2t[(64 + c0 + i) * 64];
#pragma unroll
                for (int k = 0; k < 16; k++) {
                    ulonglong2 wv = *(const ulonglong2*)&wr[k * 4];
                    fma2(acc2[2 * k],     wv.x, hd);
                    fma2(acc2[2 * k + 1], wv.y, hd);
                }
            }
        }
#pragma unroll
        for (int i = 0; i < 32; i++) {
            float2 f = u2f(acc2[i]);
            g_outpre[(size_t)(2 * i) * N_PIX + p]     = f.x;
            g_outpre[(size_t)(2 * i + 1) * N_PIX + p] = f.y;
        }
    }

    stats_block_reduce(acc2, ssum, ssq, g_sum2, g_sumsq2, tid, tid & 31, tid >> 5);
}

// ---------------- BN2 apply ----------------
__global__ void k_apply2(const float* __restrict__ g, const float* __restrict__ b,
                         float* __restrict__ out) {
    __shared__ float ssc, sbi;
    int c = blockIdx.y;
    if (threadIdx.x == 0) {
        float m = g_sum2[c] * (1.f / (float)N_PIX);
        float var = g_sumsq2[c] * (1.f / (float)N_PIX) - m * m;
        float sc = g[c] * rsqrtf(var + 1e-5f);
        ssc = sc;
        sbi = b[c] - m * sc;
    }
    __syncthreads();
    int p = blockIdx.x * 256 + threadIdx.x;
    if (p >= N_PIX) return;
    float v = g_outpre[(size_t)c * N_PIX + p] * ssc + sbi;
    out[(size_t)c * N_PIX + p] = v > 0.f ? v : 0.f;
}

// ---------------- launch ----------------
extern "C" void kernel_launch(void* const* d_in, const int* in_sizes, int n_in,
                              void* d_out, int out_size) {
    const float* x         = (const float*)d_in[0];
    const int*   prop      = (const int*)d_in[1];
    const int*   rand_inds = (const int*)d_in[2];
    const float* w_conv1   = (const float*)d_in[3];
    const float* bn1_g     = (const float*)d_in[4];
    const float* bn1_b     = (const float*)d_in[5];
    const float* wq        = (const float*)d_in[6];
    const float* wkv       = (const float*)d_in[7];
    const float* w_out     = (const float*)d_in[8];
    const float* b_out     = (const float*)d_in[9];
    const float* w_conv2   = (const float*)d_in[10];
    const float* bn2_g     = (const float*)d_in[11];
    const float* bn2_b     = (const float*)d_in[12];
    float* out = (float*)d_out;

    cudaFuncSetAttribute(k_attn, cudaFuncAttributeMaxDynamicSharedMemorySize, SM_ATT_BYTES);

    k_init<<<1, 256>>>();
    k_scanA<<<SCAN_B, 256>>>(prop);
    k_scanBC<<<SCAN_B, 256>>>(prop);
    dim3 gc1((N_PIX / 4 + 255) / 256, 8);
    k_conv1<<<gc1, 256>>>(x, w_conv1);
    k_attn<<<HEADS * CROP, ATT_THREADS, SM_ATT_BYTES>>>(wq, wkv, rand_inds, bn1_g, bn1_b);
    k_wout<<<(N_PIX + 255) / 256, 256>>>(w_out, b_out);
    k_conv2<<<(N_PIX + 255) / 256, 256>>>(w_conv2, bn1_g, bn1_b);
    dim3 g2((N_PIX + 255) / 256, E_CH);
    k_apply2<<<g2, 256>>>(bn2_g, bn2_b, out);
}

// round 15
// speedup vs baseline: 1.7288x; 1.1597x over previous
#include <cuda_runtime.h>
#include <math.h>

#define N_PIX    90000
#define HALF_PIX 45000
#define C_IN     256
#define E_CH     64
#define CROP     300
#define HEADS    2
#define DH       32

typedef unsigned long long ull;

__device__ __forceinline__ void fma2(ull& d, ull a, ull b) {
    asm("fma.rn.f32x2 %0, %1, %2, %0;" : "+l"(d) : "l"(a), "l"(b));
}
__device__ __forceinline__ ull add2(ull a, ull b) {
    ull r; asm("add.rn.f32x2 %0, %1, %2;" : "=l"(r) : "l"(a), "l"(b)); return r;
}
__device__ __forceinline__ ull mul2(ull a, ull b) {
    ull r; asm("mul.rn.f32x2 %0, %1, %2;" : "=l"(r) : "l"(a), "l"(b)); return r;
}
__device__ __forceinline__ ull fdup(float v) {
    ull r; asm("mov.b64 %0, {%1, %1};" : "=l"(r) : "f"(v)); return r;
}
__device__ __forceinline__ float2 u2f(ull v) {
    float2 f; asm("mov.b64 {%0, %1}, %2;" : "=f"(f.x), "=f"(f.y) : "l"(v)); return f;
}
__device__ __forceinline__ float hsum2(ull v) { float2 f = u2f(v); return f.x + f.y; }

// ---------------- scratch ----------------
__device__ float g_h[N_PIX * E_CH];        // [p][c] pre-BN1 (attn gather)
__device__ float g_h_cp[E_CH * N_PIX];     // [c][p] pre-BN1 (epilogue streaming)
__device__ float g_new[E_CH * N_PIX];      // [c][p] attention scatter target
__device__ float g_xa[E_CH * N_PIX];       // [d][p] relu(w_out . new + b)
__device__ float g_outpre[E_CH * N_PIX];   // [c][p] pre-BN2
__device__ int   g_obj[HALF_PIX];
__device__ int   g_bg[HALF_PIX];
__device__ int   g_blkcnt[360];
__device__ float g_sum1[E_CH], g_sumsq1[E_CH];
__device__ float g_sum2[E_CH], g_sumsq2[E_CH];

// ---------------- init ----------------
__global__ void k_init() {
    int t = threadIdx.x;
    if (t < 64) g_sum1[t] = 0.f;
    else if (t < 128) g_sumsq1[t - 64] = 0.f;
    else if (t < 192) g_sum2[t - 128] = 0.f;
    else if (t < 256) g_sumsq2[t - 192] = 0.f;
}

// ---------------- scanA ----------------
#define SCAN_B 352
__global__ void k_scanA(const int* __restrict__ prop) {
    int idx = blockIdx.x * 256 + threadIdx.x;
    int v = (idx < N_PIX) ? (prop[idx] != 0) : 0;
    unsigned m = __ballot_sync(0xffffffffu, v);
    __shared__ int wc[8];
    if ((threadIdx.x & 31) == 0) wc[threadIdx.x >> 5] = __popc(m);
    __syncthreads();
    if (threadIdx.x == 0) {
        int t = 0;
        for (int w = 0; w < 8; w++) t += wc[w];
        g_blkcnt[blockIdx.x] = t;
    }
}

// ---------------- scanBC ----------------
__global__ void k_scanBC(const int* __restrict__ prop) {
    int tid = threadIdx.x;
    int b = blockIdx.x;
    int acc = 0;
    for (int i = tid; i < b; i += 256) acc += g_blkcnt[i];
    __shared__ int red[256];
    red[tid] = acc;
    __syncthreads();
    for (int off = 128; off > 0; off >>= 1) {
        if (tid < off) red[tid] += red[tid + off];
        __syncthreads();
    }
    int blkobj = red[0];

    int idx = b * 256 + tid;
    int valid = idx < N_PIX;
    int v = valid ? (prop[idx] != 0) : 0;
    unsigned objm = __ballot_sync(0xffffffffu, v);
    unsigned valm = __ballot_sync(0xffffffffu, valid);
    int lane = tid & 31, w = tid >> 5;
    __shared__ int wobj[8], wval[8];
    if (lane == 0) { wobj[w] = __popc(objm); wval[w] = __popc(valm); }
    __syncthreads();
    int objbase = 0, valbase = 0;
    for (int i = 0; i < w; i++) { objbase += wobj[i]; valbase += wval[i]; }
    unsigned ltm = (1u << lane) - 1u;
    if (valid) {
        if (v) {
            g_obj[blkobj + objbase + __popc(objm & ltm)] = idx;
        } else {
            int bg_before_blk = b * 256 - blkobj;
            int intra = (valbase - objbase) + (__popc(valm & ltm) - __popc(objm & ltm));
            g_bg[bg_before_blk + intra] = idx;
        }
    }
}

// stats reduce for 8 channels (4 ull) at gsum[ebase..]
__device__ __forceinline__ void stats_block_reduce4(ull* s4, ull* q4, float* ssum, float* ssq,
                                                    float* gsum, float* gsq, int ebase,
                                                    int tid, int lane, int warp) {
#pragma unroll
    for (int k = 0; k < 4; k++) {
        ull s = s4[k];
        ull q = q4[k];
#pragma unroll
        for (int o = 16; o > 0; o >>= 1) {
            s = add2(s, __shfl_xor_sync(0xffffffffu, s, o));
            q = add2(q, __shfl_xor_sync(0xffffffffu, q, o));
        }
        if (lane == 0) {
            float2 sf = u2f(s), qf = u2f(q);
            ssum[warp * 8 + 2 * k]     = sf.x;
            ssum[warp * 8 + 2 * k + 1] = sf.y;
            ssq[warp * 8 + 2 * k]      = qf.x;
            ssq[warp * 8 + 2 * k + 1]  = qf.y;
        }
    }
    __syncthreads();
    if (tid < 8) {
        float t = 0.f;
#pragma unroll
        for (int w = 0; w < 8; w++) t += ssum[w * 8 + tid];
        atomicAdd(&gsum[ebase + tid], t);
    } else if (tid < 16) {
        int c = tid - 8;
        float t = 0.f;
#pragma unroll
        for (int w = 0; w < 8; w++) t += ssq[w * 8 + c];
        atomicAdd(&gsq[ebase + c], t);
    }
}

// stats reduce for 16 channels (8 ull) at gsum[ebase..]
__device__ __forceinline__ void stats_block_reduce8(ull* s8, ull* q8, float* ssum, float* ssq,
                                                    float* gsum, float* gsq, int ebase,
                                                    int tid, int lane, int warp) {
#pragma unroll
    for (int k = 0; k < 8; k++) {
        ull s = s8[k];
        ull q = q8[k];
#pragma unroll
        for (int o = 16; o > 0; o >>= 1) {
            s = add2(s, __shfl_xor_sync(0xffffffffu, s, o));
            q = add2(q, __shfl_xor_sync(0xffffffffu, q, o));
        }
        if (lane == 0) {
            float2 sf = u2f(s), qf = u2f(q);
            ssum[warp * 16 + 2 * k]     = sf.x;
            ssum[warp * 16 + 2 * k + 1] = sf.y;
            ssq[warp * 16 + 2 * k]      = qf.x;
            ssq[warp * 16 + 2 * k + 1]  = qf.y;
        }
    }
    __syncthreads();
    if (tid < 16) {
        float t = 0.f;
#pragma unroll
        for (int w = 0; w < 8; w++) t += ssum[w * 16 + tid];
        atomicAdd(&gsum[ebase + tid], t);
    } else if (tid < 32) {
        int c = tid - 16;
        float t = 0.f;
#pragma unroll
        for (int w = 0; w < 8; w++) t += ssq[w * 16 + c];
        atomicAdd(&gsq[ebase + c], t);
    }
}

// ---------------- conv1: 4 px/thread, 8 outputs/CTA (blockIdx.y of 8), 3 CTAs/SM ----------------
__global__ __launch_bounds__(256, 3) void k_conv1(const float* __restrict__ x,
                                                  const float* __restrict__ w) {
    __shared__ float ws[C_IN * 8];       // [c][e'] 8 KB
    __shared__ float ssum[64], ssq[64];
    int tid = threadIdx.x;
    int ebase = blockIdx.y * 8;
    for (int i = tid; i < C_IN * 8; i += 256) {
        int c = i >> 3, e = i & 7;
        ws[c * 8 + e] = w[(ebase + e) * C_IN + c];
    }
    __syncthreads();
    int p0 = (blockIdx.x * 256 + tid) * 4;
    bool valid = p0 < N_PIX;

    ull acc[4][4];
#pragma unroll
    for (int px = 0; px < 4; px++)
#pragma unroll
        for (int i = 0; i < 4; i++) acc[px][i] = 0ull;

    if (valid) {
        for (int c0 = 0; c0 < C_IN; c0 += 4) {
            float4 xr[4];
#pragma unroll
            for (int i = 0; i < 4; i++)
                xr[i] = __ldg((const float4*)&x[(size_t)(c0 + i) * N_PIX + p0]);
#pragma unroll
            for (int i = 0; i < 4; i++) {
                const ulonglong2* wr = (const ulonglong2*)&ws[(c0 + i) * 8];
                ulonglong2 w0 = wr[0], w1 = wr[1];
                float xs[4] = {xr[i].x, xr[i].y, xr[i].z, xr[i].w};
#pragma unroll
                for (int px = 0; px < 4; px++) {
                    ull xd = fdup(xs[px]);
                    fma2(acc[px][0], w0.x, xd);
                    fma2(acc[px][1], w0.y, xd);
                    fma2(acc[px][2], w1.x, xd);
                    fma2(acc[px][3], w1.y, xd);
                }
            }
        }
#pragma unroll
        for (int px = 0; px < 4; px++) {
            ull* op = (ull*)&g_h[(size_t)(p0 + px) * 64 + ebase];
#pragma unroll
            for (int i = 0; i < 4; i++) op[i] = acc[px][i];
        }
#pragma unroll
        for (int i = 0; i < 4; i++) {
            float2 f0 = u2f(acc[0][i]), f1 = u2f(acc[1][i]);
            float2 f2 = u2f(acc[2][i]), f3 = u2f(acc[3][i]);
            *(float4*)&g_h_cp[(size_t)(ebase + 2 * i) * N_PIX + p0] =
                make_float4(f0.x, f1.x, f2.x, f3.x);
            *(float4*)&g_h_cp[(size_t)(ebase + 2 * i + 1) * N_PIX + p0] =
                make_float4(f0.y, f1.y, f2.y, f3.y);
        }
    }

    ull s4[4], q4[4];
#pragma unroll
    for (int i = 0; i < 4; i++) {
        s4[i] = add2(add2(acc[0][i], acc[1][i]), add2(acc[2][i], acc[3][i]));
        q4[i] = add2(add2(mul2(acc[0][i], acc[0][i]), mul2(acc[1][i], acc[1][i])),
                     add2(mul2(acc[2][i], acc[2][i]), mul2(acc[3][i], acc[3][i])));
    }
    stats_block_reduce4(s4, q4, ssum, ssq, g_sum1, g_sumsq1, ebase, tid, tid & 31, tid >> 5);
}

// ---------------- attention: r8 configuration (4 rows/warp, 384 threads) ----------------
#define ATT_THREADS 384
#define ATT_WARPS 12
#define SM_ATT_FLOATS (64 + 64 + 1152 * 3 + 14400 + 9600 * 3 + 300)
#define SM_ATT_BYTES (SM_ATT_FLOATS * 4)

__global__ __launch_bounds__(ATT_THREADS, 1) void k_attn(const float* __restrict__ wq,
                                                         const float* __restrict__ wkv,
                                                         const int* __restrict__ rand_inds,
                                                         const float* __restrict__ bn1_g,
                                                         const float* __restrict__ bn1_b) {
    extern __shared__ float sm[];
    float* sc1    = sm;                    // 64
    float* bi1    = sm + 64;               // 64
    float* wq_t   = sm + 128;              // 32*36
    float* wk_t   = wq_t + 1152;
    float* wv_t   = wk_t + 1152;
    float* p_rows = wv_t + 1152;           // 14400 (seq alias)
    float* q_s    = p_rows + 14400;        // 9600
    float* k_s    = q_s + 9600;            // 9600
    float* v_t    = k_s + 9600;            // 9600 : [d][300]
    int*   pix_s  = (int*)(v_t + 9600);    // 300
    float* seq_s  = p_rows;

    int tid = threadIdx.x, warp = tid >> 5, lane = tid & 31;
    int b = blockIdx.x;
    int head = b / CROP;
    int iblk = b - head * CROP;
    int hoff = head * DH;

    if (tid < 64) {
        float m = g_sum1[tid] * (1.f / (float)N_PIX);
        float var = g_sumsq1[tid] * (1.f / (float)N_PIX) - m * m;
        float sc = bn1_g[tid] * rsqrtf(var + 1e-5f);
        sc1[tid] = sc;
        bi1[tid] = bn1_b[tid] - m * sc;
    }
    const int* src = (iblk < CROP / 2) ? g_obj : g_bg;
    const int* ri = rand_inds + (size_t)head * N_PIX + (size_t)iblk * CROP;
    for (int j = tid; j < CROP; j += ATT_THREADS) pix_s[j] = src[ri[j]];
    for (int i = tid; i < 1024; i += ATT_THREADS) {
        int e = i >> 5, d = i & 31;
        wq_t[d * 36 + e] = wq[i];
    }
    for (int i = tid; i < 2048; i += ATT_THREADS) {
        int e = i >> 6, c = i & 63;
        if (c < 32) wk_t[c * 36 + e] = wkv[i];
        else        wv_t[(c - 32) * 36 + e] = wkv[i];
    }
    __syncthreads();

    // gather + BN1 + relu, XOR-swizzled [j][32]
    for (int u = tid; u < CROP * 8; u += ATT_THREADS) {
        int j = u >> 3, seg = u & 7;
        int ch = hoff + seg * 4;
        float4 v = *(const float4*)&g_h[(size_t)pix_s[j] * 64 + ch];
        float4 s4 = *(const float4*)&sc1[ch];
        float4 b4 = *(const float4*)&bi1[ch];
        v.x = fmaxf(fmaf(v.x, s4.x, b4.x), 0.f);
        v.y = fmaxf(fmaf(v.y, s4.y, b4.y), 0.f);
        v.z = fmaxf(fmaf(v.z, s4.z, b4.z), 0.f);
        v.w = fmaxf(fmaf(v.w, s4.w, b4.w), 0.f);
        int pc = seg ^ (j & 7);
        *(float4*)&seq_s[j * 32 + pc * 4] = v;
    }
    __syncthreads();

    // QKV with register-resident weights (d = lane)
    {
        ull rq[16], rk[16], rv[16];
#pragma unroll
        for (int e2 = 0; e2 < 8; e2++) {
            ulonglong2 t;
            t = *(const ulonglong2*)&wq_t[lane * 36 + e2 * 4]; rq[2*e2] = t.x; rq[2*e2+1] = t.y;
            t = *(const ulonglong2*)&wk_t[lane * 36 + e2 * 4]; rk[2*e2] = t.x; rk[2*e2+1] = t.y;
            t = *(const ulonglong2*)&wv_t[lane * 36 + e2 * 4]; rv[2*e2] = t.x; rv[2*e2+1] = t.y;
        }
        for (int j = warp; j < CROP; j += ATT_WARPS) {
            int sw2 = (j & 7) << 2;
            ull aq = 0, ak = 0, av = 0;
#pragma unroll
            for (int e4 = 0; e4 < 8; e4++) {
                ulonglong2 sp = *(const ulonglong2*)&seq_s[j * 32 + ((e4 << 2) ^ sw2)];
                fma2(aq, sp.x, rq[2*e4]);
                fma2(ak, sp.x, rk[2*e4]);
                fma2(av, sp.x, rv[2*e4]);
                fma2(aq, sp.y, rq[2*e4+1]);
                fma2(ak, sp.y, rk[2*e4+1]);
                fma2(av, sp.y, rv[2*e4+1]);
            }
            int wi = j * 32 + (lane ^ sw2);
            q_s[wi] = hsum2(aq);
            k_s[wi] = hsum2(ak);
            v_t[lane * 300 + j] = hsum2(av);
        }
    }
    __syncthreads();

    const float scale = 0.17677669529663687f; // 1/sqrt(32)
    float* pw = &p_rows[warp * 4 * 300];
    for (int rp = warp; rp < 75; rp += ATT_WARPS) {
        int r0 = rp * 4;
        ull a[4][10];
#pragma unroll
        for (int r = 0; r < 4; r++)
#pragma unroll
            for (int jj = 0; jj < 10; jj++) a[r][jj] = 0ull;

#pragma unroll
        for (int c = 0; c < 8; c++) {
            ull qx[4], qy[4];
#pragma unroll
            for (int r = 0; r < 4; r++) {
                int row = r0 + r;
                ulonglong2 t = *(const ulonglong2*)&q_s[row * 32 + ((c << 2) ^ ((row & 7) << 2))];
                qx[r] = t.x; qy[r] = t.y;
            }
#pragma unroll
            for (int jj = 0; jj < 10; jj++) {
                int j = lane + (jj << 5);
                int jc = (j < CROP) ? j : 0;
                ulonglong2 kv = *(const ulonglong2*)&k_s[jc * 32 + ((c << 2) ^ ((jc & 7) << 2))];
                fma2(a[0][jj], qx[0], kv.x);
                fma2(a[1][jj], qx[1], kv.x);
                fma2(a[2][jj], qx[2], kv.x);
                fma2(a[3][jj], qx[3], kv.x);
                fma2(a[0][jj], qy[0], kv.y);
                fma2(a[1][jj], qy[1], kv.y);
                fma2(a[2][jj], qy[2], kv.y);
                fma2(a[3][jj], qy[3], kv.y);
            }
        }
#pragma unroll
        for (int r = 0; r < 4; r++) {
            float sv[10];
            float mx = -1e30f;
#pragma unroll
            for (int jj = 0; jj < 10; jj++) {
                float s = hsum2(a[r][jj]) * scale;
                sv[jj] = s;
                if (lane + (jj << 5) < CROP) mx = fmaxf(mx, s);
            }
#pragma unroll
            for (int o = 16; o > 0; o >>= 1)
                mx = fmaxf(mx, __shfl_xor_sync(0xffffffffu, mx, o));
            float sum = 0.f;
#pragma unroll
            for (int jj = 0; jj < 10; jj++) {
                int j = lane + (jj << 5);
                float e = (j < CROP) ? __expf(sv[jj] - mx) : 0.f;
                sv[jj] = e;
                sum += e;
            }
#pragma unroll
            for (int o = 16; o > 0; o >>= 1)
                sum += __shfl_xor_sync(0xffffffffu, sum, o);
            float inv = 1.f / sum;
#pragma unroll
            for (int jj = 0; jj < 10; jj++) {
                int j = lane + (jj << 5);
                if (j < CROP) pw[r * 300 + j] = sv[jj] * inv;
            }
        }
        __syncwarp();
        ull oa[4] = {0, 0, 0, 0}, ob[4] = {0, 0, 0, 0};
        const float* vrow = &v_t[lane * 300];
#pragma unroll 5
        for (int j4 = 0; j4 < 75; j4++) {
            ulonglong2 vv = *(const ulonglong2*)&vrow[j4 * 4];
#pragma unroll
            for (int r = 0; r < 4; r++) {
                ulonglong2 pv = *(const ulonglong2*)&pw[r * 300 + j4 * 4];
                fma2(oa[r], pv.x, vv.x);
                fma2(ob[r], pv.y, vv.y);
            }
        }
#pragma unroll
        for (int r = 0; r < 4; r++) {
            float ov = hsum2(add2(oa[r], ob[r]));
            int t = (r0 + r) * 32 + lane;
            int d = t / 300, mm = t - d * 300;
            g_new[(size_t)(hoff + d) * N_PIX + pix_s[mm]] = ov;
        }
        __syncwarp();
    }
}

// ---------------- w_out: 4 px/thread, 8 outputs/CTA ----------------
__global__ __launch_bounds__(256, 3) void k_wout(const float* __restrict__ w_out,
                                                 const float* __restrict__ b_out) {
    __shared__ float ws[64 * 8];   // [c][d']
    __shared__ float bs[8];
    int tid = threadIdx.x;
    int dbase = blockIdx.y * 8;
    for (int i = tid; i < 64 * 8; i += 256) {
        int c = i >> 3, d = i & 7;
        ws[c * 8 + d] = w_out[c * 64 + dbase + d];
    }
    if (tid < 8) bs[tid] = b_out[dbase + tid];
    __syncthreads();
    int p0 = (blockIdx.x * 256 + tid) * 4;
    if (p0 >= N_PIX) return;

    ull acc[4][4];
#pragma unroll
    for (int px = 0; px < 4; px++)
#pragma unroll
        for (int i = 0; i < 4; i++) acc[px][i] = 0ull;

    for (int c0 = 0; c0 < 64; c0 += 4) {
        float4 xr[4];
#pragma unroll
        for (int i = 0; i < 4; i++)
            xr[i] = __ldg((const float4*)&g_new[(size_t)(c0 + i) * N_PIX + p0]);
#pragma unroll
        for (int i = 0; i < 4; i++) {
            const ulonglong2* wr = (const ulonglong2*)&ws[(c0 + i) * 8];
            ulonglong2 w0 = wr[0], w1 = wr[1];
            float xs[4] = {xr[i].x, xr[i].y, xr[i].z, xr[i].w};
#pragma unroll
            for (int px = 0; px < 4; px++) {
                ull xd = fdup(xs[px]);
                fma2(acc[px][0], w0.x, xd);
                fma2(acc[px][1], w0.y, xd);
                fma2(acc[px][2], w1.x, xd);
                fma2(acc[px][3], w1.y, xd);
            }
        }
    }
#pragma unroll
    for (int i = 0; i < 4; i++) {
        float2 f0 = u2f(acc[0][i]), f1 = u2f(acc[1][i]);
        float2 f2 = u2f(acc[2][i]), f3 = u2f(acc[3][i]);
        float ba = bs[2 * i], bb = bs[2 * i + 1];
        *(float4*)&g_xa[(size_t)(dbase + 2 * i) * N_PIX + p0] =
            make_float4(fmaxf(f0.x + ba, 0.f), fmaxf(f1.x + ba, 0.f),
                        fmaxf(f2.x + ba, 0.f), fmaxf(f3.x + ba, 0.f));
        *(float4*)&g_xa[(size_t)(dbase + 2 * i + 1) * N_PIX + p0] =
            make_float4(fmaxf(f0.y + bb, 0.f), fmaxf(f1.y + bb, 0.f),
                        fmaxf(f2.y + bb, 0.f), fmaxf(f3.y + bb, 0.f));
    }
}

// ---------------- conv2: 4 px/thread, 16 outputs/CTA + fused BN2 stats ----------------
__global__ __launch_bounds__(256, 2) void k_conv2(const float* __restrict__ w2,
                                                  const float* __restrict__ bn1_g,
                                                  const float* __restrict__ bn1_b) {
    __shared__ float w2t[128 * 16]; // [c][o'] 8 KB
    __shared__ float sc1[64], bi1[64];
    __shared__ float ssum[128], ssq[128];
    int tid = threadIdx.x;
    int obase = blockIdx.y * 16;
    for (int i = tid; i < 128 * 16; i += 256) {
        int c = i >> 4, o = i & 15;
        w2t[c * 16 + o] = w2[(obase + o) * 128 + c];
    }
    if (tid < 64) {
        float m = g_sum1[tid] * (1.f / (float)N_PIX);
        float var = g_sumsq1[tid] * (1.f / (float)N_PIX) - m * m;
        float sc = bn1_g[tid] * rsqrtf(var + 1e-5f);
        sc1[tid] = sc;
        bi1[tid] = bn1_b[tid] - m * sc;
    }
    __syncthreads();
    int p0 = (blockIdx.x * 256 + tid) * 4;
    bool valid = p0 < N_PIX;

    ull acc[4][8];
#pragma unroll
    for (int px = 0; px < 4; px++)
#pragma unroll
        for (int i = 0; i < 8; i++) acc[px][i] = 0ull;

    if (valid) {
        // xa half (channels 0..63)
        for (int c0 = 0; c0 < 64; c0 += 4) {
            float4 xr[4];
#pragma unroll
            for (int i = 0; i < 4; i++)
                xr[i] = __ldg((const float4*)&g_xa[(size_t)(c0 + i) * N_PIX + p0]);
#pragma unroll
            for (int i = 0; i < 4; i++) {
                const ulonglong2* wr = (const ulonglong2*)&w2t[(c0 + i) * 16];
                ulonglong2 w0 = wr[0], w1 = wr[1], w2v = wr[2], w3 = wr[3];
                float xs[4] = {xr[i].x, xr[i].y, xr[i].z, xr[i].w};
#pragma unroll
                for (int px = 0; px < 4; px++) {
                    ull xd = fdup(xs[px]);
                    fma2(acc[px][0], w0.x, xd);
                    fma2(acc[px][1], w0.y, xd);
                    fma2(acc[px][2], w1.x, xd);
                    fma2(acc[px][3], w1.y, xd);
                    fma2(acc[px][4], w2v.x, xd);
                    fma2(acc[px][5], w2v.y, xd);
                    fma2(acc[px][6], w3.x, xd);
                    fma2(acc[px][7], w3.y, xd);
                }
            }
        }
        // h half (channels 64..127), BN1+relu inline
        for (int c0 = 0; c0 < 64; c0 += 4) {
            float4 xr[4];
#pragma unroll
            for (int i = 0; i < 4; i++)
                xr[i] = __ldg((const float4*)&g_h_cp[(size_t)(c0 + i) * N_PIX + p0]);
#pragma unroll
            for (int i = 0; i < 4; i++) {
                const ulonglong2* wr = (const ulonglong2*)&w2t[(64 + c0 + i) * 16];
                ulonglong2 w0 = wr[0], w1 = wr[1], w2v = wr[2], w3 = wr[3];
                float scv = sc1[c0 + i], biv = bi1[c0 + i];
                float xs[4];
                xs[0] = fmaxf(fmaf(xr[i].x, scv, biv), 0.f);
                xs[1] = fmaxf(fmaf(xr[i].y, scv, biv), 0.f);
                xs[2] = fmaxf(fmaf(xr[i].z, scv, biv), 0.f);
                xs[3] = fmaxf(fmaf(xr[i].w, scv, biv), 0.f);
#pragma unroll
                for (int px = 0; px < 4; px++) {
                    ull xd = fdup(xs[px]);
                    fma2(acc[px][0], w0.x, xd);
                    fma2(acc[px][1], w0.y, xd);
                    fma2(acc[px][2], w1.x, xd);
                    fma2(acc[px][3], w1.y, xd);
                    fma2(acc[px][4], w2v.x, xd);
                    fma2(acc[px][5], w2v.y, xd);
                    fma2(acc[px][6], w3.x, xd);
                    fma2(acc[px][7], w3.y, xd);
                }
            }
        }
        // stores: float4 per channel
#pragma unroll
        for (int i = 0; i < 8; i++) {
            float2 f0 = u2f(acc[0][i]), f1 = u2f(acc[1][i]);
            float2 f2 = u2f(acc[2][i]), f3 = u2f(acc[3][i]);
            *(float4*)&g_outpre[(size_t)(obase + 2 * i) * N_PIX + p0] =
                make_float4(f0.x, f1.x, f2.x, f3.x);
            *(float4*)&g_outpre[(size_t)(obase + 2 * i + 1) * N_PIX + p0] =
                make_float4(f0.y, f1.y, f2.y, f3.y);
        }
    }

    // BN2 stats: combine px then block-reduce (16 channels)
    ull s8[8], q8[8];
#pragma unroll
    for (int i = 0; i < 8; i++) {
        s8[i] = add2(add2(acc[0][i], acc[1][i]), add2(acc[2][i], acc[3][i]));
        q8[i] = add2(add2(mul2(acc[0][i], acc[0][i]), mul2(acc[1][i], acc[1][i])),
                     add2(mul2(acc[2][i], acc[2][i]), mul2(acc[3][i], acc[3][i])));
    }
    stats_block_reduce8(s8, q8, ssum, ssq, g_sum2, g_sumsq2, obase, tid, tid & 31, tid >> 5);
}

// ---------------- BN2 apply ----------------
__global__ void k_apply2(const float* __restrict__ g, const float* __restrict__ b,
                         float* __restrict__ out) {
    __shared__ float ssc, sbi;
    int c = blockIdx.y;
    if (threadIdx.x == 0) {
        float m = g_sum2[c] * (1.f / (float)N_PIX);
        float var = g_sumsq2[c] * (1.f / (float)N_PIX) - m * m;
        float sc = g[c] * rsqrtf(var + 1e-5f);
        ssc = sc;
        sbi = b[c] - m * sc;
    }
    __syncthreads();
    int p = blockIdx.x * 256 + threadIdx.x;
    if (p >= N_PIX) return;
    float v = g_outpre[(size_t)c * N_PIX + p] * ssc + sbi;
    out[(size_t)c * N_PIX + p] = v > 0.f ? v : 0.f;
}

// ---------------- launch ----------------
extern "C" void kernel_launch(void* const* d_in, const int* in_sizes, int n_in,
                              void* d_out, int out_size) {
    const float* x         = (const float*)d_in[0];
    const int*   prop      = (const int*)d_in[1];
    const int*   rand_inds = (const int*)d_in[2];
    const float* w_conv1   = (const float*)d_in[3];
    const float* bn1_g     = (const float*)d_in[4];
    const float* bn1_b     = (const float*)d_in[5];
    const float* wq        = (const float*)d_in[6];
    const float* wkv       = (const float*)d_in[7];
    const float* w_out     = (const float*)d_in[8];
    const float* b_out     = (const float*)d_in[9];
    const float* w_conv2   = (const float*)d_in[10];
    const float* bn2_g     = (const float*)d_in[11];
    const float* bn2_b     = (const float*)d_in[12];
    float* out = (float*)d_out;

    cudaFuncSetAttribute(k_attn, cudaFuncAttributeMaxDynamicSharedMemorySize, SM_ATT_BYTES);

    k_init<<<1, 256>>>();
    k_scanA<<<SCAN_B, 256>>>(prop);
    k_scanBC<<<SCAN_B, 256>>>(prop);
    dim3 gc1((N_PIX / 4 + 255) / 256, 8);
    k_conv1<<<gc1, 256>>>(x, w_conv1);
    k_attn<<<HEADS * CROP, ATT_THREADS, SM_ATT_BYTES>>>(wq, wkv, rand_inds, bn1_g, bn1_b);
    dim3 gwo((N_PIX / 4 + 255) / 256, 8);
    k_wout<<<gwo, 256>>>(w_out, b_out);
    dim3 gc2((N_PIX / 4 + 255) / 256, 4);
    k_conv2<<<gc2, 256>>>(w_conv2, bn1_g, bn1_b);
    dim3 g2((N_PIX + 255) / 256, E_CH);
    k_apply2<<<g2, 256>>>(bn2_g, bn2_b, out);
}

// round 16
// speedup vs baseline: 1.7309x; 1.0012x over previous
#include <cuda_runtime.h>
#include <math.h>

#define N_PIX    90000
#define HALF_PIX 45000
#define C_IN     256
#define E_CH     64
#define CROP     300
#define HEADS    2
#define DH       32

typedef unsigned long long ull;

__device__ __forceinline__ void fma2(ull& d, ull a, ull b) {
    asm("fma.rn.f32x2 %0, %1, %2, %0;" : "+l"(d) : "l"(a), "l"(b));
}
__device__ __forceinline__ ull add2(ull a, ull b) {
    ull r; asm("add.rn.f32x2 %0, %1, %2;" : "=l"(r) : "l"(a), "l"(b)); return r;
}
__device__ __forceinline__ ull mul2(ull a, ull b) {
    ull r; asm("mul.rn.f32x2 %0, %1, %2;" : "=l"(r) : "l"(a), "l"(b)); return r;
}
__device__ __forceinline__ ull fdup(float v) {
    ull r; asm("mov.b64 %0, {%1, %1};" : "=l"(r) : "f"(v)); return r;
}
__device__ __forceinline__ float2 u2f(ull v) {
    float2 f; asm("mov.b64 {%0, %1}, %2;" : "=f"(f.x), "=f"(f.y) : "l"(v)); return f;
}
__device__ __forceinline__ float hsum2(ull v) { float2 f = u2f(v); return f.x + f.y; }

// ---------------- scratch ----------------
__device__ float g_h[N_PIX * E_CH];        // [p][c] pre-BN1 (attn gather)
__device__ float g_h_cp[E_CH * N_PIX];     // [c][p] pre-BN1 (epilogue streaming)
__device__ float g_new[E_CH * N_PIX];      // [c][p] attention scatter target
__device__ float g_xa[E_CH * N_PIX];       // [d][p] relu(w_out . new + b)
__device__ float g_outpre[E_CH * N_PIX];   // [c][p] pre-BN2
__device__ int   g_obj[HALF_PIX];
__device__ int   g_bg[HALF_PIX];
__device__ int   g_blkcnt[360];
__device__ float g_sum1[E_CH], g_sumsq1[E_CH];
__device__ float g_sum2[E_CH], g_sumsq2[E_CH];

// ---------------- init ----------------
__global__ void k_init() {
    int t = threadIdx.x;
    if (t < 64) g_sum1[t] = 0.f;
    else if (t < 128) g_sumsq1[t - 64] = 0.f;
    else if (t < 192) g_sum2[t - 128] = 0.f;
    else if (t < 256) g_sumsq2[t - 192] = 0.f;
}

// ---------------- scanA ----------------
#define SCAN_B 352
__global__ void k_scanA(const int* __restrict__ prop) {
    int idx = blockIdx.x * 256 + threadIdx.x;
    int v = (idx < N_PIX) ? (prop[idx] != 0) : 0;
    unsigned m = __ballot_sync(0xffffffffu, v);
    __shared__ int wc[8];
    if ((threadIdx.x & 31) == 0) wc[threadIdx.x >> 5] = __popc(m);
    __syncthreads();
    if (threadIdx.x == 0) {
        int t = 0;
        for (int w = 0; w < 8; w++) t += wc[w];
        g_blkcnt[blockIdx.x] = t;
    }
}

// ---------------- scanBC ----------------
__global__ void k_scanBC(const int* __restrict__ prop) {
    int tid = threadIdx.x;
    int b = blockIdx.x;
    int acc = 0;
    for (int i = tid; i < b; i += 256) acc += g_blkcnt[i];
    __shared__ int red[256];
    red[tid] = acc;
    __syncthreads();
    for (int off = 128; off > 0; off >>= 1) {
        if (tid < off) red[tid] += red[tid + off];
        __syncthreads();
    }
    int blkobj = red[0];

    int idx = b * 256 + tid;
    int valid = idx < N_PIX;
    int v = valid ? (prop[idx] != 0) : 0;
    unsigned objm = __ballot_sync(0xffffffffu, v);
    unsigned valm = __ballot_sync(0xffffffffu, valid);
    int lane = tid & 31, w = tid >> 5;
    __shared__ int wobj[8], wval[8];
    if (lane == 0) { wobj[w] = __popc(objm); wval[w] = __popc(valm); }
    __syncthreads();
    int objbase = 0, valbase = 0;
    for (int i = 0; i < w; i++) { objbase += wobj[i]; valbase += wval[i]; }
    unsigned ltm = (1u << lane) - 1u;
    if (valid) {
        if (v) {
            g_obj[blkobj + objbase + __popc(objm & ltm)] = idx;
        } else {
            int bg_before_blk = b * 256 - blkobj;
            int intra = (valbase - objbase) + (__popc(valm & ltm) - __popc(objm & ltm));
            g_bg[bg_before_blk + intra] = idx;
        }
    }
}

// stats reduce for 8 channels (4 ull) at gsum[ebase..]
__device__ __forceinline__ void stats_block_reduce4(ull* s4, ull* q4, float* ssum, float* ssq,
                                                    float* gsum, float* gsq, int ebase,
                                                    int tid, int lane, int warp) {
#pragma unroll
    for (int k = 0; k < 4; k++) {
        ull s = s4[k];
        ull q = q4[k];
#pragma unroll
        for (int o = 16; o > 0; o >>= 1) {
            s = add2(s, __shfl_xor_sync(0xffffffffu, s, o));
            q = add2(q, __shfl_xor_sync(0xffffffffu, q, o));
        }
        if (lane == 0) {
            float2 sf = u2f(s), qf = u2f(q);
            ssum[warp * 8 + 2 * k]     = sf.x;
            ssum[warp * 8 + 2 * k + 1] = sf.y;
            ssq[warp * 8 + 2 * k]      = qf.x;
            ssq[warp * 8 + 2 * k + 1]  = qf.y;
        }
    }
    __syncthreads();
    if (tid < 8) {
        float t = 0.f;
#pragma unroll
        for (int w = 0; w < 8; w++) t += ssum[w * 8 + tid];
        atomicAdd(&gsum[ebase + tid], t);
    } else if (tid < 16) {
        int c = tid - 8;
        float t = 0.f;
#pragma unroll
        for (int w = 0; w < 8; w++) t += ssq[w * 8 + c];
        atomicAdd(&gsq[ebase + c], t);
    }
}

// stats reduce for 16 channels (8 ull) at gsum[ebase..]
__device__ __forceinline__ void stats_block_reduce8(ull* s8, ull* q8, float* ssum, float* ssq,
                                                    float* gsum, float* gsq, int ebase,
                                                    int tid, int lane, int warp) {
#pragma unroll
    for (int k = 0; k < 8; k++) {
        ull s = s8[k];
        ull q = q8[k];
#pragma unroll
        for (int o = 16; o > 0; o >>= 1) {
            s = add2(s, __shfl_xor_sync(0xffffffffu, s, o));
            q = add2(q, __shfl_xor_sync(0xffffffffu, q, o));
        }
        if (lane == 0) {
            float2 sf = u2f(s), qf = u2f(q);
            ssum[warp * 16 + 2 * k]     = sf.x;
            ssum[warp * 16 + 2 * k + 1] = sf.y;
            ssq[warp * 16 + 2 * k]      = qf.x;
            ssq[warp * 16 + 2 * k + 1]  = qf.y;
        }
    }
    __syncthreads();
    if (tid < 16) {
        float t = 0.f;
#pragma unroll
        for (int w = 0; w < 8; w++) t += ssum[w * 16 + tid];
        atomicAdd(&gsum[ebase + tid], t);
    } else if (tid < 32) {
        int c = tid - 16;
        float t = 0.f;
#pragma unroll
        for (int w = 0; w < 8; w++) t += ssq[w * 16 + c];
        atomicAdd(&gsq[ebase + c], t);
    }
}

// ---------------- conv1: 4 px/thread, 8 outputs/CTA (blockIdx.y of 8), 3 CTAs/SM ----------------
__global__ __launch_bounds__(256, 3) void k_conv1(const float* __restrict__ x,
                                                  const float* __restrict__ w) {
    __shared__ float ws[C_IN * 8];       // [c][e'] 8 KB
    __shared__ float ssum[64], ssq[64];
    int tid = threadIdx.x;
    int ebase = blockIdx.y * 8;
    for (int i = tid; i < C_IN * 8; i += 256) {
        int c = i >> 3, e = i & 7;
        ws[c * 8 + e] = w[(ebase + e) * C_IN + c];
    }
    __syncthreads();
    int p0 = (blockIdx.x * 256 + tid) * 4;
    bool valid = p0 < N_PIX;

    ull acc[4][4];
#pragma unroll
    for (int px = 0; px < 4; px++)
#pragma unroll
        for (int i = 0; i < 4; i++) acc[px][i] = 0ull;

    if (valid) {
        for (int c0 = 0; c0 < C_IN; c0 += 4) {
            float4 xr[4];
#pragma unroll
            for (int i = 0; i < 4; i++)
                xr[i] = __ldg((const float4*)&x[(size_t)(c0 + i) * N_PIX + p0]);
#pragma unroll
            for (int i = 0; i < 4; i++) {
                const ulonglong2* wr = (const ulonglong2*)&ws[(c0 + i) * 8];
                ulonglong2 w0 = wr[0], w1 = wr[1];
                float xs[4] = {xr[i].x, xr[i].y, xr[i].z, xr[i].w};
#pragma unroll
                for (int px = 0; px < 4; px++) {
                    ull xd = fdup(xs[px]);
                    fma2(acc[px][0], w0.x, xd);
                    fma2(acc[px][1], w0.y, xd);
                    fma2(acc[px][2], w1.x, xd);
                    fma2(acc[px][3], w1.y, xd);
                }
            }
        }
#pragma unroll
        for (int px = 0; px < 4; px++) {
            ull* op = (ull*)&g_h[(size_t)(p0 + px) * 64 + ebase];
#pragma unroll
            for (int i = 0; i < 4; i++) op[i] = acc[px][i];
        }
#pragma unroll
        for (int i = 0; i < 4; i++) {
            float2 f0 = u2f(acc[0][i]), f1 = u2f(acc[1][i]);
            float2 f2 = u2f(acc[2][i]), f3 = u2f(acc[3][i]);
            *(float4*)&g_h_cp[(size_t)(ebase + 2 * i) * N_PIX + p0] =
                make_float4(f0.x, f1.x, f2.x, f3.x);
            *(float4*)&g_h_cp[(size_t)(ebase + 2 * i + 1) * N_PIX + p0] =
                make_float4(f0.y, f1.y, f2.y, f3.y);
        }
    }

    ull s4[4], q4[4];
#pragma unroll
    for (int i = 0; i < 4; i++) {
        s4[i] = add2(add2(acc[0][i], acc[1][i]), add2(acc[2][i], acc[3][i]));
        q4[i] = add2(add2(mul2(acc[0][i], acc[0][i]), mul2(acc[1][i], acc[1][i])),
                     add2(mul2(acc[2][i], acc[2][i]), mul2(acc[3][i], acc[3][i])));
    }
    stats_block_reduce4(s4, q4, ssum, ssq, g_sum1, g_sumsq1, ebase, tid, tid & 31, tid >> 5);
}

// ---------------- attention: r8 configuration (4 rows/warp, 384 threads) ----------------
#define ATT_THREADS 384
#define ATT_WARPS 12
#define SM_ATT_FLOATS (64 + 64 + 1152 * 3 + 14400 + 9600 * 3 + 300)
#define SM_ATT_BYTES (SM_ATT_FLOATS * 4)

__global__ __launch_bounds__(ATT_THREADS, 1) void k_attn(const float* __restrict__ wq,
                                                         const float* __restrict__ wkv,
                                                         const int* __restrict__ rand_inds,
                                                         const float* __restrict__ bn1_g,
                                                         const float* __restrict__ bn1_b) {
    extern __shared__ float sm[];
    float* sc1    = sm;                    // 64
    float* bi1    = sm + 64;               // 64
    float* wq_t   = sm + 128;              // 32*36
    float* wk_t   = wq_t + 1152;
    float* wv_t   = wk_t + 1152;
    float* p_rows = wv_t + 1152;           // 14400 (seq alias)
    float* q_s    = p_rows + 14400;        // 9600
    float* k_s    = q_s + 9600;            // 9600
    float* v_t    = k_s + 9600;            // 9600 : [d][300]
    int*   pix_s  = (int*)(v_t + 9600);    // 300
    float* seq_s  = p_rows;

    int tid = threadIdx.x, warp = tid >> 5, lane = tid & 31;
    int b = blockIdx.x;
    int head = b / CROP;
    int iblk = b - head * CROP;
    int hoff = head * DH;

    if (tid < 64) {
        float m = g_sum1[tid] * (1.f / (float)N_PIX);
        float var = g_sumsq1[tid] * (1.f / (float)N_PIX) - m * m;
        float sc = bn1_g[tid] * rsqrtf(var + 1e-5f);
        sc1[tid] = sc;
        bi1[tid] = bn1_b[tid] - m * sc;
    }
    const int* src = (iblk < CROP / 2) ? g_obj : g_bg;
    const int* ri = rand_inds + (size_t)head * N_PIX + (size_t)iblk * CROP;
    for (int j = tid; j < CROP; j += ATT_THREADS) pix_s[j] = src[ri[j]];
    for (int i = tid; i < 1024; i += ATT_THREADS) {
        int e = i >> 5, d = i & 31;
        wq_t[d * 36 + e] = wq[i];
    }
    for (int i = tid; i < 2048; i += ATT_THREADS) {
        int e = i >> 6, c = i & 63;
        if (c < 32) wk_t[c * 36 + e] = wkv[i];
        else        wv_t[(c - 32) * 36 + e] = wkv[i];
    }
    __syncthreads();

    // gather + BN1 + relu, XOR-swizzled [j][32]
    for (int u = tid; u < CROP * 8; u += ATT_THREADS) {
        int j = u >> 3, seg = u & 7;
        int ch = hoff + seg * 4;
        float4 v = *(const float4*)&g_h[(size_t)pix_s[j] * 64 + ch];
        float4 s4 = *(const float4*)&sc1[ch];
        float4 b4 = *(const float4*)&bi1[ch];
        v.x = fmaxf(fmaf(v.x, s4.x, b4.x), 0.f);
        v.y = fmaxf(fmaf(v.y, s4.y, b4.y), 0.f);
        v.z = fmaxf(fmaf(v.z, s4.z, b4.z), 0.f);
        v.w = fmaxf(fmaf(v.w, s4.w, b4.w), 0.f);
        int pc = seg ^ (j & 7);
        *(float4*)&seq_s[j * 32 + pc * 4] = v;
    }
    __syncthreads();

    // QKV with register-resident weights (d = lane)
    {
        ull rq[16], rk[16], rv[16];
#pragma unroll
        for (int e2 = 0; e2 < 8; e2++) {
            ulonglong2 t;
            t = *(const ulonglong2*)&wq_t[lane * 36 + e2 * 4]; rq[2*e2] = t.x; rq[2*e2+1] = t.y;
            t = *(const ulonglong2*)&wk_t[lane * 36 + e2 * 4]; rk[2*e2] = t.x; rk[2*e2+1] = t.y;
            t = *(const ulonglong2*)&wv_t[lane * 36 + e2 * 4]; rv[2*e2] = t.x; rv[2*e2+1] = t.y;
        }
        for (int j = warp; j < CROP; j += ATT_WARPS) {
            int sw2 = (j & 7) << 2;
            ull aq = 0, ak = 0, av = 0;
#pragma unroll
            for (int e4 = 0; e4 < 8; e4++) {
                ulonglong2 sp = *(const ulonglong2*)&seq_s[j * 32 + ((e4 << 2) ^ sw2)];
                fma2(aq, sp.x, rq[2*e4]);
                fma2(ak, sp.x, rk[2*e4]);
                fma2(av, sp.x, rv[2*e4]);
                fma2(aq, sp.y, rq[2*e4+1]);
                fma2(ak, sp.y, rk[2*e4+1]);
                fma2(av, sp.y, rv[2*e4+1]);
            }
            int wi = j * 32 + (lane ^ sw2);
            q_s[wi] = hsum2(aq);
            k_s[wi] = hsum2(ak);
            v_t[lane * 300 + j] = hsum2(av);
        }
    }
    __syncthreads();

    const float scale = 0.17677669529663687f; // 1/sqrt(32)
    float* pw = &p_rows[warp * 4 * 300];
    for (int rp = warp; rp < 75; rp += ATT_WARPS) {
        int r0 = rp * 4;
        ull a[4][10];
#pragma unroll
        for (int r = 0; r < 4; r++)
#pragma unroll
            for (int jj = 0; jj < 10; jj++) a[r][jj] = 0ull;

#pragma unroll
        for (int c = 0; c < 8; c++) {
            ull qx[4], qy[4];
#pragma unroll
            for (int r = 0; r < 4; r++) {
                int row = r0 + r;
                ulonglong2 t = *(const ulonglong2*)&q_s[row * 32 + ((c << 2) ^ ((row & 7) << 2))];
                qx[r] = t.x; qy[r] = t.y;
            }
#pragma unroll
            for (int jj = 0; jj < 10; jj++) {
                int j = lane + (jj << 5);
                int jc = (j < CROP) ? j : 0;
                ulonglong2 kv = *(const ulonglong2*)&k_s[jc * 32 + ((c << 2) ^ ((jc & 7) << 2))];
                fma2(a[0][jj], qx[0], kv.x);
                fma2(a[1][jj], qx[1], kv.x);
                fma2(a[2][jj], qx[2], kv.x);
                fma2(a[3][jj], qx[3], kv.x);
                fma2(a[0][jj], qy[0], kv.y);
                fma2(a[1][jj], qy[1], kv.y);
                fma2(a[2][jj], qy[2], kv.y);
                fma2(a[3][jj], qy[3], kv.y);
            }
        }
#pragma unroll
        for (int r = 0; r < 4; r++) {
            float sv[10];
            float mx = -1e30f;
#pragma unroll
            for (int jj = 0; jj < 10; jj++) {
                float s = hsum2(a[r][jj]) * scale;
                sv[jj] = s;
                if (lane + (jj << 5) < CROP) mx = fmaxf(mx, s);
            }
#pragma unroll
            for (int o = 16; o > 0; o >>= 1)
                mx = fmaxf(mx, __shfl_xor_sync(0xffffffffu, mx, o));
            float sum = 0.f;
#pragma unroll
            for (int jj = 0; jj < 10; jj++) {
                int j = lane + (jj << 5);
                float e = (j < CROP) ? __expf(sv[jj] - mx) : 0.f;
                sv[jj] = e;
                sum += e;
            }
#pragma unroll
            for (int o = 16; o > 0; o >>= 1)
                sum += __shfl_xor_sync(0xffffffffu, sum, o);
            float inv = 1.f / sum;
#pragma unroll
            for (int jj = 0; jj < 10; jj++) {
                int j = lane + (jj << 5);
                if (j < CROP) pw[r * 300 + j] = sv[jj] * inv;
            }
        }
        __syncwarp();
        ull oa[4] = {0, 0, 0, 0}, ob[4] = {0, 0, 0, 0};
        const float* vrow = &v_t[lane * 300];
#pragma unroll 5
        for (int j4 = 0; j4 < 75; j4++) {
            ulonglong2 vv = *(const ulonglong2*)&vrow[j4 * 4];
#pragma unroll
            for (int r = 0; r < 4; r++) {
                ulonglong2 pv = *(const ulonglong2*)&pw[r * 300 + j4 * 4];
                fma2(oa[r], pv.x, vv.x);
                fma2(ob[r], pv.y, vv.y);
            }
        }
#pragma unroll
        for (int r = 0; r < 4; r++) {
            float ov = hsum2(add2(oa[r], ob[r]));
            int t = (r0 + r) * 32 + lane;
            int d = t / 300, mm = t - d * 300;
            g_new[(size_t)(hoff + d) * N_PIX + pix_s[mm]] = ov;
        }
        __syncwarp();
    }
}

// ---------------- w_out: 4 px/thread, 8 outputs/CTA ----------------
__global__ __launch_bounds__(256, 3) void k_wout(const float* __restrict__ w_out,
                                                 const float* __restrict__ b_out) {
    __shared__ float ws[64 * 8];   // [c][d']
    __shared__ float bs[8];
    int tid = threadIdx.x;
    int dbase = blockIdx.y * 8;
    for (int i = tid; i < 64 * 8; i += 256) {
        int c = i >> 3, d = i & 7;
        ws[c * 8 + d] = w_out[c * 64 + dbase + d];
    }
    if (tid < 8) bs[tid] = b_out[dbase + tid];
    __syncthreads();
    int p0 = (blockIdx.x * 256 + tid) * 4;
    if (p0 >= N_PIX) return;

    ull acc[4][4];
#pragma unroll
    for (int px = 0; px < 4; px++)
#pragma unroll
        for (int i = 0; i < 4; i++) acc[px][i] = 0ull;

    for (int c0 = 0; c0 < 64; c0 += 4) {
        float4 xr[4];
#pragma unroll
        for (int i = 0; i < 4; i++)
            xr[i] = __ldg((const float4*)&g_new[(size_t)(c0 + i) * N_PIX + p0]);
#pragma unroll
        for (int i = 0; i < 4; i++) {
            const ulonglong2* wr = (const ulonglong2*)&ws[(c0 + i) * 8];
            ulonglong2 w0 = wr[0], w1 = wr[1];
            float xs[4] = {xr[i].x, xr[i].y, xr[i].z, xr[i].w};
#pragma unroll
            for (int px = 0; px < 4; px++) {
                ull xd = fdup(xs[px]);
                fma2(acc[px][0], w0.x, xd);
                fma2(acc[px][1], w0.y, xd);
                fma2(acc[px][2], w1.x, xd);
                fma2(acc[px][3], w1.y, xd);
            }
        }
    }
#pragma unroll
    for (int i = 0; i < 4; i++) {
        float2 f0 = u2f(acc[0][i]), f1 = u2f(acc[1][i]);
        float2 f2 = u2f(acc[2][i]), f3 = u2f(acc[3][i]);
        float ba = bs[2 * i], bb = bs[2 * i + 1];
        *(float4*)&g_xa[(size_t)(dbase + 2 * i) * N_PIX + p0] =
            make_float4(fmaxf(f0.x + ba, 0.f), fmaxf(f1.x + ba, 0.f),
                        fmaxf(f2.x + ba, 0.f), fmaxf(f3.x + ba, 0.f));
        *(float4*)&g_xa[(size_t)(dbase + 2 * i + 1) * N_PIX + p0] =
            make_float4(fmaxf(f0.y + bb, 0.f), fmaxf(f1.y + bb, 0.f),
                        fmaxf(f2.y + bb, 0.f), fmaxf(f3.y + bb, 0.f));
    }
}

// ---------------- conv2: 4 px/thread, 16 outputs/CTA + fused BN2 stats ----------------
__global__ __launch_bounds__(256, 2) void k_conv2(const float* __restrict__ w2,
                                                  const float* __restrict__ bn1_g,
                                                  const float* __restrict__ bn1_b) {
    __shared__ float w2t[128 * 16]; // [c][o'] 8 KB
    __shared__ float sc1[64], bi1[64];
    __shared__ float ssum[128], ssq[128];
    int tid = threadIdx.x;
    int obase = blockIdx.y * 16;
    for (int i = tid; i < 128 * 16; i += 256) {
        int c = i >> 4, o = i & 15;
        w2t[c * 16 + o] = w2[(obase + o) * 128 + c];
    }
    if (tid < 64) {
        float m = g_sum1[tid] * (1.f / (float)N_PIX);
        float var = g_sumsq1[tid] * (1.f / (float)N_PIX) - m * m;
        float sc = bn1_g[tid] * rsqrtf(var + 1e-5f);
        sc1[tid] = sc;
        bi1[tid] = bn1_b[tid] - m * sc;
    }
    __syncthreads();
    int p0 = (blockIdx.x * 256 + tid) * 4;
    bool valid = p0 < N_PIX;

    ull acc[4][8];
#pragma unroll
    for (int px = 0; px < 4; px++)
#pragma unroll
        for (int i = 0; i < 8; i++) acc[px][i] = 0ull;

    if (valid) {
        // xa half (channels 0..63)
        for (int c0 = 0; c0 < 64; c0 += 4) {
            float4 xr[4];
#pragma unroll
            for (int i = 0; i < 4; i++)
                xr[i] = __ldg((const float4*)&g_xa[(size_t)(c0 + i) * N_PIX + p0]);
#pragma unroll
            for (int i = 0; i < 4; i++) {
                const ulonglong2* wr = (const ulonglong2*)&w2t[(c0 + i) * 16];
                ulonglong2 w0 = wr[0], w1 = wr[1], w2v = wr[2], w3 = wr[3];
                float xs[4] = {xr[i].x, xr[i].y, xr[i].z, xr[i].w};
#pragma unroll
                for (int px = 0; px < 4; px++) {
                    ull xd = fdup(xs[px]);
                    fma2(acc[px][0], w0.x, xd);
                    fma2(acc[px][1], w0.y, xd);
                    fma2(acc[px][2], w1.x, xd);
                    fma2(acc[px][3], w1.y, xd);
                    fma2(acc[px][4], w2v.x, xd);
                    fma2(acc[px][5], w2v.y, xd);
                    fma2(acc[px][6], w3.x, xd);
                    fma2(acc[px][7], w3.y, xd);
                }
            }
        }
        // h half (channels 64..127), BN1+relu inline
        for (int c0 = 0; c0 < 64; c0 += 4) {
            float4 xr[4];
#pragma unroll
            for (int i = 0; i < 4; i++)
                xr[i] = __ldg((const float4*)&g_h_cp[(size_t)(c0 + i) * N_PIX + p0]);
#pragma unroll
            for (int i = 0; i < 4; i++) {
                const ulonglong2* wr = (const ulonglong2*)&w2t[(64 + c0 + i) * 16];
                ulonglong2 w0 = wr[0], w1 = wr[1], w2v = wr[2], w3 = wr[3];
                float scv = sc1[c0 + i], biv = bi1[c0 + i];
                float xs[4];
                xs[0] = fmaxf(fmaf(xr[i].x, scv, biv), 0.f);
                xs[1] = fmaxf(fmaf(xr[i].y, scv, biv), 0.f);
                xs[2] = fmaxf(fmaf(xr[i].z, scv, biv), 0.f);
                xs[3] = fmaxf(fmaf(xr[i].w, scv, biv), 0.f);
#pragma unroll
                for (int px = 0; px < 4; px++) {
                    ull xd = fdup(xs[px]);
                    fma2(acc[px][0], w0.x, xd);
                    fma2(acc[px][1], w0.y, xd);
                    fma2(acc[px][2], w1.x, xd);
                    fma2(acc[px][3], w1.y, xd);
                    fma2(acc[px][4], w2v.x, xd);
                    fma2(acc[px][5], w2v.y, xd);
                    fma2(acc[px][6], w3.x, xd);
                    fma2(acc[px][7], w3.y, xd);
                }
            }
        }
        // stores: float4 per channel
#pragma unroll
        for (int i = 0; i < 8; i++) {
            float2 f0 = u2f(acc[0][i]), f1 = u2f(acc[1][i]);
            float2 f2 = u2f(acc[2][i]), f3 = u2f(acc[3][i]);
            *(float4*)&g_outpre[(size_t)(obase + 2 * i) * N_PIX + p0] =
                make_float4(f0.x, f1.x, f2.x, f3.x);
            *(float4*)&g_outpre[(size_t)(obase + 2 * i + 1) * N_PIX + p0] =
                make_float4(f0.y, f1.y, f2.y, f3.y);
        }
    }

    // BN2 stats: combine px then block-reduce (16 channels)
    ull s8[8], q8[8];
#pragma unroll
    for (int i = 0; i < 8; i++) {
        s8[i] = add2(add2(acc[0][i], acc[1][i]), add2(acc[2][i], acc[3][i]));
        q8[i] = add2(add2(mul2(acc[0][i], acc[0][i]), mul2(acc[1][i], acc[1][i])),
                     add2(mul2(acc[2][i], acc[2][i]), mul2(acc[3][i], acc[3][i])));
    }
    stats_block_reduce8(s8, q8, ssum, ssq, g_sum2, g_sumsq2, obase, tid, tid & 31, tid >> 5);
}

// ---------------- BN2 apply ----------------
__global__ void k_apply2(const float* __restrict__ g, const float* __restrict__ b,
                         float* __restrict__ out) {
    __shared__ float ssc, sbi;
    int c = blockIdx.y;
    if (threadIdx.x == 0) {
        float m = g_sum2[c] * (1.f / (float)N_PIX);
        float var = g_sumsq2[c] * (1.f / (float)N_PIX) - m * m;
        float sc = g[c] * rsqrtf(var + 1e-5f);
        ssc = sc;
        sbi = b[c] - m * sc;
    }
    __syncthreads();
    int p = blockIdx.x * 256 + threadIdx.x;
    if (p >= N_PIX) return;
    float v = g_outpre[(size_t)c * N_PIX + p] * ssc + sbi;
    out[(size_t)c * N_PIX + p] = v > 0.f ? v : 0.f;
}

// ---------------- launch ----------------
extern "C" void kernel_launch(void* const* d_in, const int* in_sizes, int n_in,
                              void* d_out, int out_size) {
    const float* x         = (const float*)d_in[0];
    const int*   prop      = (const int*)d_in[1];
    const int*   rand_inds = (const int*)d_in[2];
    const float* w_conv1   = (const float*)d_in[3];
    const float* bn1_g     = (const float*)d_in[4];
    const float* bn1_b     = (const float*)d_in[5];
    const float* wq        = (const float*)d_in[6];
    const float* wkv       = (const float*)d_in[7];
    const float* w_out     = (const float*)d_in[8];
    const float* b_out     = (const float*)d_in[9];
    const float* w_conv2   = (const float*)d_in[10];
    const float* bn2_g     = (const float*)d_in[11];
    const float* bn2_b     = (const float*)d_in[12];
    float* out = (float*)d_out;

    cudaFuncSetAttribute(k_attn, cudaFuncAttributeMaxDynamicSharedMemorySize, SM_ATT_BYTES);

    k_init<<<1, 256>>>();
    k_scanA<<<SCAN_B, 256>>>(prop);
    k_scanBC<<<SCAN_B, 256>>>(prop);
    dim3 gc1((N_PIX / 4 + 255) / 256, 8);
    k_conv1<<<gc1, 256>>>(x, w_conv1);
    k_attn<<<HEADS * CROP, ATT_THREADS, SM_ATT_BYTES>>>(wq, wkv, rand_inds, bn1_g, bn1_b);
    dim3 gwo((N_PIX / 4 + 255) / 256, 8);
    k_wout<<<gwo, 256>>>(w_out, b_out);
    dim3 gc2((N_PIX / 4 + 255) / 256, 4);
    k_conv2<<<gc2, 256>>>(w_conv2, bn1_g, bn1_b);
    dim3 g2((N_PIX + 255) / 256, E_CH);
    k_apply2<<<g2, 256>>>(bn2_g, bn2_b, out);
}

// round 17
// speedup vs baseline: 1.7329x; 1.0011x over previous
#include <cuda_runtime.h>
#include <math.h>

#define N_PIX    90000
#define HALF_PIX 45000
#define C_IN     256
#define E_CH     64
#define CROP     300
#define HEADS    2
#define DH       32

typedef unsigned long long ull;

__device__ __forceinline__ void fma2(ull& d, ull a, ull b) {
    asm("fma.rn.f32x2 %0, %1, %2, %0;" : "+l"(d) : "l"(a), "l"(b));
}
__device__ __forceinline__ ull add2(ull a, ull b) {
    ull r; asm("add.rn.f32x2 %0, %1, %2;" : "=l"(r) : "l"(a), "l"(b)); return r;
}
__device__ __forceinline__ ull mul2(ull a, ull b) {
    ull r; asm("mul.rn.f32x2 %0, %1, %2;" : "=l"(r) : "l"(a), "l"(b)); return r;
}
__device__ __forceinline__ ull fdup(float v) {
    ull r; asm("mov.b64 %0, {%1, %1};" : "=l"(r) : "f"(v)); return r;
}
__device__ __forceinline__ float2 u2f(ull v) {
    float2 f; asm("mov.b64 {%0, %1}, %2;" : "=f"(f.x), "=f"(f.y) : "l"(v)); return f;
}
__device__ __forceinline__ float hsum2(ull v) { float2 f = u2f(v); return f.x + f.y; }

// ---------------- scratch ----------------
__device__ float g_h[N_PIX * E_CH];        // [p][c] pre-BN1 (attn gather)
__device__ float g_h_cp[E_CH * N_PIX];     // [c][p] pre-BN1 (epilogue streaming)
__device__ float g_new[E_CH * N_PIX];      // [c][p] attention scatter target
__device__ float g_xa[E_CH * N_PIX];       // [d][p] relu(w_out . new + b)
__device__ float g_outpre[E_CH * N_PIX];   // [c][p] pre-BN2
__device__ int   g_obj[HALF_PIX];
__device__ int   g_bg[HALF_PIX];
__device__ int   g_blkcnt[360];
__device__ float g_sum1[E_CH], g_sumsq1[E_CH];
__device__ float g_sum2[E_CH], g_sumsq2[E_CH];

// ---------------- init ----------------
__global__ void k_init() {
    int t = threadIdx.x;
    if (t < 64) g_sum1[t] = 0.f;
    else if (t < 128) g_sumsq1[t - 64] = 0.f;
    else if (t < 192) g_sum2[t - 128] = 0.f;
    else if (t < 256) g_sumsq2[t - 192] = 0.f;
}

// ---------------- scanA ----------------
#define SCAN_B 352
__global__ void k_scanA(const int* __restrict__ prop) {
    int idx = blockIdx.x * 256 + threadIdx.x;
    int v = (idx < N_PIX) ? (prop[idx] != 0) : 0;
    unsigned m = __ballot_sync(0xffffffffu, v);
    __shared__ int wc[8];
    if ((threadIdx.x & 31) == 0) wc[threadIdx.x >> 5] = __popc(m);
    __syncthreads();
    if (threadIdx.x == 0) {
        int t = 0;
        for (int w = 0; w < 8; w++) t += wc[w];
        g_blkcnt[blockIdx.x] = t;
    }
}

// ---------------- scanBC ----------------
__global__ void k_scanBC(const int* __restrict__ prop) {
    int tid = threadIdx.x;
    int b = blockIdx.x;
    int acc = 0;
    for (int i = tid; i < b; i += 256) acc += g_blkcnt[i];
    __shared__ int red[256];
    red[tid] = acc;
    __syncthreads();
    for (int off = 128; off > 0; off >>= 1) {
        if (tid < off) red[tid] += red[tid + off];
        __syncthreads();
    }
    int blkobj = red[0];

    int idx = b * 256 + tid;
    int valid = idx < N_PIX;
    int v = valid ? (prop[idx] != 0) : 0;
    unsigned objm = __ballot_sync(0xffffffffu, v);
    unsigned valm = __ballot_sync(0xffffffffu, valid);
    int lane = tid & 31, w = tid >> 5;
    __shared__ int wobj[8], wval[8];
    if (lane == 0) { wobj[w] = __popc(objm); wval[w] = __popc(valm); }
    __syncthreads();
    int objbase = 0, valbase = 0;
    for (int i = 0; i < w; i++) { objbase += wobj[i]; valbase += wval[i]; }
    unsigned ltm = (1u << lane) - 1u;
    if (valid) {
        if (v) {
            g_obj[blkobj + objbase + __popc(objm & ltm)] = idx;
        } else {
            int bg_before_blk = b * 256 - blkobj;
            int intra = (valbase - objbase) + (__popc(valm & ltm) - __popc(objm & ltm));
            g_bg[bg_before_blk + intra] = idx;
        }
    }
}

// stats reduce for 8 channels (4 ull) at gsum[ebase..]
__device__ __forceinline__ void stats_block_reduce4(ull* s4, ull* q4, float* ssum, float* ssq,
                                                    float* gsum, float* gsq, int ebase,
                                                    int tid, int lane, int warp) {
#pragma unroll
    for (int k = 0; k < 4; k++) {
        ull s = s4[k];
        ull q = q4[k];
#pragma unroll
        for (int o = 16; o > 0; o >>= 1) {
            s = add2(s, __shfl_xor_sync(0xffffffffu, s, o));
            q = add2(q, __shfl_xor_sync(0xffffffffu, q, o));
        }
        if (lane == 0) {
            float2 sf = u2f(s), qf = u2f(q);
            ssum[warp * 8 + 2 * k]     = sf.x;
            ssum[warp * 8 + 2 * k + 1] = sf.y;
            ssq[warp * 8 + 2 * k]      = qf.x;
            ssq[warp * 8 + 2 * k + 1]  = qf.y;
        }
    }
    __syncthreads();
    if (tid < 8) {
        float t = 0.f;
#pragma unroll
        for (int w = 0; w < 8; w++) t += ssum[w * 8 + tid];
        atomicAdd(&gsum[ebase + tid], t);
    } else if (tid < 16) {
        int c = tid - 8;
        float t = 0.f;
#pragma unroll
        for (int w = 0; w < 8; w++) t += ssq[w * 8 + c];
        atomicAdd(&gsq[ebase + c], t);
    }
}

// stats reduce for 16 channels (8 ull) at gsum[ebase..]
__device__ __forceinline__ void stats_block_reduce8(ull* s8, ull* q8, float* ssum, float* ssq,
                                                    float* gsum, float* gsq, int ebase,
                                                    int tid, int lane, int warp) {
#pragma unroll
    for (int k = 0; k < 8; k++) {
        ull s = s8[k];
        ull q = q8[k];
#pragma unroll
        for (int o = 16; o > 0; o >>= 1) {
            s = add2(s, __shfl_xor_sync(0xffffffffu, s, o));
            q = add2(q, __shfl_xor_sync(0xffffffffu, q, o));
        }
        if (lane == 0) {
            float2 sf = u2f(s), qf = u2f(q);
            ssum[warp * 16 + 2 * k]     = sf.x;
            ssum[warp * 16 + 2 * k + 1] = sf.y;
            ssq[warp * 16 + 2 * k]      = qf.x;
            ssq[warp * 16 + 2 * k + 1]  = qf.y;
        }
    }
    __syncthreads();
    if (tid < 16) {
        float t = 0.f;
#pragma unroll
        for (int w = 0; w < 8; w++) t += ssum[w * 16 + tid];
        atomicAdd(&gsum[ebase + tid], t);
    } else if (tid < 32) {
        int c = tid - 16;
        float t = 0.f;
#pragma unroll
        for (int w = 0; w < 8; w++) t += ssq[w * 16 + c];
        atomicAdd(&gsq[ebase + c], t);
    }
}

// ---------------- conv1: 4 px/thread, 8 outputs/CTA (blockIdx.y of 8), 3 CTAs/SM ----------------
__global__ __launch_bounds__(256, 3) void k_conv1(const float* __restrict__ x,
                                                  const float* __restrict__ w) {
    __shared__ float ws[C_IN * 8];       // [c][e'] 8 KB
    __shared__ float ssum[64], ssq[64];
    int tid = threadIdx.x;
    int ebase = blockIdx.y * 8;
    for (int i = tid; i < C_IN * 8; i += 256) {
        int c = i >> 3, e = i & 7;
        ws[c * 8 + e] = w[(ebase + e) * C_IN + c];
    }
    __syncthreads();
    int p0 = (blockIdx.x * 256 + tid) * 4;
    bool valid = p0 < N_PIX;

    ull acc[4][4];
#pragma unroll
    for (int px = 0; px < 4; px++)
#pragma unroll
        for (int i = 0; i < 4; i++) acc[px][i] = 0ull;

    if (valid) {
        for (int c0 = 0; c0 < C_IN; c0 += 4) {
            float4 xr[4];
#pragma unroll
            for (int i = 0; i < 4; i++)
                xr[i] = __ldg((const float4*)&x[(size_t)(c0 + i) * N_PIX + p0]);
#pragma unroll
            for (int i = 0; i < 4; i++) {
                const ulonglong2* wr = (const ulonglong2*)&ws[(c0 + i) * 8];
                ulonglong2 w0 = wr[0], w1 = wr[1];
                float xs[4] = {xr[i].x, xr[i].y, xr[i].z, xr[i].w};
#pragma unroll
                for (int px = 0; px < 4; px++) {
                    ull xd = fdup(xs[px]);
                    fma2(acc[px][0], w0.x, xd);
                    fma2(acc[px][1], w0.y, xd);
                    fma2(acc[px][2], w1.x, xd);
                    fma2(acc[px][3], w1.y, xd);
                }
            }
        }
#pragma unroll
        for (int px = 0; px < 4; px++) {
            ull* op = (ull*)&g_h[(size_t)(p0 + px) * 64 + ebase];
#pragma unroll
            for (int i = 0; i < 4; i++) op[i] = acc[px][i];
        }
#pragma unroll
        for (int i = 0; i < 4; i++) {
            float2 f0 = u2f(acc[0][i]), f1 = u2f(acc[1][i]);
            float2 f2 = u2f(acc[2][i]), f3 = u2f(acc[3][i]);
            *(float4*)&g_h_cp[(size_t)(ebase + 2 * i) * N_PIX + p0] =
                make_float4(f0.x, f1.x, f2.x, f3.x);
            *(float4*)&g_h_cp[(size_t)(ebase + 2 * i + 1) * N_PIX + p0] =
                make_float4(f0.y, f1.y, f2.y, f3.y);
        }
    }

    ull s4[4], q4[4];
#pragma unroll
    for (int i = 0; i < 4; i++) {
        s4[i] = add2(add2(acc[0][i], acc[1][i]), add2(acc[2][i], acc[3][i]));
        q4[i] = add2(add2(mul2(acc[0][i], acc[0][i]), mul2(acc[1][i], acc[1][i])),
                     add2(mul2(acc[2][i], acc[2][i]), mul2(acc[3][i], acc[3][i])));
    }
    stats_block_reduce4(s4, q4, ssum, ssq, g_sum1, g_sumsq1, ebase, tid, tid & 31, tid >> 5);
}

// ---------------- attention: r8 configuration (4 rows/warp, 384 threads) ----------------
#define ATT_THREADS 384
#define ATT_WARPS 12
#define SM_ATT_FLOATS (64 + 64 + 1152 * 3 + 14400 + 9600 * 3 + 300)
#define SM_ATT_BYTES (SM_ATT_FLOATS * 4)

__global__ __launch_bounds__(ATT_THREADS, 1) void k_attn(const float* __restrict__ wq,
                                                         const float* __restrict__ wkv,
                                                         const int* __restrict__ rand_inds,
                                                         const float* __restrict__ bn1_g,
                                                         const float* __restrict__ bn1_b) {
    extern __shared__ float sm[];
    float* sc1    = sm;                    // 64
    float* bi1    = sm + 64;               // 64
    float* wq_t   = sm + 128;              // 32*36
    float* wk_t   = wq_t + 1152;
    float* wv_t   = wk_t + 1152;
    float* p_rows = wv_t + 1152;           // 14400 (seq alias)
    float* q_s    = p_rows + 14400;        // 9600
    float* k_s    = q_s + 9600;            // 9600
    float* v_t    = k_s + 9600;            // 9600 : [d][300]
    int*   pix_s  = (int*)(v_t + 9600);    // 300
    float* seq_s  = p_rows;

    int tid = threadIdx.x, warp = tid >> 5, lane = tid & 31;
    int b = blockIdx.x;
    int head = b / CROP;
    int iblk = b - head * CROP;
    int hoff = head * DH;

    if (tid < 64) {
        float m = g_sum1[tid] * (1.f / (float)N_PIX);
        float var = g_sumsq1[tid] * (1.f / (float)N_PIX) - m * m;
        float sc = bn1_g[tid] * rsqrtf(var + 1e-5f);
        sc1[tid] = sc;
        bi1[tid] = bn1_b[tid] - m * sc;
    }
    const int* src = (iblk < CROP / 2) ? g_obj : g_bg;
    const int* ri = rand_inds + (size_t)head * N_PIX + (size_t)iblk * CROP;
    for (int j = tid; j < CROP; j += ATT_THREADS) pix_s[j] = src[ri[j]];
    for (int i = tid; i < 1024; i += ATT_THREADS) {
        int e = i >> 5, d = i & 31;
        wq_t[d * 36 + e] = wq[i];
    }
    for (int i = tid; i < 2048; i += ATT_THREADS) {
        int e = i >> 6, c = i & 63;
        if (c < 32) wk_t[c * 36 + e] = wkv[i];
        else        wv_t[(c - 32) * 36 + e] = wkv[i];
    }
    __syncthreads();

    // gather + BN1 + relu, XOR-swizzled [j][32]
    for (int u = tid; u < CROP * 8; u += ATT_THREADS) {
        int j = u >> 3, seg = u & 7;
        int ch = hoff + seg * 4;
        float4 v = *(const float4*)&g_h[(size_t)pix_s[j] * 64 + ch];
        float4 s4 = *(const float4*)&sc1[ch];
        float4 b4 = *(const float4*)&bi1[ch];
        v.x = fmaxf(fmaf(v.x, s4.x, b4.x), 0.f);
        v.y = fmaxf(fmaf(v.y, s4.y, b4.y), 0.f);
        v.z = fmaxf(fmaf(v.z, s4.z, b4.z), 0.f);
        v.w = fmaxf(fmaf(v.w, s4.w, b4.w), 0.f);
        int pc = seg ^ (j & 7);
        *(float4*)&seq_s[j * 32 + pc * 4] = v;
    }
    __syncthreads();

    // QKV with register-resident weights (d = lane)
    {
        ull rq[16], rk[16], rv[16];
#pragma unroll
        for (int e2 = 0; e2 < 8; e2++) {
            ulonglong2 t;
            t = *(const ulonglong2*)&wq_t[lane * 36 + e2 * 4]; rq[2*e2] = t.x; rq[2*e2+1] = t.y;
            t = *(const ulonglong2*)&wk_t[lane * 36 + e2 * 4]; rk[2*e2] = t.x; rk[2*e2+1] = t.y;
            t = *(const ulonglong2*)&wv_t[lane * 36 + e2 * 4]; rv[2*e2] = t.x; rv[2*e2+1] = t.y;
        }
        for (int j = warp; j < CROP; j += ATT_WARPS) {
            int sw2 = (j & 7) << 2;
            ull aq = 0, ak = 0, av = 0;
#pragma unroll
            for (int e4 = 0; e4 < 8; e4++) {
                ulonglong2 sp = *(const ulonglong2*)&seq_s[j * 32 + ((e4 << 2) ^ sw2)];
                fma2(aq, sp.x, rq[2*e4]);
                fma2(ak, sp.x, rk[2*e4]);
                fma2(av, sp.x, rv[2*e4]);
                fma2(aq, sp.y, rq[2*e4+1]);
                fma2(ak, sp.y, rk[2*e4+1]);
                fma2(av, sp.y, rv[2*e4+1]);
            }
            int wi = j * 32 + (lane ^ sw2);
            q_s[wi] = hsum2(aq);
            k_s[wi] = hsum2(ak);
            v_t[lane * 300 + j] = hsum2(av);
        }
    }
    __syncthreads();

    const float scale = 0.17677669529663687f; // 1/sqrt(32)
    float* pw = &p_rows[warp * 4 * 300];
    for (int rp = warp; rp < 75; rp += ATT_WARPS) {
        int r0 = rp * 4;
        ull a[4][10];
#pragma unroll
        for (int r = 0; r < 4; r++)
#pragma unroll
            for (int jj = 0; jj < 10; jj++) a[r][jj] = 0ull;

#pragma unroll
        for (int c = 0; c < 8; c++) {
            ull qx[4], qy[4];
#pragma unroll
            for (int r = 0; r < 4; r++) {
                int row = r0 + r;
                ulonglong2 t = *(const ulonglong2*)&q_s[row * 32 + ((c << 2) ^ ((row & 7) << 2))];
                qx[r] = t.x; qy[r] = t.y;
            }
#pragma unroll
            for (int jj = 0; jj < 10; jj++) {
                int j = lane + (jj << 5);
                int jc = (j < CROP) ? j : 0;
                ulonglong2 kv = *(const ulonglong2*)&k_s[jc * 32 + ((c << 2) ^ ((jc & 7) << 2))];
                fma2(a[0][jj], qx[0], kv.x);
                fma2(a[1][jj], qx[1], kv.x);
                fma2(a[2][jj], qx[2], kv.x);
                fma2(a[3][jj], qx[3], kv.x);
                fma2(a[0][jj], qy[0], kv.y);
                fma2(a[1][jj], qy[1], kv.y);
                fma2(a[2][jj], qy[2], kv.y);
                fma2(a[3][jj], qy[3], kv.y);
            }
        }
#pragma unroll
        for (int r = 0; r < 4; r++) {
            float sv[10];
            float mx = -1e30f;
#pragma unroll
            for (int jj = 0; jj < 10; jj++) {
                float s = hsum2(a[r][jj]) * scale;
                sv[jj] = s;
                if (lane + (jj << 5) < CROP) mx = fmaxf(mx, s);
            }
#pragma unroll
            for (int o = 16; o > 0; o >>= 1)
                mx = fmaxf(mx, __shfl_xor_sync(0xffffffffu, mx, o));
            float sum = 0.f;
#pragma unroll
            for (int jj = 0; jj < 10; jj++) {
                int j = lane + (jj << 5);
                float e = (j < CROP) ? __expf(sv[jj] - mx) : 0.f;
                sv[jj] = e;
                sum += e;
            }
#pragma unroll
            for (int o = 16; o > 0; o >>= 1)
                sum += __shfl_xor_sync(0xffffffffu, sum, o);
            float inv = 1.f / sum;
#pragma unroll
            for (int jj = 0; jj < 10; jj++) {
                int j = lane + (jj << 5);
                if (j < CROP) pw[r * 300 + j] = sv[jj] * inv;
            }
        }
        __syncwarp();
        ull oa[4] = {0, 0, 0, 0}, ob[4] = {0, 0, 0, 0};
        const float* vrow = &v_t[lane * 300];
#pragma unroll 5
        for (int j4 = 0; j4 < 75; j4++) {
            ulonglong2 vv = *(const ulonglong2*)&vrow[j4 * 4];
#pragma unroll
            for (int r = 0; r < 4; r++) {
                ulonglong2 pv = *(const ulonglong2*)&pw[r * 300 + j4 * 4];
                fma2(oa[r], pv.x, vv.x);
                fma2(ob[r], pv.y, vv.y);
            }
        }
#pragma unroll
        for (int r = 0; r < 4; r++) {
            float ov = hsum2(add2(oa[r], ob[r]));
            int t = (r0 + r) * 32 + lane;
            int d = t / 300, mm = t - d * 300;
            g_new[(size_t)(hoff + d) * N_PIX + pix_s[mm]] = ov;
        }
        __syncwarp();
    }
}

// ---------------- w_out: 4 px/thread, 8 outputs/CTA ----------------
__global__ __launch_bounds__(256, 3) void k_wout(const float* __restrict__ w_out,
                                                 const float* __restrict__ b_out) {
    __shared__ float ws[64 * 8];   // [c][d']
    __shared__ float bs[8];
    int tid = threadIdx.x;
    int dbase = blockIdx.y * 8;
    for (int i = tid; i < 64 * 8; i += 256) {
        int c = i >> 3, d = i & 7;
        ws[c * 8 + d] = w_out[c * 64 + dbase + d];
    }
    if (tid < 8) bs[tid] = b_out[dbase + tid];
    __syncthreads();
    int p0 = (blockIdx.x * 256 + tid) * 4;
    if (p0 >= N_PIX) return;

    ull acc[4][4];
#pragma unroll
    for (int px = 0; px < 4; px++)
#pragma unroll
        for (int i = 0; i < 4; i++) acc[px][i] = 0ull;

    for (int c0 = 0; c0 < 64; c0 += 4) {
        float4 xr[4];
#pragma unroll
        for (int i = 0; i < 4; i++)
            xr[i] = __ldg((const float4*)&g_new[(size_t)(c0 + i) * N_PIX + p0]);
#pragma unroll
        for (int i = 0; i < 4; i++) {
            const ulonglong2* wr = (const ulonglong2*)&ws[(c0 + i) * 8];
            ulonglong2 w0 = wr[0], w1 = wr[1];
            float xs[4] = {xr[i].x, xr[i].y, xr[i].z, xr[i].w};
#pragma unroll
            for (int px = 0; px < 4; px++) {
                ull xd = fdup(xs[px]);
                fma2(acc[px][0], w0.x, xd);
                fma2(acc[px][1], w0.y, xd);
                fma2(acc[px][2], w1.x, xd);
                fma2(acc[px][3], w1.y, xd);
            }
        }
    }
#pragma unroll
    for (int i = 0; i < 4; i++) {
        float2 f0 = u2f(acc[0][i]), f1 = u2f(acc[1][i]);
        float2 f2 = u2f(acc[2][i]), f3 = u2f(acc[3][i]);
        float ba = bs[2 * i], bb = bs[2 * i + 1];
        *(float4*)&g_xa[(size_t)(dbase + 2 * i) * N_PIX + p0] =
            make_float4(fmaxf(f0.x + ba, 0.f), fmaxf(f1.x + ba, 0.f),
                        fmaxf(f2.x + ba, 0.f), fmaxf(f3.x + ba, 0.f));
        *(float4*)&g_xa[(size_t)(dbase + 2 * i + 1) * N_PIX + p0] =
            make_float4(fmaxf(f0.y + bb, 0.f), fmaxf(f1.y + bb, 0.f),
                        fmaxf(f2.y + bb, 0.f), fmaxf(f3.y + bb, 0.f));
    }
}

// ---------------- conv2: 4 px/thread, 16 outputs/CTA + fused BN2 stats ----------------
__global__ __launch_bounds__(256, 2) void k_conv2(const float* __restrict__ w2,
                                                  const float* __restrict__ bn1_g,
                                                  const float* __restrict__ bn1_b) {
    __shared__ float w2t[128 * 16]; // [c][o'] 8 KB
    __shared__ float sc1[64], bi1[64];
    __shared__ float ssum[128], ssq[128];
    int tid = threadIdx.x;
    int obase = blockIdx.y * 16;
    for (int i = tid; i < 128 * 16; i += 256) {
        int c = i >> 4, o = i & 15;
        w2t[c * 16 + o] = w2[(obase + o) * 128 + c];
    }
    if (tid < 64) {
        float m = g_sum1[tid] * (1.f / (float)N_PIX);
        float var = g_sumsq1[tid] * (1.f / (float)N_PIX) - m * m;
        float sc = bn1_g[tid] * rsqrtf(var + 1e-5f);
        sc1[tid] = sc;
        bi1[tid] = bn1_b[tid] - m * sc;
    }
    __syncthreads();
    int p0 = (blockIdx.x * 256 + tid) * 4;
    bool valid = p0 < N_PIX;

    ull acc[4][8];
#pragma unroll
    for (int px = 0; px < 4; px++)
#pragma unroll
        for (int i = 0; i < 8; i++) acc[px][i] = 0ull;

    if (valid) {
        // xa half (channels 0..63)
        for (int c0 = 0; c0 < 64; c0 += 4) {
            float4 xr[4];
#pragma unroll
            for (int i = 0; i < 4; i++)
                xr[i] = __ldg((const float4*)&g_xa[(size_t)(c0 + i) * N_PIX + p0]);
#pragma unroll
            for (int i = 0; i < 4; i++) {
                const ulonglong2* wr = (const ulonglong2*)&w2t[(c0 + i) * 16];
                ulonglong2 w0 = wr[0], w1 = wr[1], w2v = wr[2], w3 = wr[3];
                float xs[4] = {xr[i].x, xr[i].y, xr[i].z, xr[i].w};
#pragma unroll
                for (int px = 0; px < 4; px++) {
                    ull xd = fdup(xs[px]);
                    fma2(acc[px][0], w0.x, xd);
                    fma2(acc[px][1], w0.y, xd);
                    fma2(acc[px][2], w1.x, xd);
                    fma2(acc[px][3], w1.y, xd);
                    fma2(acc[px][4], w2v.x, xd);
                    fma2(acc[px][5], w2v.y, xd);
                    fma2(acc[px][6], w3.x, xd);
                    fma2(acc[px][7], w3.y, xd);
                }
            }
        }
        // h half (channels 64..127), BN1+relu inline
        for (int c0 = 0; c0 < 64; c0 += 4) {
            float4 xr[4];
#pragma unroll
            for (int i = 0; i < 4; i++)
                xr[i] = __ldg((const float4*)&g_h_cp[(size_t)(c0 + i) * N_PIX + p0]);
#pragma unroll
            for (int i = 0; i < 4; i++) {
                const ulonglong2* wr = (const ulonglong2*)&w2t[(64 + c0 + i) * 16];
                ulonglong2 w0 = wr[0], w1 = wr[1], w2v = wr[2], w3 = wr[3];
                float scv = sc1[c0 + i], biv = bi1[c0 + i];
                float xs[4];
                xs[0] = fmaxf(fmaf(xr[i].x, scv, biv), 0.f);
                xs[1] = fmaxf(fmaf(xr[i].y, scv, biv), 0.f);
                xs[2] = fmaxf(fmaf(xr[i].z, scv, biv), 0.f);
                xs[3] = fmaxf(fmaf(xr[i].w, scv, biv), 0.f);
#pragma unroll
                for (int px = 0; px < 4; px++) {
                    ull xd = fdup(xs[px]);
                    fma2(acc[px][0], w0.x, xd);
                    fma2(acc[px][1], w0.y, xd);
                    fma2(acc[px][2], w1.x, xd);
                    fma2(acc[px][3], w1.y, xd);
                    fma2(acc[px][4], w2v.x, xd);
                    fma2(acc[px][5], w2v.y, xd);
                    fma2(acc[px][6], w3.x, xd);
                    fma2(acc[px][7], w3.y, xd);
                }
            }
        }
        // stores: float4 per channel
#pragma unroll
        for (int i = 0; i < 8; i++) {
            float2 f0 = u2f(acc[0][i]), f1 = u2f(acc[1][i]);
            float2 f2 = u2f(acc[2][i]), f3 = u2f(acc[3][i]);
            *(float4*)&g_outpre[(size_t)(obase + 2 * i) * N_PIX + p0] =
                make_float4(f0.x, f1.x, f2.x, f3.x);
            *(float4*)&g_outpre[(size_t)(obase + 2 * i + 1) * N_PIX + p0] =
                make_float4(f0.y, f1.y, f2.y, f3.y);
        }
    }

    // BN2 stats: combine px then block-reduce (16 channels)
    ull s8[8], q8[8];
#pragma unroll
    for (int i = 0; i < 8; i++) {
        s8[i] = add2(add2(acc[0][i], acc[1][i]), add2(acc[2][i], acc[3][i]));
        q8[i] = add2(add2(mul2(acc[0][i], acc[0][i]), mul2(acc[1][i], acc[1][i])),
                     add2(mul2(acc[2][i], acc[2][i]), mul2(acc[3][i], acc[3][i])));
    }
    stats_block_reduce8(s8, q8, ssum, ssq, g_sum2, g_sumsq2, obase, tid, tid & 31, tid >> 5);
}

// ---------------- BN2 apply ----------------
__global__ void k_apply2(const float* __restrict__ g, const float* __restrict__ b,
                         float* __restrict__ out) {
    __shared__ float ssc, sbi;
    int c = blockIdx.y;
    if (threadIdx.x == 0) {
        float m = g_sum2[c] * (1.f / (float)N_PIX);
        float var = g_sumsq2[c] * (1.f / (float)N_PIX) - m * m;
        float sc = g[c] * rsqrtf(var + 1e-5f);
        ssc = sc;
        sbi = b[c] - m * sc;
    }
    __syncthreads();
    int p = blockIdx.x * 256 + threadIdx.x;
    if (p >= N_PIX) return;
    float v = g_outpre[(size_t)c * N_PIX + p] * ssc + sbi;
    out[(size_t)c * N_PIX + p] = v > 0.f ? v : 0.f;
}

// ---------------- launch ----------------
extern "C" void kernel_launch(void* const* d_in, const int* in_sizes, int n_in,
                              void* d_out, int out_size) {
    const float* x         = (const float*)d_in[0];
    const int*   prop      = (const int*)d_in[1];
    const int*   rand_inds = (const int*)d_in[2];
    const float* w_conv1   = (const float*)d_in[3];
    const float* bn1_g     = (const float*)d_in[4];
    const float* bn1_b     = (const float*)d_in[5];
    const float* wq        = (const float*)d_in[6];
    const float* wkv       = (const float*)d_in[7];
    const float* w_out     = (const float*)d_in[8];
    const float* b_out     = (const float*)d_in[9];
    const float* w_conv2   = (const float*)d_in[10];
    const float* bn2_g     = (const float*)d_in[11];
    const float* bn2_b     = (const float*)d_in[12];
    float* out = (float*)d_out;

    cudaFuncSetAttribute(k_attn, cudaFuncAttributeMaxDynamicSharedMemorySize, SM_ATT_BYTES);

    k_init<<<1, 256>>>();
    k_scanA<<<SCAN_B, 256>>>(prop);
    k_scanBC<<<SCAN_B, 256>>>(prop);
    dim3 gc1((N_PIX / 4 + 255) / 256, 8);
    k_conv1<<<gc1, 256>>>(x, w_conv1);
    k_attn<<<HEADS * CROP, ATT_THREADS, SM_ATT_BYTES>>>(wq, wkv, rand_inds, bn1_g, bn1_b);
    dim3 gwo((N_PIX / 4 + 255) / 256, 8);
    k_wout<<<gwo, 256>>>(w_out, b_out);
    dim3 gc2((N_PIX / 4 + 255) / 256, 4);
    k_conv2<<<gc2, 256>>>(w_conv2, bn1_g, bn1_b);
    dim3 g2((N_PIX + 255) / 256, E_CH);
    k_apply2<<<g2, 256>>>(bn2_g, bn2_b, out);
}